// round 8
// baseline (speedup 1.0000x reference)
#include <cuda_runtime.h>
#include <stdint.h>

#define NN      100000
#define FDIM    128
#define HDIM    256
#define EMAX    1800000
#define NEG_SLOPE 0.2f
#define SCAN_T  512

// dynamic smem (floats):
//   rawA[2][4096]   @ 0      (A slab: 16k x 256m, chunk layout [k4][m][4])
//   rawB[2][2048]   @ 8192   (B slab: 16k x 128n, row-major)
//   planes[2][12288]@ 12288  (Ah[16][256], Al, Bh[16][128], Bl — XOR swizzled)
#define SMEM_FLOATS 36864
#define SMEM_BYTES (SMEM_FLOATS * 4)

// -------- scratch (static device arrays; no runtime malloc) ----------
__device__ float g_h   [(size_t)NN * FDIM];
__device__ float g_asrc[NN];
__device__ float g_adst[NN];
__device__ float g_gat [(size_t)NN * FDIM];
__device__ float g_h1  [(size_t)NN * HDIM];
__device__ float g_h2  [(size_t)NN * HDIM];
__device__ float g_bias2[HDIM];               // b1 + bias @ W1
__device__ int   g_src [EMAX];
__device__ int   g_dst [EMAX];
__device__ int   g_csrc[EMAX];
__device__ int   g_cnt [NN];
__device__ int   g_cnt2[NN];
__device__ int   g_rp  [NN + 1];
__device__ int   g_part[256];
__device__ int   g_is64;

// --------------------------- dtype probe ---------------------------
__global__ void k_detect(const int* __restrict__ ei, int E) {
    __shared__ int nz;
    if (threadIdx.x == 0) nz = 0;
    __syncthreads();
    int samples = 4096;
    if (samples > E) samples = E;
    for (int i = threadIdx.x; i < samples; i += blockDim.x)
        if (ei[2 * i + 1] != 0) atomicOr(&nz, 1);
    __syncthreads();
    if (threadIdx.x == 0) g_is64 = (nz == 0) ? 1 : 0;
}

// ----------------- edge expansion (+ self loops) -------------------
__global__ void k_convert(const int* __restrict__ ei, int E, int n) {
    int tot = E + n;
    int stride = gridDim.x * blockDim.x;
    int is64 = g_is64;
    for (int idx = blockIdx.x * blockDim.x + threadIdx.x; idx < tot; idx += stride) {
        int s, d;
        if (idx < E) {
            if (is64) { s = ei[2 * idx]; d = ei[2 * E + 2 * idx]; }
            else      { s = ei[idx];     d = ei[E + idx]; }
        } else {
            s = d = idx - E;
        }
        g_src[idx] = s;
        g_dst[idx] = d;
    }
}

__global__ void k_zero(int n) {
    int stride = gridDim.x * blockDim.x;
    for (int i = blockIdx.x * blockDim.x + threadIdx.x; i < n; i += stride) {
        g_cnt[i] = 0; g_cnt2[i] = 0;
    }
}

__global__ void k_hist(int tot) {
    int stride = gridDim.x * blockDim.x;
    for (int i = blockIdx.x * blockDim.x + threadIdx.x; i < tot; i += stride)
        atomicAdd(&g_cnt[g_dst[i]], 1);
}

// ------------------------ hierarchical scan ------------------------
__global__ void k_scan1(int n) {
    __shared__ int sh[SCAN_T];
    int t = threadIdx.x;
    int i = blockIdx.x * SCAN_T + t;
    int v = (i < n) ? g_cnt[i] : 0;
    sh[t] = v;
    __syncthreads();
    for (int o = 1; o < SCAN_T; o <<= 1) {
        int x = (t >= o) ? sh[t - o] : 0;
        __syncthreads();
        sh[t] += x;
        __syncthreads();
    }
    if (i < n) g_rp[i] = sh[t] - v;
    if (t == SCAN_T - 1) g_part[blockIdx.x] = sh[t];
}

__global__ void k_scan2(int nb) {
    __shared__ int sh[256];
    int t = threadIdx.x;
    int v = (t < nb) ? g_part[t] : 0;
    sh[t] = v;
    __syncthreads();
    for (int o = 1; o < 256; o <<= 1) {
        int x = (t >= o) ? sh[t - o] : 0;
        __syncthreads();
        sh[t] += x;
        __syncthreads();
    }
    if (t < nb) g_part[t] = sh[t] - v;
}

__global__ void k_scan3(int n, int etot) {
    int i = blockIdx.x * SCAN_T + threadIdx.x;
    if (i < n) g_rp[i] += g_part[blockIdx.x];
    if (i == 0) g_rp[n] = etot;
}

__global__ void k_slot(int tot) {
    int stride = gridDim.x * blockDim.x;
    for (int i = blockIdx.x * blockDim.x + threadIdx.x; i < tot; i += stride) {
        int d = g_dst[i];
        int slot = g_rp[d] + atomicAdd(&g_cnt2[d], 1);
        g_csrc[slot] = g_src[i];
    }
}

// ---------------- fused layer-1 bias: bias2 = b1 + bias @ W1 --------------
__global__ void k_bias2(const float* __restrict__ bias,
                        const float* __restrict__ W1,
                        const float* __restrict__ b1, int K, int N) {
    int n = blockIdx.x * (blockDim.x >> 5) + (threadIdx.x >> 5);
    int lane = threadIdx.x & 31;
    if (n >= N) return;
    float s = 0.f;
    for (int k = lane; k < K; k += 32) s += bias[k] * W1[(size_t)k * N + n];
#pragma unroll
    for (int o = 16; o; o >>= 1) s += __shfl_xor_sync(0xFFFFFFFFu, s, o);
    if (lane == 0) g_bias2[n] = s + b1[n];
}

// --------------------------- tf32 helpers ---------------------------
__device__ __forceinline__ unsigned tf32_rna(float v) {
    unsigned r;
    asm("cvt.rna.tf32.f32 %0, %1;" : "=r"(r) : "f"(v));
    return r;
}

__device__ __forceinline__ void mma_tf32(float c[4],
                                         unsigned a0, unsigned a1, unsigned a2, unsigned a3,
                                         unsigned b0, unsigned b1) {
    asm volatile(
        "mma.sync.aligned.m16n8k8.row.col.f32.tf32.tf32.f32 "
        "{%0,%1,%2,%3}, {%4,%5,%6,%7}, {%8,%9}, {%0,%1,%2,%3};"
        : "+f"(c[0]), "+f"(c[1]), "+f"(c[2]), "+f"(c[3])
        : "r"(a0), "r"(a1), "r"(a2), "r"(a3), "r"(b0), "r"(b1));
}

__device__ __forceinline__ void cp_async16(uint32_t dst, const float* src, bool pred) {
    int sz = pred ? 16 : 0;
    asm volatile("cp.async.cg.shared.global [%0], [%1], 16, %2;"
                 :: "r"(dst), "l"(src), "r"(sz));
}
__device__ __forceinline__ void cp_commit() {
    asm volatile("cp.async.commit_group;");
}
template<int NW>
__device__ __forceinline__ void cp_wait() {
    asm volatile("cp.async.wait_group %0;" :: "n"(NW));
}

// --------- tensor-core GEMM: tf32x3, 256x128 CTA tile, BK=16 --------------
// 256 threads, 8 warps (4M x 2N), 64x64 warp tiles.  cp.async raw staging
// + in-smem hi/lo conversion; fragment code reads swizzled planes.
template<bool RELU, bool CBIAS>
__global__ void __launch_bounds__(256) k_mma(
    const float* __restrict__ A, const float* __restrict__ B,
    float* __restrict__ C, const float* __restrict__ cbias,
    int M, int N, int K)
{
    extern __shared__ float sm[];
    const uint32_t smem_base = (uint32_t)__cvta_generic_to_shared(sm);

    const int tid  = threadIdx.x;
    const int wid  = tid >> 5;
    const int lane = tid & 31;
    const int gid  = lane >> 2;
    const int tig  = lane & 3;
    const int warpM = (wid & 3) * 64;
    const int warpN = (wid >> 2) * 64;
    const int rowBase = blockIdx.y * 256;
    const int colBase = blockIdx.x * 128;

    float acc[4][8][4];
#pragma unroll
    for (int mf = 0; mf < 4; mf++)
#pragma unroll
        for (int nf = 0; nf < 8; nf++)
#pragma unroll
            for (int r = 0; r < 4; r++) acc[mf][nf][r] = 0.f;

    // ---- cp.async one slab (16 k) into raw[stage]
    const int grA = rowBase + tid;
    const bool pA = grA < M;
    const float* srcArow = A + (size_t)(pA ? grA : 0) * K;
    auto cp_slab = [&](int k0, int stage) {
        uint32_t raA = smem_base + (stage * 4096) * 4;
        uint32_t raB = smem_base + (8192 + stage * 2048) * 4;
#pragma unroll
        for (int k4 = 0; k4 < 4; k4++)
            cp_async16(raA + (k4 * 1024 + tid * 4) * 4, srcArow + k0 + k4 * 4, pA);
#pragma unroll
        for (int i = 0; i < 2; i++) {
            int idx = i * 256 + tid;
            int k = idx >> 5, n4 = idx & 31;
            cp_async16(raB + (k * 128 + n4 * 4) * 4,
                       B + (size_t)(k0 + k) * N + colBase + n4 * 4, true);
        }
    };

    // ---- convert raw[stage] -> hi/lo planes[stage]
    auto convert = [&](int stage) {
        const float* rawA = sm + stage * 4096;
        const float* rawB = sm + 8192 + stage * 2048;
        float* pl = sm + 12288 + stage * 12288;
        float* Ah = pl;
        float* Al = pl + 4096;
        float* Bh = pl + 8192;
        float* Bl = pl + 10240;
#pragma unroll
        for (int k4 = 0; k4 < 4; k4++) {
            float4 v = *(const float4*)&rawA[k4 * 1024 + tid * 4];
            float vv[4] = {v.x, v.y, v.z, v.w};
#pragma unroll
            for (int j = 0; j < 4; j++) {
                int k = k4 * 4 + j;
                int sw = (k & 3) * 8;
                unsigned h = tf32_rna(vv[j]);
                unsigned l = tf32_rna(vv[j] - __uint_as_float(h));
                Ah[k * 256 + (tid ^ sw)] = __uint_as_float(h);
                Al[k * 256 + (tid ^ sw)] = __uint_as_float(l);
            }
        }
        int kb = tid >> 4, n8 = (tid & 15) * 8;
        float4 u0 = *(const float4*)&rawB[kb * 128 + n8];
        float4 u1 = *(const float4*)&rawB[kb * 128 + n8 + 4];
        float uu[8] = {u0.x, u0.y, u0.z, u0.w, u1.x, u1.y, u1.z, u1.w};
        int swb = (kb & 3) * 8;
#pragma unroll
        for (int j = 0; j < 8; j++) {
            int n = n8 + j;
            unsigned h = tf32_rna(uu[j]);
            unsigned l = tf32_rna(uu[j] - __uint_as_float(h));
            Bh[kb * 128 + (n ^ swb)] = __uint_as_float(h);
            Bl[kb * 128 + (n ^ swb)] = __uint_as_float(l);
        }
    };

    const int S = K >> 4;

    // prologue: prefetch slabs 0,1; convert slab 0
    cp_slab(0, 0);  cp_commit();
    cp_slab(16, 1); cp_commit();
    cp_wait<1>();
    __syncthreads();
    convert(0);
    __syncthreads();

    for (int s = 0; s < S; s++) {
        if (s + 2 < S) { cp_slab((s + 2) * 16, s & 1); cp_commit(); }
        if (s + 1 < S) {
            if (s + 2 < S) cp_wait<1>(); else cp_wait<0>();
            convert((s + 1) & 1);
        }

        const float* pl = sm + 12288 + (s & 1) * 12288;
        const float* Ah = pl;
        const float* Al = pl + 4096;
        const float* Bh = pl + 8192;
        const float* Bl = pl + 10240;

#pragma unroll
        for (int ks = 0; ks < 2; ks++) {
            const int kO = ks * 8;
            const int sw = tig * 8;
            const int krA0 = (kO + tig) * 256;
            const int krA1 = (kO + tig + 4) * 256;
            const int krB0 = (kO + tig) * 128;
            const int krB1 = (kO + tig + 4) * 128;

            unsigned ah[4][4], al[4][4];
#pragma unroll
            for (int mf = 0; mf < 4; mf++) {
                int m0 = warpM + mf * 16 + gid;
                int m1 = m0 + 8;
                ah[mf][0] = __float_as_uint(Ah[krA0 + (m0 ^ sw)]);
                ah[mf][1] = __float_as_uint(Ah[krA0 + (m1 ^ sw)]);
                ah[mf][2] = __float_as_uint(Ah[krA1 + (m0 ^ sw)]);
                ah[mf][3] = __float_as_uint(Ah[krA1 + (m1 ^ sw)]);
                al[mf][0] = __float_as_uint(Al[krA0 + (m0 ^ sw)]);
                al[mf][1] = __float_as_uint(Al[krA0 + (m1 ^ sw)]);
                al[mf][2] = __float_as_uint(Al[krA1 + (m0 ^ sw)]);
                al[mf][3] = __float_as_uint(Al[krA1 + (m1 ^ sw)]);
            }
#pragma unroll
            for (int nf = 0; nf < 8; nf++) {
                int n = warpN + nf * 8 + gid;
                int pc = n ^ sw;
                unsigned bh0 = __float_as_uint(Bh[krB0 + pc]);
                unsigned bh1 = __float_as_uint(Bh[krB1 + pc]);
                unsigned bl0 = __float_as_uint(Bl[krB0 + pc]);
                unsigned bl1 = __float_as_uint(Bl[krB1 + pc]);
#pragma unroll
                for (int mf = 0; mf < 4; mf++) {
                    mma_tf32(acc[mf][nf], al[mf][0], al[mf][1], al[mf][2], al[mf][3], bh0, bh1);
                    mma_tf32(acc[mf][nf], ah[mf][0], ah[mf][1], ah[mf][2], ah[mf][3], bl0, bl1);
                    mma_tf32(acc[mf][nf], ah[mf][0], ah[mf][1], ah[mf][2], ah[mf][3], bh0, bh1);
                }
            }
        }
        __syncthreads();
    }

    // ---- epilogue
#pragma unroll
    for (int mf = 0; mf < 4; mf++) {
        int r0 = rowBase + warpM + mf * 16 + gid;
        int r1 = r0 + 8;
#pragma unroll
        for (int nf = 0; nf < 8; nf++) {
            int gc = colBase + warpN + nf * 8 + tig * 2;
            float v0 = acc[mf][nf][0], v1 = acc[mf][nf][1];
            float v2 = acc[mf][nf][2], v3 = acc[mf][nf][3];
            if (CBIAS) {
                float2 bb = *(const float2*)(cbias + gc);
                v0 += bb.x; v1 += bb.y; v2 += bb.x; v3 += bb.y;
            }
            if (RELU) {
                v0 = fmaxf(v0, 0.f); v1 = fmaxf(v1, 0.f);
                v2 = fmaxf(v2, 0.f); v3 = fmaxf(v3, 0.f);
            }
            if (r0 < M) { float2 o = {v0, v1}; *(float2*)(C + (size_t)r0 * N + gc) = o; }
            if (r1 < M) { float2 o = {v2, v3}; *(float2*)(C + (size_t)r1 * N + gc) = o; }
        }
    }
}

// ----------------------- per-node attention dots --------------------------
__global__ void k_att(const float* __restrict__ att_src,
                      const float* __restrict__ att_dst, int n) {
    int w = (blockIdx.x * blockDim.x + threadIdx.x) >> 5;
    int lane = threadIdx.x & 31;
    if (w >= n) return;
    float4 hv = ((const float4*)(g_h + (size_t)w * FDIM))[lane];
    float4 as = ((const float4*)att_src)[lane];
    float4 ad = ((const float4*)att_dst)[lane];
    float s = hv.x * as.x + hv.y * as.y + hv.z * as.z + hv.w * as.w;
    float d = hv.x * ad.x + hv.y * ad.y + hv.z * ad.z + hv.w * ad.w;
#pragma unroll
    for (int o = 16; o; o >>= 1) {
        s += __shfl_xor_sync(0xFFFFFFFFu, s, o);
        d += __shfl_xor_sync(0xFFFFFFFFu, d, o);
    }
    if (lane == 0) { g_asrc[w] = s; g_adst[w] = d; }
}

// --------- fused per-node softmax + aggregation (warp per dst) ------------
__global__ void k_gather(int n) {
    int w = (blockIdx.x * blockDim.x + threadIdx.x) >> 5;
    int lane = threadIdx.x & 31;
    if (w >= n) return;

    int base = g_rp[w];
    int deg  = g_rp[w + 1] - base;
    float adst = g_adst[w];

    float m_l = -3.4e38f, z_l = 0.f;
    for (int j = lane; j < deg; j += 32) {
        int s = g_csrc[base + j];
        float e = g_asrc[s] + adst;
        e = (e > 0.f) ? e : NEG_SLOPE * e;
        float mn = fmaxf(m_l, e);
        z_l = z_l * __expf(m_l - mn) + __expf(e - mn);
        m_l = mn;
    }
#pragma unroll
    for (int o = 16; o; o >>= 1) {
        float mo = __shfl_xor_sync(0xFFFFFFFFu, m_l, o);
        float zo = __shfl_xor_sync(0xFFFFFFFFu, z_l, o);
        float mn = fmaxf(m_l, mo);
        z_l = z_l * __expf(m_l - mn) + zo * __expf(mo - mn);
        m_l = mn;
    }
    float m = m_l;
    float inv_z = 1.f / z_l;

    float4 acc = make_float4(0.f, 0.f, 0.f, 0.f);
    for (int j0 = 0; j0 < deg; j0 += 32) {
        int j = j0 + lane;
        int s = 0; float wgt = 0.f;
        if (j < deg) {
            s = g_csrc[base + j];
            float e = g_asrc[s] + adst;
            e = (e > 0.f) ? e : NEG_SLOPE * e;
            wgt = __expf(e - m);
        }
        int cnt = deg - j0; if (cnt > 32) cnt = 32;
        for (int jj = 0; jj < cnt; jj++) {
            int   ss = __shfl_sync(0xFFFFFFFFu, s,   jj);
            float ww = __shfl_sync(0xFFFFFFFFu, wgt, jj);
            float4 v = ((const float4*)(g_h + (size_t)ss * FDIM))[lane];
            acc.x += ww * v.x; acc.y += ww * v.y;
            acc.z += ww * v.z; acc.w += ww * v.w;
        }
    }
    acc.x *= inv_z; acc.y *= inv_z; acc.z *= inv_z; acc.w *= inv_z;
    ((float4*)(g_gat + (size_t)w * FDIM))[lane] = acc;
}

// ----------------------- final 256->1 + sigmoid ---------------------------
__global__ void k_final(const float* __restrict__ W3,
                        const float* __restrict__ b3,
                        float* __restrict__ out, int n) {
    int w = (blockIdx.x * blockDim.x + threadIdx.x) >> 5;
    int lane = threadIdx.x & 31;
    if (w >= n) return;
    const float4* hp = (const float4*)(g_h2 + (size_t)w * HDIM);
    const float4* wp = (const float4*)W3;
    float acc = 0.f;
#pragma unroll
    for (int j = 0; j < 2; j++) {
        float4 h = hp[lane + 32 * j];
        float4 ww = wp[lane + 32 * j];
        acc += h.x * ww.x + h.y * ww.y + h.z * ww.z + h.w * ww.w;
    }
#pragma unroll
    for (int o = 16; o; o >>= 1) acc += __shfl_xor_sync(0xFFFFFFFFu, acc, o);
    if (lane == 0) out[w] = 1.f / (1.f + expf(-(acc + b3[0])));
}

// --------------------------- host launcher --------------------------------
extern "C" void kernel_launch(void* const* d_in, const int* in_sizes, int n_in,
                              void* d_out, int out_size) {
    const float* x       = (const float*)d_in[0];
    const int*   ei      = (const int*)d_in[1];
    const float* W       = (const float*)d_in[2];
    const float* att_src = (const float*)d_in[3];
    const float* att_dst = (const float*)d_in[4];
    const float* bias    = (const float*)d_in[5];
    const float* W1      = (const float*)d_in[6];
    const float* b1      = (const float*)d_in[7];
    const float* W2      = (const float*)d_in[8];
    const float* b2      = (const float*)d_in[9];
    const float* W3      = (const float*)d_in[10];
    const float* b3      = (const float*)d_in[11];
    float* out = (float*)d_out;

    int n = in_sizes[0] / FDIM;
    int E = in_sizes[1] / 2;
    int Etot = E + n;
    int scanBlocks = (n + SCAN_T - 1) / SCAN_T;

    void *p_h, *p_gat, *p_h1, *p_h2, *p_b2;
    cudaGetSymbolAddress(&p_h,   g_h);
    cudaGetSymbolAddress(&p_gat, g_gat);
    cudaGetSymbolAddress(&p_h1,  g_h1);
    cudaGetSymbolAddress(&p_h2,  g_h2);
    cudaGetSymbolAddress(&p_b2,  g_bias2);

    int mBlocks = (n + 255) / 256;

    cudaFuncSetAttribute(k_mma<false, false>,
                         cudaFuncAttributeMaxDynamicSharedMemorySize, SMEM_BYTES);
    cudaFuncSetAttribute(k_mma<true, true>,
                         cudaFuncAttributeMaxDynamicSharedMemorySize, SMEM_BYTES);

    // CSR build + fused bias + GEMM1 (GEMM1 kept at the profiled launch slot)
    k_detect<<<1, 256>>>(ei, E);
    k_convert<<<2048, 256>>>(ei, E, n);
    k_zero<<<512, 256>>>(n);

    // h = x @ W
    k_mma<false, false><<<dim3(1, mBlocks), 256, SMEM_BYTES>>>(
        x, W, (float*)p_h, nullptr, n, FDIM, FDIM);

    k_bias2<<<(HDIM + 7) / 8, 256>>>(bias, W1, b1, FDIM, HDIM);
    k_hist<<<2048, 256>>>(Etot);
    k_scan1<<<scanBlocks, SCAN_T>>>(n);
    k_scan2<<<1, 256>>>(scanBlocks);
    k_scan3<<<scanBlocks, SCAN_T>>>(n, Etot);
    k_slot<<<2048, 256>>>(Etot);

    k_att<<<(n + 7) / 8, 256>>>(att_src, att_dst, n);
    k_gather<<<(n + 7) / 8, 256>>>(n);

    // h1 = relu(gat @ W1 + bias2)      (bias folded: (gat+b)@W1 = gat@W1 + b@W1)
    k_mma<true, true><<<dim3(2, mBlocks), 256, SMEM_BYTES>>>(
        (const float*)p_gat, W1, (float*)p_h1, (const float*)p_b2, n, HDIM, FDIM);
    // h2 = relu(h1 @ W2 + b2)
    k_mma<true, true><<<dim3(2, mBlocks), 256, SMEM_BYTES>>>(
        (const float*)p_h1, W2, (float*)p_h2, b2, n, HDIM, HDIM);
    k_final<<<(n + 7) / 8, 256>>>(W3, b3, out, n);
}

// round 9
// speedup vs baseline: 1.1727x; 1.1727x over previous
#include <cuda_runtime.h>
#include <stdint.h>

#define NN      100000
#define FDIM    128
#define HDIM    256
#define EMAX    1800000
#define NEG_SLOPE 0.2f
#define SCAN_T  512

// dynamic smem (floats), per stage: rawA[4][256][4]=4096 + rawB[16][128]=2048
#define STAGE_F 6144
#define SMEM_FLOATS (2 * STAGE_F)
#define SMEM_BYTES (SMEM_FLOATS * 4)

// -------- scratch (static device arrays; no runtime malloc) ----------
__device__ float g_h   [(size_t)NN * FDIM];
__device__ float g_asrc[NN];
__device__ float g_adst[NN];
__device__ float g_gat [(size_t)NN * FDIM];
__device__ float g_h1  [(size_t)NN * HDIM];
__device__ float g_h2  [(size_t)NN * HDIM];
__device__ float g_bias2[HDIM];               // b1 + bias @ W1
__device__ int   g_src [EMAX];
__device__ int   g_dst [EMAX];
__device__ int   g_csrc[EMAX];
__device__ int   g_cnt [NN];
__device__ int   g_cnt2[NN];
__device__ int   g_rp  [NN + 1];
__device__ int   g_part[256];
__device__ int   g_is64;

// --------------------------- dtype probe ---------------------------
__global__ void k_detect(const int* __restrict__ ei, int E) {
    __shared__ int nz;
    if (threadIdx.x == 0) nz = 0;
    __syncthreads();
    int samples = 4096;
    if (samples > E) samples = E;
    for (int i = threadIdx.x; i < samples; i += blockDim.x)
        if (ei[2 * i + 1] != 0) atomicOr(&nz, 1);
    __syncthreads();
    if (threadIdx.x == 0) g_is64 = (nz == 0) ? 1 : 0;
}

// ----------------- edge expansion (+ self loops) -------------------
__global__ void k_convert(const int* __restrict__ ei, int E, int n) {
    int tot = E + n;
    int stride = gridDim.x * blockDim.x;
    int is64 = g_is64;
    for (int idx = blockIdx.x * blockDim.x + threadIdx.x; idx < tot; idx += stride) {
        int s, d;
        if (idx < E) {
            if (is64) { s = ei[2 * idx]; d = ei[2 * E + 2 * idx]; }
            else      { s = ei[idx];     d = ei[E + idx]; }
        } else {
            s = d = idx - E;
        }
        g_src[idx] = s;
        g_dst[idx] = d;
    }
}

__global__ void k_zero(int n) {
    int stride = gridDim.x * blockDim.x;
    for (int i = blockIdx.x * blockDim.x + threadIdx.x; i < n; i += stride) {
        g_cnt[i] = 0; g_cnt2[i] = 0;
    }
}

__global__ void k_hist(int tot) {
    int stride = gridDim.x * blockDim.x;
    for (int i = blockIdx.x * blockDim.x + threadIdx.x; i < tot; i += stride)
        atomicAdd(&g_cnt[g_dst[i]], 1);
}

// ------------------------ hierarchical scan ------------------------
__global__ void k_scan1(int n) {
    __shared__ int sh[SCAN_T];
    int t = threadIdx.x;
    int i = blockIdx.x * SCAN_T + t;
    int v = (i < n) ? g_cnt[i] : 0;
    sh[t] = v;
    __syncthreads();
    for (int o = 1; o < SCAN_T; o <<= 1) {
        int x = (t >= o) ? sh[t - o] : 0;
        __syncthreads();
        sh[t] += x;
        __syncthreads();
    }
    if (i < n) g_rp[i] = sh[t] - v;
    if (t == SCAN_T - 1) g_part[blockIdx.x] = sh[t];
}

__global__ void k_scan2(int nb) {
    __shared__ int sh[256];
    int t = threadIdx.x;
    int v = (t < nb) ? g_part[t] : 0;
    sh[t] = v;
    __syncthreads();
    for (int o = 1; o < 256; o <<= 1) {
        int x = (t >= o) ? sh[t - o] : 0;
        __syncthreads();
        sh[t] += x;
        __syncthreads();
    }
    if (t < nb) g_part[t] = sh[t] - v;
}

__global__ void k_scan3(int n, int etot) {
    int i = blockIdx.x * SCAN_T + threadIdx.x;
    if (i < n) g_rp[i] += g_part[blockIdx.x];
    if (i == 0) g_rp[n] = etot;
}

__global__ void k_slot(int tot) {
    int stride = gridDim.x * blockDim.x;
    for (int i = blockIdx.x * blockDim.x + threadIdx.x; i < tot; i += stride) {
        int d = g_dst[i];
        int slot = g_rp[d] + atomicAdd(&g_cnt2[d], 1);
        g_csrc[slot] = g_src[i];
    }
}

// ---------------- fused layer-1 bias: bias2 = b1 + bias @ W1 --------------
__global__ void k_bias2(const float* __restrict__ bias,
                        const float* __restrict__ W1,
                        const float* __restrict__ b1, int K, int N) {
    int n = blockIdx.x * (blockDim.x >> 5) + (threadIdx.x >> 5);
    int lane = threadIdx.x & 31;
    if (n >= N) return;
    float s = 0.f;
    for (int k = lane; k < K; k += 32) s += bias[k] * W1[(size_t)k * N + n];
#pragma unroll
    for (int o = 16; o; o >>= 1) s += __shfl_xor_sync(0xFFFFFFFFu, s, o);
    if (lane == 0) g_bias2[n] = s + b1[n];
}

// --------------------------- tf32 helpers ---------------------------
__device__ __forceinline__ unsigned tf32_rna(float v) {
    unsigned r;
    asm("cvt.rna.tf32.f32 %0, %1;" : "=r"(r) : "f"(v));
    return r;
}

__device__ __forceinline__ void mma_tf32(float c[4],
                                         unsigned a0, unsigned a1, unsigned a2, unsigned a3,
                                         unsigned b0, unsigned b1) {
    asm volatile(
        "mma.sync.aligned.m16n8k8.row.col.f32.tf32.tf32.f32 "
        "{%0,%1,%2,%3}, {%4,%5,%6,%7}, {%8,%9}, {%0,%1,%2,%3};"
        : "+f"(c[0]), "+f"(c[1]), "+f"(c[2]), "+f"(c[3])
        : "r"(a0), "r"(a1), "r"(a2), "r"(a3), "r"(b0), "r"(b1));
}

__device__ __forceinline__ void cp_async16(uint32_t dst, const float* src, bool pred) {
    int sz = pred ? 16 : 0;
    asm volatile("cp.async.cg.shared.global [%0], [%1], 16, %2;"
                 :: "r"(dst), "l"(src), "r"(sz));
}
__device__ __forceinline__ void cp_commit() {
    asm volatile("cp.async.commit_group;");
}
template<int NW>
__device__ __forceinline__ void cp_wait() {
    asm volatile("cp.async.wait_group %0;" :: "n"(NW));
}

// --------- tensor-core GEMM: tf32x3, 256x128 CTA tile, BK=16 --------------
// 256 threads, 8 warps (4M x 2N), 64x64 warp tiles.
// cp.async lands RAW fp32 in fragment-friendly layouts; the hi/lo tf32
// split happens in registers at fragment-load time (no plane pass, no STS).
//   rawA[k4][m][4]: elem (m,k) at k4*1024 + m*4 + (k&3)  — conflict-free
//   rawB[k][n^((k&3)*8)]                                  — conflict-free
template<bool RELU, bool CBIAS>
__global__ void __launch_bounds__(256) k_mma(
    const float* __restrict__ A, const float* __restrict__ B,
    float* __restrict__ C, const float* __restrict__ cbias,
    int M, int N, int K)
{
    extern __shared__ float sm[];
    const uint32_t smem_base = (uint32_t)__cvta_generic_to_shared(sm);

    const int tid  = threadIdx.x;
    const int wid  = tid >> 5;
    const int lane = tid & 31;
    const int gid  = lane >> 2;
    const int tig  = lane & 3;
    const int warpM = (wid & 3) * 64;
    const int warpN = (wid >> 2) * 64;
    const int rowBase = blockIdx.y * 256;
    const int colBase = blockIdx.x * 128;

    float acc[4][8][4];
#pragma unroll
    for (int mf = 0; mf < 4; mf++)
#pragma unroll
        for (int nf = 0; nf < 8; nf++)
#pragma unroll
            for (int r = 0; r < 4; r++) acc[mf][nf][r] = 0.f;

    const int grA = rowBase + tid;
    const bool pA = grA < M;
    const float* srcArow = A + (size_t)(pA ? grA : 0) * K;

    auto cp_slab = [&](int k0, int stage) {
        uint32_t raA = smem_base + (stage * STAGE_F) * 4;
        uint32_t raB = raA + 4096 * 4;
#pragma unroll
        for (int k4 = 0; k4 < 4; k4++)
            cp_async16(raA + (k4 * 1024 + tid * 4) * 4, srcArow + k0 + k4 * 4, pA);
#pragma unroll
        for (int i = 0; i < 2; i++) {
            int idx = i * 256 + tid;
            int k = idx >> 5, n4 = idx & 31;
            int dstCol = (n4 * 4) ^ ((k & 3) * 8);       // 16B-granular swizzle
            cp_async16(raB + (k * 128 + dstCol) * 4,
                       B + (size_t)(k0 + k) * N + colBase + n4 * 4, true);
        }
    };

    const int S = K >> 4;

    // prologue: stages 0,1 in flight; wait for slab 0
    cp_slab(0, 0);  cp_commit();
    cp_slab(16, 1); cp_commit();
    cp_wait<1>();
    __syncthreads();

    for (int s = 0; s < S; s++) {
        const int stage = s & 1;
        const float* rawA = sm + stage * STAGE_F;
        const float* rawB = rawA + 4096;

#pragma unroll
        for (int ks = 0; ks < 2; ks++) {
            const int kO = ks * 8;
            // A fragments: k = kO+tig (chunk kO/4) and kO+tig+4 (chunk kO/4+1)
            const float* A0 = rawA + (kO >> 2) * 1024 + tig;
            const float* A1 = A0 + 1024;
            unsigned ah[4][4], al[4][4];
#pragma unroll
            for (int mf = 0; mf < 4; mf++) {
                int m0 = (warpM + mf * 16 + gid) * 4;
                int m1 = m0 + 32;                       // +8 rows * 4
                float r0 = A0[m0], r1 = A0[m1], r2 = A1[m0], r3 = A1[m1];
                float h;
                h = __uint_as_float(tf32_rna(r0)); ah[mf][0] = __float_as_uint(h); al[mf][0] = tf32_rna(r0 - h);
                h = __uint_as_float(tf32_rna(r1)); ah[mf][1] = __float_as_uint(h); al[mf][1] = tf32_rna(r1 - h);
                h = __uint_as_float(tf32_rna(r2)); ah[mf][2] = __float_as_uint(h); al[mf][2] = tf32_rna(r2 - h);
                h = __uint_as_float(tf32_rna(r3)); ah[mf][3] = __float_as_uint(h); al[mf][3] = tf32_rna(r3 - h);
            }
            const int swb = tig * 8;
            const float* B0 = rawB + (kO + tig) * 128;
            const float* B1 = rawB + (kO + tig + 4) * 128;
#pragma unroll
            for (int nf = 0; nf < 8; nf++) {
                int pc = (warpN + nf * 8 + gid) ^ swb;
                float q0 = B0[pc], q1 = B1[pc];
                float h0f = __uint_as_float(tf32_rna(q0));
                float h1f = __uint_as_float(tf32_rna(q1));
                unsigned bh0 = __float_as_uint(h0f);
                unsigned bh1 = __float_as_uint(h1f);
                unsigned bl0 = tf32_rna(q0 - h0f);
                unsigned bl1 = tf32_rna(q1 - h1f);
#pragma unroll
                for (int mf = 0; mf < 4; mf++) {
                    mma_tf32(acc[mf][nf], al[mf][0], al[mf][1], al[mf][2], al[mf][3], bh0, bh1);
                    mma_tf32(acc[mf][nf], ah[mf][0], ah[mf][1], ah[mf][2], ah[mf][3], bl0, bl1);
                    mma_tf32(acc[mf][nf], ah[mf][0], ah[mf][1], ah[mf][2], ah[mf][3], bh0, bh1);
                }
            }
        }

        // stage now free; refill it with slab s+2, then ensure slab s+1 ready
        __syncthreads();
        if (s + 2 < S) {
            cp_slab((s + 2) * 16, stage);
            cp_commit();
            cp_wait<1>();          // slab s+1 complete (s+2 still pending)
        } else {
            cp_wait<0>();          // drain: slab s+1 (if any) complete
        }
        __syncthreads();
    }

    // ---- epilogue
#pragma unroll
    for (int mf = 0; mf < 4; mf++) {
        int r0 = rowBase + warpM + mf * 16 + gid;
        int r1 = r0 + 8;
#pragma unroll
        for (int nf = 0; nf < 8; nf++) {
            int gc = colBase + warpN + nf * 8 + tig * 2;
            float v0 = acc[mf][nf][0], v1 = acc[mf][nf][1];
            float v2 = acc[mf][nf][2], v3 = acc[mf][nf][3];
            if (CBIAS) {
                float2 bb = *(const float2*)(cbias + gc);
                v0 += bb.x; v1 += bb.y; v2 += bb.x; v3 += bb.y;
            }
            if (RELU) {
                v0 = fmaxf(v0, 0.f); v1 = fmaxf(v1, 0.f);
                v2 = fmaxf(v2, 0.f); v3 = fmaxf(v3, 0.f);
            }
            if (r0 < M) { float2 o = {v0, v1}; *(float2*)(C + (size_t)r0 * N + gc) = o; }
            if (r1 < M) { float2 o = {v2, v3}; *(float2*)(C + (size_t)r1 * N + gc) = o; }
        }
    }
}

// ----------------------- per-node attention dots --------------------------
__global__ void k_att(const float* __restrict__ att_src,
                      const float* __restrict__ att_dst, int n) {
    int w = (blockIdx.x * blockDim.x + threadIdx.x) >> 5;
    int lane = threadIdx.x & 31;
    if (w >= n) return;
    float4 hv = ((const float4*)(g_h + (size_t)w * FDIM))[lane];
    float4 as = ((const float4*)att_src)[lane];
    float4 ad = ((const float4*)att_dst)[lane];
    float s = hv.x * as.x + hv.y * as.y + hv.z * as.z + hv.w * as.w;
    float d = hv.x * ad.x + hv.y * ad.y + hv.z * ad.z + hv.w * ad.w;
#pragma unroll
    for (int o = 16; o; o >>= 1) {
        s += __shfl_xor_sync(0xFFFFFFFFu, s, o);
        d += __shfl_xor_sync(0xFFFFFFFFu, d, o);
    }
    if (lane == 0) { g_asrc[w] = s; g_adst[w] = d; }
}

// --------- fused per-node softmax + aggregation (warp per dst) ------------
__global__ void k_gather(int n) {
    int w = (blockIdx.x * blockDim.x + threadIdx.x) >> 5;
    int lane = threadIdx.x & 31;
    if (w >= n) return;

    int base = g_rp[w];
    int deg  = g_rp[w + 1] - base;
    float adst = g_adst[w];

    float m_l = -3.4e38f, z_l = 0.f;
    for (int j = lane; j < deg; j += 32) {
        int s = g_csrc[base + j];
        float e = g_asrc[s] + adst;
        e = (e > 0.f) ? e : NEG_SLOPE * e;
        float mn = fmaxf(m_l, e);
        z_l = z_l * __expf(m_l - mn) + __expf(e - mn);
        m_l = mn;
    }
#pragma unroll
    for (int o = 16; o; o >>= 1) {
        float mo = __shfl_xor_sync(0xFFFFFFFFu, m_l, o);
        float zo = __shfl_xor_sync(0xFFFFFFFFu, z_l, o);
        float mn = fmaxf(m_l, mo);
        z_l = z_l * __expf(m_l - mn) + zo * __expf(mo - mn);
        m_l = mn;
    }
    float m = m_l;
    float inv_z = 1.f / z_l;

    float4 acc = make_float4(0.f, 0.f, 0.f, 0.f);
    for (int j0 = 0; j0 < deg; j0 += 32) {
        int j = j0 + lane;
        int s = 0; float wgt = 0.f;
        if (j < deg) {
            s = g_csrc[base + j];
            float e = g_asrc[s] + adst;
            e = (e > 0.f) ? e : NEG_SLOPE * e;
            wgt = __expf(e - m);
        }
        int cnt = deg - j0; if (cnt > 32) cnt = 32;
        for (int jj = 0; jj < cnt; jj++) {
            int   ss = __shfl_sync(0xFFFFFFFFu, s,   jj);
            float ww = __shfl_sync(0xFFFFFFFFu, wgt, jj);
            float4 v = ((const float4*)(g_h + (size_t)ss * FDIM))[lane];
            acc.x += ww * v.x; acc.y += ww * v.y;
            acc.z += ww * v.z; acc.w += ww * v.w;
        }
    }
    acc.x *= inv_z; acc.y *= inv_z; acc.z *= inv_z; acc.w *= inv_z;
    ((float4*)(g_gat + (size_t)w * FDIM))[lane] = acc;
}

// ----------------------- final 256->1 + sigmoid ---------------------------
__global__ void k_final(const float* __restrict__ W3,
                        const float* __restrict__ b3,
                        float* __restrict__ out, int n) {
    int w = (blockIdx.x * blockDim.x + threadIdx.x) >> 5;
    int lane = threadIdx.x & 31;
    if (w >= n) return;
    const float4* hp = (const float4*)(g_h2 + (size_t)w * HDIM);
    const float4* wp = (const float4*)W3;
    float acc = 0.f;
#pragma unroll
    for (int j = 0; j < 2; j++) {
        float4 h = hp[lane + 32 * j];
        float4 ww = wp[lane + 32 * j];
        acc += h.x * ww.x + h.y * ww.y + h.z * ww.z + h.w * ww.w;
    }
#pragma unroll
    for (int o = 16; o; o >>= 1) acc += __shfl_xor_sync(0xFFFFFFFFu, acc, o);
    if (lane == 0) out[w] = 1.f / (1.f + expf(-(acc + b3[0])));
}

// --------------------------- host launcher --------------------------------
extern "C" void kernel_launch(void* const* d_in, const int* in_sizes, int n_in,
                              void* d_out, int out_size) {
    const float* x       = (const float*)d_in[0];
    const int*   ei      = (const int*)d_in[1];
    const float* W       = (const float*)d_in[2];
    const float* att_src = (const float*)d_in[3];
    const float* att_dst = (const float*)d_in[4];
    const float* bias    = (const float*)d_in[5];
    const float* W1      = (const float*)d_in[6];
    const float* b1      = (const float*)d_in[7];
    const float* W2      = (const float*)d_in[8];
    const float* b2      = (const float*)d_in[9];
    const float* W3      = (const float*)d_in[10];
    const float* b3      = (const float*)d_in[11];
    float* out = (float*)d_out;

    int n = in_sizes[0] / FDIM;
    int E = in_sizes[1] / 2;
    int Etot = E + n;
    int scanBlocks = (n + SCAN_T - 1) / SCAN_T;

    void *p_h, *p_gat, *p_h1, *p_h2, *p_b2;
    cudaGetSymbolAddress(&p_h,   g_h);
    cudaGetSymbolAddress(&p_gat, g_gat);
    cudaGetSymbolAddress(&p_h1,  g_h1);
    cudaGetSymbolAddress(&p_h2,  g_h2);
    cudaGetSymbolAddress(&p_b2,  g_bias2);

    int mBlocks = (n + 255) / 256;

    cudaFuncSetAttribute(k_mma<false, false>,
                         cudaFuncAttributeMaxDynamicSharedMemorySize, SMEM_BYTES);
    cudaFuncSetAttribute(k_mma<true, true>,
                         cudaFuncAttributeMaxDynamicSharedMemorySize, SMEM_BYTES);

    // CSR build + fused bias + GEMM1 (GEMM1 kept at the profiled launch slot)
    k_detect<<<1, 256>>>(ei, E);
    k_convert<<<2048, 256>>>(ei, E, n);
    k_zero<<<512, 256>>>(n);

    // h = x @ W
    k_mma<false, false><<<dim3(1, mBlocks), 256, SMEM_BYTES>>>(
        x, W, (float*)p_h, nullptr, n, FDIM, FDIM);

    k_bias2<<<(HDIM + 7) / 8, 256>>>(bias, W1, b1, FDIM, HDIM);
    k_hist<<<2048, 256>>>(Etot);
    k_scan1<<<scanBlocks, SCAN_T>>>(n);
    k_scan2<<<1, 256>>>(scanBlocks);
    k_scan3<<<scanBlocks, SCAN_T>>>(n, Etot);
    k_slot<<<2048, 256>>>(Etot);

    k_att<<<(n + 7) / 8, 256>>>(att_src, att_dst, n);
    k_gather<<<(n + 7) / 8, 256>>>(n);

    // h1 = relu(gat @ W1 + bias2)   (bias folded: (gat+b)@W1 = gat@W1 + b@W1)
    k_mma<true, true><<<dim3(2, mBlocks), 256, SMEM_BYTES>>>(
        (const float*)p_gat, W1, (float*)p_h1, (const float*)p_b2, n, HDIM, FDIM);
    // h2 = relu(h1 @ W2 + b2)
    k_mma<true, true><<<dim3(2, mBlocks), 256, SMEM_BYTES>>>(
        (const float*)p_h1, W2, (float*)p_h2, b2, n, HDIM, HDIM);
    k_final<<<(n + 7) / 8, 256>>>(W3, b3, out, n);
}

// round 10
// speedup vs baseline: 1.2777x; 1.0895x over previous
#include <cuda_runtime.h>
#include <stdint.h>

#define NN      100000
#define FDIM    128
#define HDIM    256
#define EMAX    1800000
#define NEG_SLOPE 0.2f
#define SCAN_T  512

// dynamic smem (floats), per stage: rawA[4][128][4]=2048 + rawB[16][128]=2048
#define STAGE_F 4096
#define SMEM_FLOATS (2 * STAGE_F)
#define SMEM_BYTES (SMEM_FLOATS * 4)

// -------- scratch (static device arrays; no runtime malloc) ----------
__device__ float g_h   [(size_t)NN * FDIM];
__device__ float g_asrc[NN];
__device__ float g_adst[NN];
__device__ float g_gat [(size_t)NN * FDIM];
__device__ float g_h1  [(size_t)NN * HDIM];
__device__ float g_h2  [(size_t)NN * HDIM];
__device__ float g_bias2[HDIM];               // b1 + bias @ W1
__device__ int   g_src [EMAX];
__device__ int   g_dst [EMAX];
__device__ int   g_csrc[EMAX];
__device__ int   g_cnt [NN];
__device__ int   g_cnt2[NN];
__device__ int   g_rp  [NN + 1];
__device__ int   g_part[256];
__device__ int   g_is64;

// --------------------------- dtype probe ---------------------------
__global__ void k_detect(const int* __restrict__ ei, int E) {
    __shared__ int nz;
    if (threadIdx.x == 0) nz = 0;
    __syncthreads();
    int samples = 4096;
    if (samples > E) samples = E;
    for (int i = threadIdx.x; i < samples; i += blockDim.x)
        if (ei[2 * i + 1] != 0) atomicOr(&nz, 1);
    __syncthreads();
    if (threadIdx.x == 0) g_is64 = (nz == 0) ? 1 : 0;
}

// ----------------- edge expansion (+ self loops) -------------------
__global__ void k_convert(const int* __restrict__ ei, int E, int n) {
    int tot = E + n;
    int stride = gridDim.x * blockDim.x;
    int is64 = g_is64;
    for (int idx = blockIdx.x * blockDim.x + threadIdx.x; idx < tot; idx += stride) {
        int s, d;
        if (idx < E) {
            if (is64) { s = ei[2 * idx]; d = ei[2 * E + 2 * idx]; }
            else      { s = ei[idx];     d = ei[E + idx]; }
        } else {
            s = d = idx - E;
        }
        g_src[idx] = s;
        g_dst[idx] = d;
    }
}

__global__ void k_zero(int n) {
    int stride = gridDim.x * blockDim.x;
    for (int i = blockIdx.x * blockDim.x + threadIdx.x; i < n; i += stride) {
        g_cnt[i] = 0; g_cnt2[i] = 0;
    }
}

__global__ void k_hist(int tot) {
    int stride = gridDim.x * blockDim.x;
    for (int i = blockIdx.x * blockDim.x + threadIdx.x; i < tot; i += stride)
        atomicAdd(&g_cnt[g_dst[i]], 1);
}

// ------------------------ hierarchical scan ------------------------
__global__ void k_scan1(int n) {
    __shared__ int sh[SCAN_T];
    int t = threadIdx.x;
    int i = blockIdx.x * SCAN_T + t;
    int v = (i < n) ? g_cnt[i] : 0;
    sh[t] = v;
    __syncthreads();
    for (int o = 1; o < SCAN_T; o <<= 1) {
        int x = (t >= o) ? sh[t - o] : 0;
        __syncthreads();
        sh[t] += x;
        __syncthreads();
    }
    if (i < n) g_rp[i] = sh[t] - v;
    if (t == SCAN_T - 1) g_part[blockIdx.x] = sh[t];
}

__global__ void k_scan2(int nb) {
    __shared__ int sh[256];
    int t = threadIdx.x;
    int v = (t < nb) ? g_part[t] : 0;
    sh[t] = v;
    __syncthreads();
    for (int o = 1; o < 256; o <<= 1) {
        int x = (t >= o) ? sh[t - o] : 0;
        __syncthreads();
        sh[t] += x;
        __syncthreads();
    }
    if (t < nb) g_part[t] = sh[t] - v;
}

__global__ void k_scan3(int n, int etot) {
    int i = blockIdx.x * SCAN_T + threadIdx.x;
    if (i < n) g_rp[i] += g_part[blockIdx.x];
    if (i == 0) g_rp[n] = etot;
}

__global__ void k_slot(int tot) {
    int stride = gridDim.x * blockDim.x;
    for (int i = blockIdx.x * blockDim.x + threadIdx.x; i < tot; i += stride) {
        int d = g_dst[i];
        int slot = g_rp[d] + atomicAdd(&g_cnt2[d], 1);
        g_csrc[slot] = g_src[i];
    }
}

// ---------------- fused layer-1 bias: bias2 = b1 + bias @ W1 --------------
__global__ void k_bias2(const float* __restrict__ bias,
                        const float* __restrict__ W1,
                        const float* __restrict__ b1, int K, int N) {
    int n = blockIdx.x * (blockDim.x >> 5) + (threadIdx.x >> 5);
    int lane = threadIdx.x & 31;
    if (n >= N) return;
    float s = 0.f;
    for (int k = lane; k < K; k += 32) s += bias[k] * W1[(size_t)k * N + n];
#pragma unroll
    for (int o = 16; o; o >>= 1) s += __shfl_xor_sync(0xFFFFFFFFu, s, o);
    if (lane == 0) g_bias2[n] = s + b1[n];
}

// --------------------------- tf32 helpers ---------------------------
__device__ __forceinline__ unsigned tf32_rna(float v) {
    unsigned r;
    asm("cvt.rna.tf32.f32 %0, %1;" : "=r"(r) : "f"(v));
    return r;
}

__device__ __forceinline__ void mma_tf32(float c[4],
                                         unsigned a0, unsigned a1, unsigned a2, unsigned a3,
                                         unsigned b0, unsigned b1) {
    asm volatile(
        "mma.sync.aligned.m16n8k8.row.col.f32.tf32.tf32.f32 "
        "{%0,%1,%2,%3}, {%4,%5,%6,%7}, {%8,%9}, {%0,%1,%2,%3};"
        : "+f"(c[0]), "+f"(c[1]), "+f"(c[2]), "+f"(c[3])
        : "r"(a0), "r"(a1), "r"(a2), "r"(a3), "r"(b0), "r"(b1));
}

__device__ __forceinline__ void cp_async16(uint32_t dst, const float* src, bool pred) {
    int sz = pred ? 16 : 0;
    asm volatile("cp.async.cg.shared.global [%0], [%1], 16, %2;"
                 :: "r"(dst), "l"(src), "r"(sz));
}
__device__ __forceinline__ void cp_commit() {
    asm volatile("cp.async.commit_group;");
}
template<int NW>
__device__ __forceinline__ void cp_wait() {
    asm volatile("cp.async.wait_group %0;" :: "n"(NW));
}

// --------- tensor-core GEMM: tf32x3, 128x128 CTA tile, BK=16 --------------
// 256 threads, 8 warps (4M x 2N), 32x64 warp tiles, 2 CTAs/SM.
// cp.async lands RAW fp32 in fragment-friendly layouts; hi/lo tf32 split
// happens in registers at fragment-load time (no plane pass, no STS).
//   rawA[k4][m][4]: elem (m,k) at k4*512 + m*4 + (k&3)   — conflict-free
//   rawB[k][n^((k&3)*8)]                                  — conflict-free
template<bool RELU, bool CBIAS>
__global__ void __launch_bounds__(256, 2) k_mma(
    const float* __restrict__ A, const float* __restrict__ B,
    float* __restrict__ C, const float* __restrict__ cbias,
    int M, int N, int K)
{
    extern __shared__ float sm[];
    const uint32_t smem_base = (uint32_t)__cvta_generic_to_shared(sm);

    const int tid  = threadIdx.x;
    const int wid  = tid >> 5;
    const int lane = tid & 31;
    const int gid  = lane >> 2;
    const int tig  = lane & 3;
    const int warpM = (wid & 3) * 32;
    const int warpN = (wid >> 2) * 64;
    const int rowBase = blockIdx.y * 128;
    const int colBase = blockIdx.x * 128;

    float acc[2][8][4];
#pragma unroll
    for (int mf = 0; mf < 2; mf++)
#pragma unroll
        for (int nf = 0; nf < 8; nf++)
#pragma unroll
            for (int r = 0; r < 4; r++) acc[mf][nf][r] = 0.f;

    auto cp_slab = [&](int k0, int stage) {
        uint32_t raA = smem_base + (stage * STAGE_F) * 4;
        uint32_t raB = raA + 2048 * 4;
        // A: 512 float4 slots = 4 k-chunks x 128 rows
#pragma unroll
        for (int it = 0; it < 2; it++) {
            int idx = it * 256 + tid;
            int row = idx & 127;
            int k4  = idx >> 7;
            int gr = rowBase + row;
            bool p = gr < M;
            cp_async16(raA + (k4 * 512 + row * 4) * 4,
                       A + (size_t)(p ? gr : 0) * K + k0 + k4 * 4, p);
        }
        // B: 512 float4 slots = 16 k x 32 n4
#pragma unroll
        for (int it = 0; it < 2; it++) {
            int idx = it * 256 + tid;
            int k = idx >> 5, n4 = idx & 31;
            int dstCol = (n4 * 4) ^ ((k & 3) * 8);       // 16B-granular swizzle
            cp_async16(raB + (k * 128 + dstCol) * 4,
                       B + (size_t)(k0 + k) * N + colBase + n4 * 4, true);
        }
    };

    const int S = K >> 4;

    // prologue: stages 0,1 in flight; wait for slab 0
    cp_slab(0, 0);  cp_commit();
    cp_slab(16, 1); cp_commit();
    cp_wait<1>();
    __syncthreads();

    for (int s = 0; s < S; s++) {
        const int stage = s & 1;
        const float* rawA = sm + stage * STAGE_F;
        const float* rawB = rawA + 2048;

#pragma unroll
        for (int ks = 0; ks < 2; ks++) {
            const int kO = ks * 8;
            // A fragments: k = kO+tig (chunk kO/4) and kO+tig+4 (chunk kO/4+1)
            const float* A0 = rawA + (kO >> 2) * 512 + tig;
            const float* A1 = A0 + 512;
            unsigned ah[2][4], al[2][4];
#pragma unroll
            for (int mf = 0; mf < 2; mf++) {
                int m0 = (warpM + mf * 16 + gid) * 4;
                int m1 = m0 + 32;                       // +8 rows * 4
                float r0 = A0[m0], r1 = A0[m1], r2 = A1[m0], r3 = A1[m1];
                float h;
                h = __uint_as_float(tf32_rna(r0)); ah[mf][0] = __float_as_uint(h); al[mf][0] = tf32_rna(r0 - h);
                h = __uint_as_float(tf32_rna(r1)); ah[mf][1] = __float_as_uint(h); al[mf][1] = tf32_rna(r1 - h);
                h = __uint_as_float(tf32_rna(r2)); ah[mf][2] = __float_as_uint(h); al[mf][2] = tf32_rna(r2 - h);
                h = __uint_as_float(tf32_rna(r3)); ah[mf][3] = __float_as_uint(h); al[mf][3] = tf32_rna(r3 - h);
            }
            const int swb = tig * 8;
            const float* B0 = rawB + (kO + tig) * 128;
            const float* B1 = rawB + (kO + tig + 4) * 128;
#pragma unroll
            for (int nf = 0; nf < 8; nf++) {
                int pc = (warpN + nf * 8 + gid) ^ swb;
                float q0 = B0[pc], q1 = B1[pc];
                float h0f = __uint_as_float(tf32_rna(q0));
                float h1f = __uint_as_float(tf32_rna(q1));
                unsigned bh0 = __float_as_uint(h0f);
                unsigned bh1 = __float_as_uint(h1f);
                unsigned bl0 = tf32_rna(q0 - h0f);
                unsigned bl1 = tf32_rna(q1 - h1f);
#pragma unroll
                for (int mf = 0; mf < 2; mf++) {
                    mma_tf32(acc[mf][nf], al[mf][0], al[mf][1], al[mf][2], al[mf][3], bh0, bh1);
                    mma_tf32(acc[mf][nf], ah[mf][0], ah[mf][1], ah[mf][2], ah[mf][3], bl0, bl1);
                    mma_tf32(acc[mf][nf], ah[mf][0], ah[mf][1], ah[mf][2], ah[mf][3], bh0, bh1);
                }
            }
        }

        // stage now free; refill it with slab s+2, then ensure slab s+1 ready
        __syncthreads();
        if (s + 2 < S) {
            cp_slab((s + 2) * 16, stage);
            cp_commit();
            cp_wait<1>();          // slab s+1 complete (s+2 still pending)
        } else {
            cp_wait<0>();          // drain: slab s+1 (if any) complete
        }
        __syncthreads();
    }

    // ---- epilogue
#pragma unroll
    for (int mf = 0; mf < 2; mf++) {
        int r0 = rowBase + warpM + mf * 16 + gid;
        int r1 = r0 + 8;
#pragma unroll
        for (int nf = 0; nf < 8; nf++) {
            int gc = colBase + warpN + nf * 8 + tig * 2;
            float v0 = acc[mf][nf][0], v1 = acc[mf][nf][1];
            float v2 = acc[mf][nf][2], v3 = acc[mf][nf][3];
            if (CBIAS) {
                float2 bb = *(const float2*)(cbias + gc);
                v0 += bb.x; v1 += bb.y; v2 += bb.x; v3 += bb.y;
            }
            if (RELU) {
                v0 = fmaxf(v0, 0.f); v1 = fmaxf(v1, 0.f);
                v2 = fmaxf(v2, 0.f); v3 = fmaxf(v3, 0.f);
            }
            if (r0 < M) { float2 o = {v0, v1}; *(float2*)(C + (size_t)r0 * N + gc) = o; }
            if (r1 < M) { float2 o = {v2, v3}; *(float2*)(C + (size_t)r1 * N + gc) = o; }
        }
    }
}

// ----------------------- per-node attention dots --------------------------
__global__ void k_att(const float* __restrict__ att_src,
                      const float* __restrict__ att_dst, int n) {
    int w = (blockIdx.x * blockDim.x + threadIdx.x) >> 5;
    int lane = threadIdx.x & 31;
    if (w >= n) return;
    float4 hv = ((const float4*)(g_h + (size_t)w * FDIM))[lane];
    float4 as = ((const float4*)att_src)[lane];
    float4 ad = ((const float4*)att_dst)[lane];
    float s = hv.x * as.x + hv.y * as.y + hv.z * as.z + hv.w * as.w;
    float d = hv.x * ad.x + hv.y * ad.y + hv.z * ad.z + hv.w * ad.w;
#pragma unroll
    for (int o = 16; o; o >>= 1) {
        s += __shfl_xor_sync(0xFFFFFFFFu, s, o);
        d += __shfl_xor_sync(0xFFFFFFFFu, d, o);
    }
    if (lane == 0) { g_asrc[w] = s; g_adst[w] = d; }
}

// --------- fused per-node softmax + aggregation (warp per dst) ------------
__global__ void k_gather(int n) {
    int w = (blockIdx.x * blockDim.x + threadIdx.x) >> 5;
    int lane = threadIdx.x & 31;
    if (w >= n) return;

    int base = g_rp[w];
    int deg  = g_rp[w + 1] - base;
    float adst = g_adst[w];

    float m_l = -3.4e38f, z_l = 0.f;
    for (int j = lane; j < deg; j += 32) {
        int s = g_csrc[base + j];
        float e = g_asrc[s] + adst;
        e = (e > 0.f) ? e : NEG_SLOPE * e;
        float mn = fmaxf(m_l, e);
        z_l = z_l * __expf(m_l - mn) + __expf(e - mn);
        m_l = mn;
    }
#pragma unroll
    for (int o = 16; o; o >>= 1) {
        float mo = __shfl_xor_sync(0xFFFFFFFFu, m_l, o);
        float zo = __shfl_xor_sync(0xFFFFFFFFu, z_l, o);
        float mn = fmaxf(m_l, mo);
        z_l = z_l * __expf(m_l - mn) + zo * __expf(mo - mn);
        m_l = mn;
    }
    float m = m_l;
    float inv_z = 1.f / z_l;

    float4 acc = make_float4(0.f, 0.f, 0.f, 0.f);
    for (int j0 = 0; j0 < deg; j0 += 32) {
        int j = j0 + lane;
        int s = 0; float wgt = 0.f;
        if (j < deg) {
            s = g_csrc[base + j];
            float e = g_asrc[s] + adst;
            e = (e > 0.f) ? e : NEG_SLOPE * e;
            wgt = __expf(e - m);
        }
        int cnt = deg - j0; if (cnt > 32) cnt = 32;
        for (int jj = 0; jj < cnt; jj++) {
            int   ss = __shfl_sync(0xFFFFFFFFu, s,   jj);
            float ww = __shfl_sync(0xFFFFFFFFu, wgt, jj);
            float4 v = ((const float4*)(g_h + (size_t)ss * FDIM))[lane];
            acc.x += ww * v.x; acc.y += ww * v.y;
            acc.z += ww * v.z; acc.w += ww * v.w;
        }
    }
    acc.x *= inv_z; acc.y *= inv_z; acc.z *= inv_z; acc.w *= inv_z;
    ((float4*)(g_gat + (size_t)w * FDIM))[lane] = acc;
}

// ----------------------- final 256->1 + sigmoid ---------------------------
__global__ void k_final(const float* __restrict__ W3,
                        const float* __restrict__ b3,
                        float* __restrict__ out, int n) {
    int w = (blockIdx.x * blockDim.x + threadIdx.x) >> 5;
    int lane = threadIdx.x & 31;
    if (w >= n) return;
    const float4* hp = (const float4*)(g_h2 + (size_t)w * HDIM);
    const float4* wp = (const float4*)W3;
    float acc = 0.f;
#pragma unroll
    for (int j = 0; j < 2; j++) {
        float4 h = hp[lane + 32 * j];
        float4 ww = wp[lane + 32 * j];
        acc += h.x * ww.x + h.y * ww.y + h.z * ww.z + h.w * ww.w;
    }
#pragma unroll
    for (int o = 16; o; o >>= 1) acc += __shfl_xor_sync(0xFFFFFFFFu, acc, o);
    if (lane == 0) out[w] = 1.f / (1.f + expf(-(acc + b3[0])));
}

// --------------------------- host launcher --------------------------------
extern "C" void kernel_launch(void* const* d_in, const int* in_sizes, int n_in,
                              void* d_out, int out_size) {
    const float* x       = (const float*)d_in[0];
    const int*   ei      = (const int*)d_in[1];
    const float* W       = (const float*)d_in[2];
    const float* att_src = (const float*)d_in[3];
    const float* att_dst = (const float*)d_in[4];
    const float* bias    = (const float*)d_in[5];
    const float* W1      = (const float*)d_in[6];
    const float* b1      = (const float*)d_in[7];
    const float* W2      = (const float*)d_in[8];
    const float* b2      = (const float*)d_in[9];
    const float* W3      = (const float*)d_in[10];
    const float* b3      = (const float*)d_in[11];
    float* out = (float*)d_out;

    int n = in_sizes[0] / FDIM;
    int E = in_sizes[1] / 2;
    int Etot = E + n;
    int scanBlocks = (n + SCAN_T - 1) / SCAN_T;

    void *p_h, *p_gat, *p_h1, *p_h2, *p_b2;
    cudaGetSymbolAddress(&p_h,   g_h);
    cudaGetSymbolAddress(&p_gat, g_gat);
    cudaGetSymbolAddress(&p_h1,  g_h1);
    cudaGetSymbolAddress(&p_h2,  g_h2);
    cudaGetSymbolAddress(&p_b2,  g_bias2);

    int mBlocks = (n + 127) / 128;

    cudaFuncSetAttribute(k_mma<false, false>,
                         cudaFuncAttributeMaxDynamicSharedMemorySize, SMEM_BYTES);
    cudaFuncSetAttribute(k_mma<true, true>,
                         cudaFuncAttributeMaxDynamicSharedMemorySize, SMEM_BYTES);

    // CSR build + fused bias + GEMM1 (GEMM1 kept at the profiled launch slot)
    k_detect<<<1, 256>>>(ei, E);
    k_convert<<<2048, 256>>>(ei, E, n);
    k_zero<<<512, 256>>>(n);

    // h = x @ W
    k_mma<false, false><<<dim3(1, mBlocks), 256, SMEM_BYTES>>>(
        x, W, (float*)p_h, nullptr, n, FDIM, FDIM);

    k_bias2<<<(HDIM + 7) / 8, 256>>>(bias, W1, b1, FDIM, HDIM);
    k_hist<<<2048, 256>>>(Etot);
    k_scan1<<<scanBlocks, SCAN_T>>>(n);
    k_scan2<<<1, 256>>>(scanBlocks);
    k_scan3<<<scanBlocks, SCAN_T>>>(n, Etot);
    k_slot<<<2048, 256>>>(Etot);

    k_att<<<(n + 7) / 8, 256>>>(att_src, att_dst, n);
    k_gather<<<(n + 7) / 8, 256>>>(n);

    // h1 = relu(gat @ W1 + bias2)   (bias folded: (gat+b)@W1 = gat@W1 + b@W1)
    k_mma<true, true><<<dim3(2, mBlocks), 256, SMEM_BYTES>>>(
        (const float*)p_gat, W1, (float*)p_h1, (const float*)p_b2, n, HDIM, FDIM);
    // h2 = relu(h1 @ W2 + b2)
    k_mma<true, true><<<dim3(2, mBlocks), 256, SMEM_BYTES>>>(
        (const float*)p_h1, W2, (float*)p_h2, b2, n, HDIM, HDIM);
    k_final<<<(n + 7) / 8, 256>>>(W3, b3, out, n);
}

// round 11
// speedup vs baseline: 1.5702x; 1.2290x over previous
#include <cuda_runtime.h>
#include <cuda_bf16.h>
#include <stdint.h>

#define NN      100000
#define FDIM    128
#define HDIM    256
#define EMAX    1800000
#define NEG_SLOPE 0.2f
#define SCAN_T  512

// dynamic smem per stage (in 4B words):
//   rawA fp32 [k4][m][4]            : 2048 words (8 KB)
//   Bth planes [n=128][8 k-words]   : 1024 words (4 KB)
//   Btl planes                      : 1024 words (4 KB)
#define STAGE_F 4096
#define SMEM_FLOATS (2 * STAGE_F)
#define SMEM_BYTES (SMEM_FLOATS * 4)

// -------- scratch (static device arrays; no runtime malloc) ----------
__device__ float g_h   [(size_t)NN * FDIM];
__device__ float g_asrc[NN];
__device__ float g_adst[NN];
__device__ float g_gat [(size_t)NN * FDIM];
__device__ float g_h1  [(size_t)NN * HDIM];
__device__ float g_h2  [(size_t)NN * HDIM];
__device__ float g_bias2[HDIM];               // b1 + bias @ W1
__device__ int   g_src [EMAX];
__device__ int   g_dst [EMAX];
__device__ int   g_csrc[EMAX];
__device__ int   g_cnt [NN];
__device__ int   g_cnt2[NN];
__device__ int   g_rp  [NN + 1];
__device__ int   g_part[256];
__device__ int   g_is64;
// weight hi/lo bf16 planes, TRANSPOSED to [N][K]
__device__ __nv_bfloat16 g_wth [FDIM * FDIM];
__device__ __nv_bfloat16 g_wtl [FDIM * FDIM];
__device__ __nv_bfloat16 g_w1th[HDIM * FDIM];
__device__ __nv_bfloat16 g_w1tl[HDIM * FDIM];
__device__ __nv_bfloat16 g_w2th[HDIM * HDIM];
__device__ __nv_bfloat16 g_w2tl[HDIM * HDIM];

// --------------------------- dtype probe ---------------------------
__global__ void k_detect(const int* __restrict__ ei, int E) {
    __shared__ int nz;
    if (threadIdx.x == 0) nz = 0;
    __syncthreads();
    int samples = 4096;
    if (samples > E) samples = E;
    for (int i = threadIdx.x; i < samples; i += blockDim.x)
        if (ei[2 * i + 1] != 0) atomicOr(&nz, 1);
    __syncthreads();
    if (threadIdx.x == 0) g_is64 = (nz == 0) ? 1 : 0;
}

// ----------------- edge expansion (+ self loops) -------------------
__global__ void k_convert(const int* __restrict__ ei, int E, int n) {
    int tot = E + n;
    int stride = gridDim.x * blockDim.x;
    int is64 = g_is64;
    for (int idx = blockIdx.x * blockDim.x + threadIdx.x; idx < tot; idx += stride) {
        int s, d;
        if (idx < E) {
            if (is64) { s = ei[2 * idx]; d = ei[2 * E + 2 * idx]; }
            else      { s = ei[idx];     d = ei[E + idx]; }
        } else {
            s = d = idx - E;
        }
        g_src[idx] = s;
        g_dst[idx] = d;
    }
}

__global__ void k_zero(int n) {
    int stride = gridDim.x * blockDim.x;
    for (int i = blockIdx.x * blockDim.x + threadIdx.x; i < n; i += stride) {
        g_cnt[i] = 0; g_cnt2[i] = 0;
    }
}

__global__ void k_hist(int tot) {
    int stride = gridDim.x * blockDim.x;
    for (int i = blockIdx.x * blockDim.x + threadIdx.x; i < tot; i += stride)
        atomicAdd(&g_cnt[g_dst[i]], 1);
}

// ------------------------ hierarchical scan ------------------------
__global__ void k_scan1(int n) {
    __shared__ int sh[SCAN_T];
    int t = threadIdx.x;
    int i = blockIdx.x * SCAN_T + t;
    int v = (i < n) ? g_cnt[i] : 0;
    sh[t] = v;
    __syncthreads();
    for (int o = 1; o < SCAN_T; o <<= 1) {
        int x = (t >= o) ? sh[t - o] : 0;
        __syncthreads();
        sh[t] += x;
        __syncthreads();
    }
    if (i < n) g_rp[i] = sh[t] - v;
    if (t == SCAN_T - 1) g_part[blockIdx.x] = sh[t];
}

__global__ void k_scan2(int nb) {
    __shared__ int sh[256];
    int t = threadIdx.x;
    int v = (t < nb) ? g_part[t] : 0;
    sh[t] = v;
    __syncthreads();
    for (int o = 1; o < 256; o <<= 1) {
        int x = (t >= o) ? sh[t - o] : 0;
        __syncthreads();
        sh[t] += x;
        __syncthreads();
    }
    if (t < nb) g_part[t] = sh[t] - v;
}

__global__ void k_scan3(int n, int etot) {
    int i = blockIdx.x * SCAN_T + threadIdx.x;
    if (i < n) g_rp[i] += g_part[blockIdx.x];
    if (i == 0) g_rp[n] = etot;
}

__global__ void k_slot(int tot) {
    int stride = gridDim.x * blockDim.x;
    for (int i = blockIdx.x * blockDim.x + threadIdx.x; i < tot; i += stride) {
        int d = g_dst[i];
        int slot = g_rp[d] + atomicAdd(&g_cnt2[d], 1);
        g_csrc[slot] = g_src[i];
    }
}

// ---------------- fused layer-1 bias: bias2 = b1 + bias @ W1 --------------
__global__ void k_bias2(const float* __restrict__ bias,
                        const float* __restrict__ W1,
                        const float* __restrict__ b1, int K, int N) {
    int n = blockIdx.x * (blockDim.x >> 5) + (threadIdx.x >> 5);
    int lane = threadIdx.x & 31;
    if (n >= N) return;
    float s = 0.f;
    for (int k = lane; k < K; k += 32) s += bias[k] * W1[(size_t)k * N + n];
#pragma unroll
    for (int o = 16; o; o >>= 1) s += __shfl_xor_sync(0xFFFFFFFFu, s, o);
    if (lane == 0) g_bias2[n] = s + b1[n];
}

// ---------- weight split: src[K][N] fp32 -> transposed bf16 hi/lo [N][K] --
__global__ void k_splitB(const float* __restrict__ src,
                         __nv_bfloat16* __restrict__ dh,
                         __nv_bfloat16* __restrict__ dl, int K, int N) {
    int i = blockIdx.x * blockDim.x + threadIdx.x;
    if (i >= K * N) return;
    int k = i / N, n = i - k * N;
    float v = src[i];
    __nv_bfloat16 h = __float2bfloat16(v);
    float hf = __bfloat162float(h);
    __nv_bfloat16 l = __float2bfloat16(v - hf);
    dh[(size_t)n * K + k] = h;
    dl[(size_t)n * K + k] = l;
}

// --------------------------- mma helpers ---------------------------
__device__ __forceinline__ void mma_bf16(float c[4],
                                         unsigned a0, unsigned a1, unsigned a2, unsigned a3,
                                         unsigned b0, unsigned b1) {
    asm volatile(
        "mma.sync.aligned.m16n8k16.row.col.f32.bf16.bf16.f32 "
        "{%0,%1,%2,%3}, {%4,%5,%6,%7}, {%8,%9}, {%0,%1,%2,%3};"
        : "+f"(c[0]), "+f"(c[1]), "+f"(c[2]), "+f"(c[3])
        : "r"(a0), "r"(a1), "r"(a2), "r"(a3), "r"(b0), "r"(b1));
}

// split two fp32 (v0 = k even -> lo half, v1 = k odd -> hi half) into
// packed bf16x2 hi-word and lo-word
__device__ __forceinline__ void split2(float v0, float v1,
                                       unsigned& hi, unsigned& lo) {
    unsigned h;
    asm("cvt.rn.bf16x2.f32 %0, %1, %2;" : "=r"(h) : "f"(v1), "f"(v0));
    float f0 = __uint_as_float(h << 16);
    float f1 = __uint_as_float(h & 0xFFFF0000u);
    float l0 = v0 - f0, l1 = v1 - f1;
    unsigned l;
    asm("cvt.rn.bf16x2.f32 %0, %1, %2;" : "=r"(l) : "f"(l1), "f"(l0));
    hi = h; lo = l;
}

__device__ __forceinline__ void cp_async16(uint32_t dst, const void* src, bool pred) {
    int sz = pred ? 16 : 0;
    asm volatile("cp.async.cg.shared.global [%0], [%1], 16, %2;"
                 :: "r"(dst), "l"(src), "r"(sz));
}
__device__ __forceinline__ void cp_commit() {
    asm volatile("cp.async.commit_group;");
}
template<int NW>
__device__ __forceinline__ void cp_wait() {
    asm volatile("cp.async.wait_group %0;" :: "n"(NW));
}

// --------- tensor-core GEMM: bf16x2 (3-term), 128x128 CTA, BK=16 ----------
// 256 threads, 8 warps (4M x 2N), 32x64 warp tiles, 2 CTAs/SM.
// A: cp.async raw fp32 [k4][m][4]; hi/lo bf16 split in registers.
// B: pre-split transposed bf16 planes [N][K]; smem [n][8 words] with
//    chunk-granular XOR swizzle — pure LDS at fragment time, zero ALU.
template<bool RELU, bool CBIAS>
__global__ void __launch_bounds__(256, 2) k_mma(
    const float* __restrict__ A,
    const __nv_bfloat16* __restrict__ Bth,
    const __nv_bfloat16* __restrict__ Btl,
    float* __restrict__ C, const float* __restrict__ cbias,
    int M, int N, int K)
{
    extern __shared__ float sm[];
    const uint32_t smem_base = (uint32_t)__cvta_generic_to_shared(sm);

    const int tid  = threadIdx.x;
    const int wid  = tid >> 5;
    const int lane = tid & 31;
    const int gid  = lane >> 2;
    const int tig  = lane & 3;
    const int warpM = (wid & 3) * 32;
    const int warpN = (wid >> 2) * 64;
    const int rowBase = blockIdx.y * 128;
    const int colBase = blockIdx.x * 128;

    float acc[2][8][4];
#pragma unroll
    for (int mf = 0; mf < 2; mf++)
#pragma unroll
        for (int nf = 0; nf < 8; nf++)
#pragma unroll
            for (int r = 0; r < 4; r++) acc[mf][nf][r] = 0.f;

    auto cp_slab = [&](int k0, int stage) {
        uint32_t raA = smem_base + (stage * STAGE_F) * 4;
        uint32_t raB = raA + 2048 * 4;
        // A: 512 chunks = 4 k-chunks x 128 rows (fp32)
#pragma unroll
        for (int it = 0; it < 2; it++) {
            int idx = it * 256 + tid;
            int row = idx & 127;
            int k4  = idx >> 7;
            int gr = rowBase + row;
            bool p = gr < M;
            cp_async16(raA + (k4 * 512 + row * 4) * 4,
                       A + (size_t)(p ? gr : 0) * K + k0 + k4 * 4, p);
        }
        // B: 512 chunks = 2 planes x 128 n x 2 k-chunks (bf16, 8 elems/chunk)
#pragma unroll
        for (int it = 0; it < 2; it++) {
            int idx = it * 256 + tid;
            int plane = idx >> 8;
            int rem = idx & 255;
            int n = rem >> 1, c = rem & 1;
            const __nv_bfloat16* srcP = plane ? Btl : Bth;
            uint32_t dst = raB + plane * 1024 * 4 +
                           (n * 8 + (c ^ ((n >> 2) & 1)) * 4) * 4;
            cp_async16(dst, srcP + (size_t)(colBase + n) * K + k0 + c * 8, true);
        }
    };

    const int S = K >> 4;

    cp_slab(0, 0);  cp_commit();
    cp_slab(16, 1); cp_commit();
    cp_wait<1>();
    __syncthreads();

    const int s4 = 4 * (gid >> 2);
    const int w0 = tig ^ s4;
    const int w1 = (tig + 4) ^ s4;

    for (int s = 0; s < S; s++) {
        const int stage = s & 1;
        const float* rawA = sm + stage * STAGE_F;
        const unsigned* Bh = reinterpret_cast<const unsigned*>(rawA + 2048);
        const unsigned* Bl = Bh + 1024;

        // ---- A fragments: raw fp32 -> packed bf16x2 hi/lo in registers
        const float* Ap = rawA + ((tig * 2) >> 2) * 512 + (tig * 2 & 2);
        unsigned ah[2][4], al[2][4];
#pragma unroll
        for (int mf = 0; mf < 2; mf++) {
            int m0 = (warpM + mf * 16 + gid) * 4;
            float2 v00 = *(const float2*)(Ap + m0);          // row m0,  k 2t..
            float2 v01 = *(const float2*)(Ap + m0 + 32);     // row m0+8
            float2 v10 = *(const float2*)(Ap + 1024 + m0);   // row m0,  k 2t+8..
            float2 v11 = *(const float2*)(Ap + 1024 + m0 + 32);
            split2(v00.x, v00.y, ah[mf][0], al[mf][0]);
            split2(v01.x, v01.y, ah[mf][1], al[mf][1]);
            split2(v10.x, v10.y, ah[mf][2], al[mf][2]);
            split2(v11.x, v11.y, ah[mf][3], al[mf][3]);
        }

        // ---- B fragments: pure LDS of pre-split planes
#pragma unroll
        for (int nf = 0; nf < 8; nf++) {
            int base = (warpN + nf * 8 + gid) * 8;
            unsigned bh0 = Bh[base + w0];
            unsigned bh1 = Bh[base + w1];
            unsigned bl0 = Bl[base + w0];
            unsigned bl1 = Bl[base + w1];
#pragma unroll
            for (int mf = 0; mf < 2; mf++) {
                mma_bf16(acc[mf][nf], al[mf][0], al[mf][1], al[mf][2], al[mf][3], bh0, bh1);
                mma_bf16(acc[mf][nf], ah[mf][0], ah[mf][1], ah[mf][2], ah[mf][3], bl0, bl1);
                mma_bf16(acc[mf][nf], ah[mf][0], ah[mf][1], ah[mf][2], ah[mf][3], bh0, bh1);
            }
        }

        __syncthreads();
        if (s + 2 < S) {
            cp_slab((s + 2) * 16, stage);
            cp_commit();
            cp_wait<1>();
        } else {
            cp_wait<0>();
        }
        __syncthreads();
    }

    // ---- epilogue
#pragma unroll
    for (int mf = 0; mf < 2; mf++) {
        int r0 = rowBase + warpM + mf * 16 + gid;
        int r1 = r0 + 8;
#pragma unroll
        for (int nf = 0; nf < 8; nf++) {
            int gc = colBase + warpN + nf * 8 + tig * 2;
            float v0 = acc[mf][nf][0], v1 = acc[mf][nf][1];
            float v2 = acc[mf][nf][2], v3 = acc[mf][nf][3];
            if (CBIAS) {
                float2 bb = *(const float2*)(cbias + gc);
                v0 += bb.x; v1 += bb.y; v2 += bb.x; v3 += bb.y;
            }
            if (RELU) {
                v0 = fmaxf(v0, 0.f); v1 = fmaxf(v1, 0.f);
                v2 = fmaxf(v2, 0.f); v3 = fmaxf(v3, 0.f);
            }
            if (r0 < M) { float2 o = {v0, v1}; *(float2*)(C + (size_t)r0 * N + gc) = o; }
            if (r1 < M) { float2 o = {v2, v3}; *(float2*)(C + (size_t)r1 * N + gc) = o; }
        }
    }
}

// ----------------------- per-node attention dots --------------------------
__global__ void k_att(const float* __restrict__ att_src,
                      const float* __restrict__ att_dst, int n) {
    int w = (blockIdx.x * blockDim.x + threadIdx.x) >> 5;
    int lane = threadIdx.x & 31;
    if (w >= n) return;
    float4 hv = ((const float4*)(g_h + (size_t)w * FDIM))[lane];
    float4 as = ((const float4*)att_src)[lane];
    float4 ad = ((const float4*)att_dst)[lane];
    float s = hv.x * as.x + hv.y * as.y + hv.z * as.z + hv.w * as.w;
    float d = hv.x * ad.x + hv.y * ad.y + hv.z * ad.z + hv.w * ad.w;
#pragma unroll
    for (int o = 16; o; o >>= 1) {
        s += __shfl_xor_sync(0xFFFFFFFFu, s, o);
        d += __shfl_xor_sync(0xFFFFFFFFu, d, o);
    }
    if (lane == 0) { g_asrc[w] = s; g_adst[w] = d; }
}

// --------- fused per-node softmax + aggregation (warp per dst) ------------
__global__ void k_gather(int n) {
    int w = (blockIdx.x * blockDim.x + threadIdx.x) >> 5;
    int lane = threadIdx.x & 31;
    if (w >= n) return;

    int base = g_rp[w];
    int deg  = g_rp[w + 1] - base;
    float adst = g_adst[w];

    float m_l = -3.4e38f, z_l = 0.f;
    for (int j = lane; j < deg; j += 32) {
        int s = g_csrc[base + j];
        float e = g_asrc[s] + adst;
        e = (e > 0.f) ? e : NEG_SLOPE * e;
        float mn = fmaxf(m_l, e);
        z_l = z_l * __expf(m_l - mn) + __expf(e - mn);
        m_l = mn;
    }
#pragma unroll
    for (int o = 16; o; o >>= 1) {
        float mo = __shfl_xor_sync(0xFFFFFFFFu, m_l, o);
        float zo = __shfl_xor_sync(0xFFFFFFFFu, z_l, o);
        float mn = fmaxf(m_l, mo);
        z_l = z_l * __expf(m_l - mn) + zo * __expf(mo - mn);
        m_l = mn;
    }
    float m = m_l;
    float inv_z = 1.f / z_l;

    float4 acc = make_float4(0.f, 0.f, 0.f, 0.f);
    for (int j0 = 0; j0 < deg; j0 += 32) {
        int j = j0 + lane;
        int s = 0; float wgt = 0.f;
        if (j < deg) {
            s = g_csrc[base + j];
            float e = g_asrc[s] + adst;
            e = (e > 0.f) ? e : NEG_SLOPE * e;
            wgt = __expf(e - m);
        }
        int cnt = deg - j0; if (cnt > 32) cnt = 32;
        for (int jj = 0; jj < cnt; jj++) {
            int   ss = __shfl_sync(0xFFFFFFFFu, s,   jj);
            float ww = __shfl_sync(0xFFFFFFFFu, wgt, jj);
            float4 v = ((const float4*)(g_h + (size_t)ss * FDIM))[lane];
            acc.x += ww * v.x; acc.y += ww * v.y;
            acc.z += ww * v.z; acc.w += ww * v.w;
        }
    }
    acc.x *= inv_z; acc.y *= inv_z; acc.z *= inv_z; acc.w *= inv_z;
    ((float4*)(g_gat + (size_t)w * FDIM))[lane] = acc;
}

// ----------------------- final 256->1 + sigmoid ---------------------------
__global__ void k_final(const float* __restrict__ W3,
                        const float* __restrict__ b3,
                        float* __restrict__ out, int n) {
    int w = (blockIdx.x * blockDim.x + threadIdx.x) >> 5;
    int lane = threadIdx.x & 31;
    if (w >= n) return;
    const float4* hp = (const float4*)(g_h2 + (size_t)w * HDIM);
    const float4* wp = (const float4*)W3;
    float acc = 0.f;
#pragma unroll
    for (int j = 0; j < 2; j++) {
        float4 h = hp[lane + 32 * j];
        float4 ww = wp[lane + 32 * j];
        acc += h.x * ww.x + h.y * ww.y + h.z * ww.z + h.w * ww.w;
    }
#pragma unroll
    for (int o = 16; o; o >>= 1) acc += __shfl_xor_sync(0xFFFFFFFFu, acc, o);
    if (lane == 0) out[w] = 1.f / (1.f + expf(-(acc + b3[0])));
}

// --------------------------- host launcher --------------------------------
extern "C" void kernel_launch(void* const* d_in, const int* in_sizes, int n_in,
                              void* d_out, int out_size) {
    const float* x       = (const float*)d_in[0];
    const int*   ei      = (const int*)d_in[1];
    const float* W       = (const float*)d_in[2];
    const float* att_src = (const float*)d_in[3];
    const float* att_dst = (const float*)d_in[4];
    const float* bias    = (const float*)d_in[5];
    const float* W1      = (const float*)d_in[6];
    const float* b1      = (const float*)d_in[7];
    const float* W2      = (const float*)d_in[8];
    const float* b2      = (const float*)d_in[9];
    const float* W3      = (const float*)d_in[10];
    const float* b3      = (const float*)d_in[11];
    float* out = (float*)d_out;

    int n = in_sizes[0] / FDIM;
    int E = in_sizes[1] / 2;
    int Etot = E + n;
    int scanBlocks = (n + SCAN_T - 1) / SCAN_T;

    void *p_h, *p_gat, *p_h1, *p_h2, *p_b2;
    void *p_wth, *p_wtl, *p_w1th, *p_w1tl, *p_w2th, *p_w2tl;
    cudaGetSymbolAddress(&p_h,    g_h);
    cudaGetSymbolAddress(&p_gat,  g_gat);
    cudaGetSymbolAddress(&p_h1,   g_h1);
    cudaGetSymbolAddress(&p_h2,   g_h2);
    cudaGetSymbolAddress(&p_b2,   g_bias2);
    cudaGetSymbolAddress(&p_wth,  g_wth);
    cudaGetSymbolAddress(&p_wtl,  g_wtl);
    cudaGetSymbolAddress(&p_w1th, g_w1th);
    cudaGetSymbolAddress(&p_w1tl, g_w1tl);
    cudaGetSymbolAddress(&p_w2th, g_w2th);
    cudaGetSymbolAddress(&p_w2tl, g_w2tl);

    int mBlocks = (n + 127) / 128;

    cudaFuncSetAttribute(k_mma<false, false>,
                         cudaFuncAttributeMaxDynamicSharedMemorySize, SMEM_BYTES);
    cudaFuncSetAttribute(k_mma<true, true>,
                         cudaFuncAttributeMaxDynamicSharedMemorySize, SMEM_BYTES);

    // weight splits (tiny) + CSR build
    k_splitB<<<(FDIM * FDIM + 255) / 256, 256>>>(
        W, (__nv_bfloat16*)p_wth, (__nv_bfloat16*)p_wtl, FDIM, FDIM);
    k_detect<<<1, 256>>>(ei, E);
    k_convert<<<2048, 256>>>(ei, E, n);
    k_zero<<<512, 256>>>(n);

    // h = x @ W
    k_mma<false, false><<<dim3(1, mBlocks), 256, SMEM_BYTES>>>(
        x, (const __nv_bfloat16*)p_wth, (const __nv_bfloat16*)p_wtl,
        (float*)p_h, nullptr, n, FDIM, FDIM);

    k_splitB<<<(FDIM * HDIM + 255) / 256, 256>>>(
        W1, (__nv_bfloat16*)p_w1th, (__nv_bfloat16*)p_w1tl, FDIM, HDIM);
    k_splitB<<<(HDIM * HDIM + 255) / 256, 256>>>(
        W2, (__nv_bfloat16*)p_w2th, (__nv_bfloat16*)p_w2tl, HDIM, HDIM);
    k_bias2<<<(HDIM + 7) / 8, 256>>>(bias, W1, b1, FDIM, HDIM);
    k_hist<<<2048, 256>>>(Etot);
    k_scan1<<<scanBlocks, SCAN_T>>>(n);
    k_scan2<<<1, 256>>>(scanBlocks);
    k_scan3<<<scanBlocks, SCAN_T>>>(n, Etot);
    k_slot<<<2048, 256>>>(Etot);

    k_att<<<(n + 7) / 8, 256>>>(att_src, att_dst, n);
    k_gather<<<(n + 7) / 8, 256>>>(n);

    // h1 = relu(gat @ W1 + bias2)   (bias folded: (gat+b)@W1 = gat@W1 + b@W1)
    k_mma<true, true><<<dim3(2, mBlocks), 256, SMEM_BYTES>>>(
        (const float*)p_gat, (const __nv_bfloat16*)p_w1th, (const __nv_bfloat16*)p_w1tl,
        (float*)p_h1, (const float*)p_b2, n, HDIM, FDIM);
    // h2 = relu(h1 @ W2 + b2)
    k_mma<true, true><<<dim3(2, mBlocks), 256, SMEM_BYTES>>>(
        (const float*)p_h1, (const __nv_bfloat16*)p_w2th, (const __nv_bfloat16*)p_w2tl,
        (float*)p_h2, b2, n, HDIM, HDIM);
    k_final<<<(n + 7) / 8, 256>>>(W3, b3, out, n);
}

// round 12
// speedup vs baseline: 1.7700x; 1.1272x over previous
#include <cuda_runtime.h>
#include <cuda_bf16.h>
#include <stdint.h>

#define NN      100000
#define FDIM    128
#define HDIM    256
#define EMAX    1800000
#define NEG_SLOPE 0.2f
#define SCAN_T  512

// smem per stage (4B words): A region 2048 (raw fp32 OR 2 packed planes),
// B region 2048 (2 bf16 planes). 3 stages.
#define STAGE_F 4096
#define SMEM_BYTES (3 * STAGE_F * 4)

// -------- scratch (static device arrays; no runtime malloc) ----------
__device__ float    g_h   [(size_t)NN * FDIM];
__device__ float    g_asrc[NN];
__device__ float    g_adst[NN];
__device__ float    g_h2  [(size_t)NN * HDIM];
__device__ float    g_bias2[HDIM];             // b1 + bias @ W1
__device__ unsigned g_gath[(size_t)NN * (FDIM / 2)];   // gat packed bf16x2 hi
__device__ unsigned g_gatl[(size_t)NN * (FDIM / 2)];   //                 lo
__device__ unsigned g_h1h [(size_t)NN * (HDIM / 2)];   // h1 packed hi
__device__ unsigned g_h1l [(size_t)NN * (HDIM / 2)];   //           lo
__device__ int      g_src [EMAX];
__device__ int      g_dst [EMAX];
__device__ int      g_csrc[EMAX];
__device__ int      g_cnt [NN];
__device__ int      g_cnt2[NN];
__device__ int      g_rp  [NN + 1];
__device__ int      g_part[256];
__device__ int      g_is64;
// weight hi/lo bf16 planes, TRANSPOSED to [N][K]
__device__ __nv_bfloat16 g_wth [FDIM * FDIM];
__device__ __nv_bfloat16 g_wtl [FDIM * FDIM];
__device__ __nv_bfloat16 g_w1th[HDIM * FDIM];
__device__ __nv_bfloat16 g_w1tl[HDIM * FDIM];
__device__ __nv_bfloat16 g_w2th[HDIM * HDIM];
__device__ __nv_bfloat16 g_w2tl[HDIM * HDIM];

// --------------------------- helpers ---------------------------
// split two fp32 (v0 -> lo half, v1 -> hi half) into bf16x2 hi-word + lo-word
__device__ __forceinline__ void split2(float v0, float v1,
                                       unsigned& hi, unsigned& lo) {
    unsigned h;
    asm("cvt.rn.bf16x2.f32 %0, %1, %2;" : "=r"(h) : "f"(v1), "f"(v0));
    float f0 = __uint_as_float(h << 16);
    float f1 = __uint_as_float(h & 0xFFFF0000u);
    float l0 = v0 - f0, l1 = v1 - f1;
    unsigned l;
    asm("cvt.rn.bf16x2.f32 %0, %1, %2;" : "=r"(l) : "f"(l1), "f"(l0));
    hi = h; lo = l;
}

__device__ __forceinline__ void mma_bf16(float c[4],
                                         unsigned a0, unsigned a1, unsigned a2, unsigned a3,
                                         unsigned b0, unsigned b1) {
    asm volatile(
        "mma.sync.aligned.m16n8k16.row.col.f32.bf16.bf16.f32 "
        "{%0,%1,%2,%3}, {%4,%5,%6,%7}, {%8,%9}, {%0,%1,%2,%3};"
        : "+f"(c[0]), "+f"(c[1]), "+f"(c[2]), "+f"(c[3])
        : "r"(a0), "r"(a1), "r"(a2), "r"(a3), "r"(b0), "r"(b1));
}

__device__ __forceinline__ void cp_async16(uint32_t dst, const void* src, bool pred) {
    int sz = pred ? 16 : 0;
    asm volatile("cp.async.cg.shared.global [%0], [%1], 16, %2;"
                 :: "r"(dst), "l"(src), "r"(sz));
}
__device__ __forceinline__ void cp_commit() {
    asm volatile("cp.async.commit_group;");
}
template<int NW>
__device__ __forceinline__ void cp_wait() {
    asm volatile("cp.async.wait_group %0;" :: "n"(NW));
}

// --------------------------- dtype probe ---------------------------
__global__ void k_detect(const int* __restrict__ ei, int E) {
    __shared__ int nz;
    if (threadIdx.x == 0) nz = 0;
    __syncthreads();
    int samples = 4096;
    if (samples > E) samples = E;
    for (int i = threadIdx.x; i < samples; i += blockDim.x)
        if (ei[2 * i + 1] != 0) atomicOr(&nz, 1);
    __syncthreads();
    if (threadIdx.x == 0) g_is64 = (nz == 0) ? 1 : 0;
}

__global__ void k_zero(int n) {
    int stride = gridDim.x * blockDim.x;
    for (int i = blockIdx.x * blockDim.x + threadIdx.x; i < n; i += stride) {
        g_cnt[i] = 0; g_cnt2[i] = 0;
    }
}

// ----------- edge expansion (+ self loops) + fused histogram --------------
__global__ void k_convert(const int* __restrict__ ei, int E, int n) {
    int tot = E + n;
    int stride = gridDim.x * blockDim.x;
    int is64 = g_is64;
    for (int idx = blockIdx.x * blockDim.x + threadIdx.x; idx < tot; idx += stride) {
        int s, d;
        if (idx < E) {
            if (is64) { s = ei[2 * idx]; d = ei[2 * E + 2 * idx]; }
            else      { s = ei[idx];     d = ei[E + idx]; }
        } else {
            s = d = idx - E;
        }
        g_src[idx] = s;
        g_dst[idx] = d;
        atomicAdd(&g_cnt[d], 1);
    }
}

// ------------------------ hierarchical scan ------------------------
__global__ void k_scan1(int n) {
    __shared__ int sh[SCAN_T];
    int t = threadIdx.x;
    int i = blockIdx.x * SCAN_T + t;
    int v = (i < n) ? g_cnt[i] : 0;
    sh[t] = v;
    __syncthreads();
    for (int o = 1; o < SCAN_T; o <<= 1) {
        int x = (t >= o) ? sh[t - o] : 0;
        __syncthreads();
        sh[t] += x;
        __syncthreads();
    }
    if (i < n) g_rp[i] = sh[t] - v;
    if (t == SCAN_T - 1) g_part[blockIdx.x] = sh[t];
}

__global__ void k_scan2(int nb) {
    __shared__ int sh[256];
    int t = threadIdx.x;
    int v = (t < nb) ? g_part[t] : 0;
    sh[t] = v;
    __syncthreads();
    for (int o = 1; o < 256; o <<= 1) {
        int x = (t >= o) ? sh[t - o] : 0;
        __syncthreads();
        sh[t] += x;
        __syncthreads();
    }
    if (t < nb) g_part[t] = sh[t] - v;
}

__global__ void k_scan3(int n, int etot) {
    int i = blockIdx.x * SCAN_T + threadIdx.x;
    if (i < n) g_rp[i] += g_part[blockIdx.x];
    if (i == 0) g_rp[n] = etot;
}

__global__ void k_slot(int tot) {
    int stride = gridDim.x * blockDim.x;
    for (int i = blockIdx.x * blockDim.x + threadIdx.x; i < tot; i += stride) {
        int d = g_dst[i];
        int slot = g_rp[d] + atomicAdd(&g_cnt2[d], 1);
        g_csrc[slot] = g_src[i];
    }
}

// ---------------- fused layer-1 bias: bias2 = b1 + bias @ W1 --------------
__global__ void k_bias2(const float* __restrict__ bias,
                        const float* __restrict__ W1,
                        const float* __restrict__ b1, int K, int N) {
    int n = blockIdx.x * (blockDim.x >> 5) + (threadIdx.x >> 5);
    int lane = threadIdx.x & 31;
    if (n >= N) return;
    float s = 0.f;
    for (int k = lane; k < K; k += 32) s += bias[k] * W1[(size_t)k * N + n];
#pragma unroll
    for (int o = 16; o; o >>= 1) s += __shfl_xor_sync(0xFFFFFFFFu, s, o);
    if (lane == 0) g_bias2[n] = s + b1[n];
}

// ---------- weight split: src[K][N] fp32 -> transposed bf16 hi/lo [N][K] --
__global__ void k_splitB(const float* __restrict__ src,
                         __nv_bfloat16* __restrict__ dh,
                         __nv_bfloat16* __restrict__ dl, int K, int N) {
    int i = blockIdx.x * blockDim.x + threadIdx.x;
    if (i >= K * N) return;
    int k = i / N, n = i - k * N;
    float v = src[i];
    __nv_bfloat16 h = __float2bfloat16(v);
    float hf = __bfloat162float(h);
    __nv_bfloat16 l = __float2bfloat16(v - hf);
    dh[(size_t)n * K + k] = h;
    dl[(size_t)n * K + k] = l;
}

// --------- tensor-core GEMM: bf16x2 (3-term), 128x128 CTA, BK=16 ----------
// 256 threads, 8 warps (4M x 2N), 32x64 warp tiles, 2 CTAs/SM, 3 stages,
// single __syncthreads per slab.
// A: either raw fp32 (register split) or pre-packed bf16x2 hi/lo planes.
// B: pre-split transposed bf16 planes — pure LDS.
// C: fp32, or packed hi/lo planes for the next GEMM's A.
template<bool A_PACKED, bool C_PACKED, bool RELU, bool CBIAS>
__global__ void __launch_bounds__(256, 2) k_mma(
    const float* __restrict__ A,
    const unsigned* __restrict__ Ahi, const unsigned* __restrict__ Alo,
    const __nv_bfloat16* __restrict__ Bth,
    const __nv_bfloat16* __restrict__ Btl,
    float* __restrict__ C,
    unsigned* __restrict__ Chi, unsigned* __restrict__ Clo,
    const float* __restrict__ cbias,
    int M, int N, int K)
{
    extern __shared__ float sm[];
    const uint32_t smem_base = (uint32_t)__cvta_generic_to_shared(sm);

    const int tid  = threadIdx.x;
    const int wid  = tid >> 5;
    const int lane = tid & 31;
    const int gid  = lane >> 2;
    const int tig  = lane & 3;
    const int warpM = (wid & 3) * 32;
    const int warpN = (wid >> 2) * 64;
    const int rowBase = blockIdx.y * 128;
    const int colBase = blockIdx.x * 128;

    float acc[2][8][4];
#pragma unroll
    for (int mf = 0; mf < 2; mf++)
#pragma unroll
        for (int nf = 0; nf < 8; nf++)
#pragma unroll
            for (int r = 0; r < 4; r++) acc[mf][nf][r] = 0.f;

    auto cp_slab = [&](int k0, int stage) {
        uint32_t raA = smem_base + (stage * STAGE_F) * 4;
        uint32_t raB = raA + 2048 * 4;
        if (A_PACKED) {
            // A: 2 planes x 128 rows x 2 chunks (uint32 words, 8/row)
#pragma unroll
            for (int it = 0; it < 2; it++) {
                int idx = it * 256 + tid;
                int plane = idx >> 8;
                int rem = idx & 255;
                int m = rem >> 1, c = rem & 1;
                int gr = rowBase + m;
                bool p = gr < M;
                const unsigned* srcP = plane ? Alo : Ahi;
                uint32_t dst = raA + plane * 1024 * 4 +
                               (m * 8 + (c ^ ((m >> 2) & 1)) * 4) * 4;
                cp_async16(dst, srcP + (size_t)(p ? gr : 0) * (K >> 1) + (k0 >> 1) + c * 4, p);
            }
        } else {
            // A: raw fp32, 4 k-chunks x 128 rows
#pragma unroll
            for (int it = 0; it < 2; it++) {
                int idx = it * 256 + tid;
                int row = idx & 127;
                int k4  = idx >> 7;
                int gr = rowBase + row;
                bool p = gr < M;
                cp_async16(raA + (k4 * 512 + row * 4) * 4,
                           A + (size_t)(p ? gr : 0) * K + k0 + k4 * 4, p);
            }
        }
        // B: 2 planes x 128 n x 2 chunks (bf16, 8 elems/chunk)
#pragma unroll
        for (int it = 0; it < 2; it++) {
            int idx = it * 256 + tid;
            int plane = idx >> 8;
            int rem = idx & 255;
            int n = rem >> 1, c = rem & 1;
            const __nv_bfloat16* srcP = plane ? Btl : Bth;
            uint32_t dst = raB + plane * 1024 * 4 +
                           (n * 8 + (c ^ ((n >> 2) & 1)) * 4) * 4;
            cp_async16(dst, srcP + (size_t)(colBase + n) * K + k0 + c * 8, true);
        }
    };

    const int S = K >> 4;

    cp_slab(0, 0);  cp_commit();
    cp_slab(16, 1); cp_commit();

    const int s4 = 4 * (gid >> 2);
    const int w0 = tig ^ s4;
    const int w1 = (tig + 4) ^ s4;

    for (int s = 0; s < S; s++) {
        if (s + 1 < S) cp_wait<1>(); else cp_wait<0>();
        __syncthreads();
        if (s + 2 < S) { cp_slab((s + 2) * 16, (s + 2) % 3); cp_commit(); }

        const int stage = s % 3;
        const float* rawA = sm + stage * STAGE_F;

        // ---- A fragments
        unsigned ah[2][4], al[2][4];
        if (A_PACKED) {
            const unsigned* AhS = reinterpret_cast<const unsigned*>(rawA);
            const unsigned* AlS = AhS + 1024;
#pragma unroll
            for (int mf = 0; mf < 2; mf++) {
                int b0 = (warpM + mf * 16 + gid) * 8;
                int b1 = b0 + 64;                    // +8 rows
                ah[mf][0] = AhS[b0 + w0]; ah[mf][1] = AhS[b1 + w0];
                ah[mf][2] = AhS[b0 + w1]; ah[mf][3] = AhS[b1 + w1];
                al[mf][0] = AlS[b0 + w0]; al[mf][1] = AlS[b1 + w0];
                al[mf][2] = AlS[b0 + w1]; al[mf][3] = AlS[b1 + w1];
            }
        } else {
            const float* Ap = rawA + ((tig * 2) >> 2) * 512 + (tig * 2 & 2);
#pragma unroll
            for (int mf = 0; mf < 2; mf++) {
                int m0 = (warpM + mf * 16 + gid) * 4;
                float2 v00 = *(const float2*)(Ap + m0);
                float2 v01 = *(const float2*)(Ap + m0 + 32);
                float2 v10 = *(const float2*)(Ap + 1024 + m0);
                float2 v11 = *(const float2*)(Ap + 1024 + m0 + 32);
                split2(v00.x, v00.y, ah[mf][0], al[mf][0]);
                split2(v01.x, v01.y, ah[mf][1], al[mf][1]);
                split2(v10.x, v10.y, ah[mf][2], al[mf][2]);
                split2(v11.x, v11.y, ah[mf][3], al[mf][3]);
            }
        }

        // ---- B fragments + MMAs
        const unsigned* Bh = reinterpret_cast<const unsigned*>(rawA + 2048);
        const unsigned* Bl = Bh + 1024;
#pragma unroll
        for (int nf = 0; nf < 8; nf++) {
            int base = (warpN + nf * 8 + gid) * 8;
            unsigned bh0 = Bh[base + w0];
            unsigned bh1 = Bh[base + w1];
            unsigned bl0 = Bl[base + w0];
            unsigned bl1 = Bl[base + w1];
#pragma unroll
            for (int mf = 0; mf < 2; mf++) {
                mma_bf16(acc[mf][nf], al[mf][0], al[mf][1], al[mf][2], al[mf][3], bh0, bh1);
                mma_bf16(acc[mf][nf], ah[mf][0], ah[mf][1], ah[mf][2], ah[mf][3], bl0, bl1);
                mma_bf16(acc[mf][nf], ah[mf][0], ah[mf][1], ah[mf][2], ah[mf][3], bh0, bh1);
            }
        }
    }

    // ---- epilogue
#pragma unroll
    for (int mf = 0; mf < 2; mf++) {
        int r0 = rowBase + warpM + mf * 16 + gid;
        int r1 = r0 + 8;
#pragma unroll
        for (int nf = 0; nf < 8; nf++) {
            int gc = colBase + warpN + nf * 8 + tig * 2;
            float v0 = acc[mf][nf][0], v1 = acc[mf][nf][1];
            float v2 = acc[mf][nf][2], v3 = acc[mf][nf][3];
            if (CBIAS) {
                float2 bb = *(const float2*)(cbias + gc);
                v0 += bb.x; v1 += bb.y; v2 += bb.x; v3 += bb.y;
            }
            if (RELU) {
                v0 = fmaxf(v0, 0.f); v1 = fmaxf(v1, 0.f);
                v2 = fmaxf(v2, 0.f); v3 = fmaxf(v3, 0.f);
            }
            if (C_PACKED) {
                int wp = (gc >> 1);
                unsigned hi, lo;
                if (r0 < M) {
                    split2(v0, v1, hi, lo);
                    Chi[(size_t)r0 * (N >> 1) + wp] = hi;
                    Clo[(size_t)r0 * (N >> 1) + wp] = lo;
                }
                if (r1 < M) {
                    split2(v2, v3, hi, lo);
                    Chi[(size_t)r1 * (N >> 1) + wp] = hi;
                    Clo[(size_t)r1 * (N >> 1) + wp] = lo;
                }
            } else {
                if (r0 < M) { float2 o = {v0, v1}; *(float2*)(C + (size_t)r0 * N + gc) = o; }
                if (r1 < M) { float2 o = {v2, v3}; *(float2*)(C + (size_t)r1 * N + gc) = o; }
            }
        }
    }
}

// ----------------------- per-node attention dots --------------------------
__global__ void k_att(const float* __restrict__ att_src,
                      const float* __restrict__ att_dst, int n) {
    int w = (blockIdx.x * blockDim.x + threadIdx.x) >> 5;
    int lane = threadIdx.x & 31;
    if (w >= n) return;
    float4 hv = ((const float4*)(g_h + (size_t)w * FDIM))[lane];
    float4 as = ((const float4*)att_src)[lane];
    float4 ad = ((const float4*)att_dst)[lane];
    float s = hv.x * as.x + hv.y * as.y + hv.z * as.z + hv.w * as.w;
    float d = hv.x * ad.x + hv.y * ad.y + hv.z * ad.z + hv.w * ad.w;
#pragma unroll
    for (int o = 16; o; o >>= 1) {
        s += __shfl_xor_sync(0xFFFFFFFFu, s, o);
        d += __shfl_xor_sync(0xFFFFFFFFu, d, o);
    }
    if (lane == 0) { g_asrc[w] = s; g_adst[w] = d; }
}

// --------- fused per-node softmax + aggregation (warp per dst) ------------
// output written as packed bf16x2 hi/lo planes (GEMM2's A operand)
__global__ void k_gather(int n) {
    int w = (blockIdx.x * blockDim.x + threadIdx.x) >> 5;
    int lane = threadIdx.x & 31;
    if (w >= n) return;

    int base = g_rp[w];
    int deg  = g_rp[w + 1] - base;
    float adst = g_adst[w];

    float m_l = -3.4e38f, z_l = 0.f;
    for (int j = lane; j < deg; j += 32) {
        int s = g_csrc[base + j];
        float e = g_asrc[s] + adst;
        e = (e > 0.f) ? e : NEG_SLOPE * e;
        float mn = fmaxf(m_l, e);
        z_l = z_l * __expf(m_l - mn) + __expf(e - mn);
        m_l = mn;
    }
#pragma unroll
    for (int o = 16; o; o >>= 1) {
        float mo = __shfl_xor_sync(0xFFFFFFFFu, m_l, o);
        float zo = __shfl_xor_sync(0xFFFFFFFFu, z_l, o);
        float mn = fmaxf(m_l, mo);
        z_l = z_l * __expf(m_l - mn) + zo * __expf(mo - mn);
        m_l = mn;
    }
    float m = m_l;
    float inv_z = 1.f / z_l;

    float4 acc = make_float4(0.f, 0.f, 0.f, 0.f);
    for (int j0 = 0; j0 < deg; j0 += 32) {
        int j = j0 + lane;
        int s = 0; float wgt = 0.f;
        if (j < deg) {
            s = g_csrc[base + j];
            float e = g_asrc[s] + adst;
            e = (e > 0.f) ? e : NEG_SLOPE * e;
            wgt = __expf(e - m);
        }
        int cnt = deg - j0; if (cnt > 32) cnt = 32;
        for (int jj = 0; jj < cnt; jj++) {
            int   ss = __shfl_sync(0xFFFFFFFFu, s,   jj);
            float ww = __shfl_sync(0xFFFFFFFFu, wgt, jj);
            float4 v = ((const float4*)(g_h + (size_t)ss * FDIM))[lane];
            acc.x += ww * v.x; acc.y += ww * v.y;
            acc.z += ww * v.z; acc.w += ww * v.w;
        }
    }
    acc.x *= inv_z; acc.y *= inv_z; acc.z *= inv_z; acc.w *= inv_z;

    unsigned hi0, lo0, hi1, lo1;
    split2(acc.x, acc.y, hi0, lo0);
    split2(acc.z, acc.w, hi1, lo1);
    size_t b2 = (size_t)w * (FDIM / 2) + 2 * lane;
    g_gath[b2]     = hi0; g_gath[b2 + 1] = hi1;
    g_gatl[b2]     = lo0; g_gatl[b2 + 1] = lo1;
}

// ----------------------- final 256->1 + sigmoid ---------------------------
__global__ void k_final(const float* __restrict__ W3,
                        const float* __restrict__ b3,
                        float* __restrict__ out, int n) {
    int w = (blockIdx.x * blockDim.x + threadIdx.x) >> 5;
    int lane = threadIdx.x & 31;
    if (w >= n) return;
    const float4* hp = (const float4*)(g_h2 + (size_t)w * HDIM);
    const float4* wp = (const float4*)W3;
    float acc = 0.f;
#pragma unroll
    for (int j = 0; j < 2; j++) {
        float4 h = hp[lane + 32 * j];
        float4 ww = wp[lane + 32 * j];
        acc += h.x * ww.x + h.y * ww.y + h.z * ww.z + h.w * ww.w;
    }
#pragma unroll
    for (int o = 16; o; o >>= 1) acc += __shfl_xor_sync(0xFFFFFFFFu, acc, o);
    if (lane == 0) out[w] = 1.f / (1.f + expf(-(acc + b3[0])));
}

// --------------------------- host launcher --------------------------------
extern "C" void kernel_launch(void* const* d_in, const int* in_sizes, int n_in,
                              void* d_out, int out_size) {
    const float* x       = (const float*)d_in[0];
    const int*   ei      = (const int*)d_in[1];
    const float* W       = (const float*)d_in[2];
    const float* att_src = (const float*)d_in[3];
    const float* att_dst = (const float*)d_in[4];
    const float* bias    = (const float*)d_in[5];
    const float* W1      = (const float*)d_in[6];
    const float* b1      = (const float*)d_in[7];
    const float* W2      = (const float*)d_in[8];
    const float* b2      = (const float*)d_in[9];
    const float* W3      = (const float*)d_in[10];
    const float* b3      = (const float*)d_in[11];
    float* out = (float*)d_out;

    int n = in_sizes[0] / FDIM;
    int E = in_sizes[1] / 2;
    int Etot = E + n;
    int scanBlocks = (n + SCAN_T - 1) / SCAN_T;

    void *p_h, *p_h2, *p_b2;
    void *p_gath, *p_gatl, *p_h1h, *p_h1l;
    void *p_wth, *p_wtl, *p_w1th, *p_w1tl, *p_w2th, *p_w2tl;
    cudaGetSymbolAddress(&p_h,    g_h);
    cudaGetSymbolAddress(&p_h2,   g_h2);
    cudaGetSymbolAddress(&p_b2,   g_bias2);
    cudaGetSymbolAddress(&p_gath, g_gath);
    cudaGetSymbolAddress(&p_gatl, g_gatl);
    cudaGetSymbolAddress(&p_h1h,  g_h1h);
    cudaGetSymbolAddress(&p_h1l,  g_h1l);
    cudaGetSymbolAddress(&p_wth,  g_wth);
    cudaGetSymbolAddress(&p_wtl,  g_wtl);
    cudaGetSymbolAddress(&p_w1th, g_w1th);
    cudaGetSymbolAddress(&p_w1tl, g_w1tl);
    cudaGetSymbolAddress(&p_w2th, g_w2th);
    cudaGetSymbolAddress(&p_w2tl, g_w2tl);

    int mBlocks = (n + 127) / 128;

    cudaFuncSetAttribute(k_mma<false, false, false, false>,
                         cudaFuncAttributeMaxDynamicSharedMemorySize, SMEM_BYTES);
    cudaFuncSetAttribute(k_mma<true, true, true, true>,
                         cudaFuncAttributeMaxDynamicSharedMemorySize, SMEM_BYTES);
    cudaFuncSetAttribute(k_mma<true, false, true, true>,
                         cudaFuncAttributeMaxDynamicSharedMemorySize, SMEM_BYTES);

    // weight splits (tiny) + CSR build (hist fused into convert)
    k_splitB<<<(FDIM * FDIM + 255) / 256, 256>>>(
        W, (__nv_bfloat16*)p_wth, (__nv_bfloat16*)p_wtl, FDIM, FDIM);
    k_detect<<<1, 256>>>(ei, E);
    k_zero<<<512, 256>>>(n);
    k_convert<<<2048, 256>>>(ei, E, n);

    // h = x @ W   (raw-A path)
    k_mma<false, false, false, false><<<dim3(1, mBlocks), 256, SMEM_BYTES>>>(
        x, nullptr, nullptr,
        (const __nv_bfloat16*)p_wth, (const __nv_bfloat16*)p_wtl,
        (float*)p_h, nullptr, nullptr, nullptr, n, FDIM, FDIM);

    k_splitB<<<(FDIM * HDIM + 255) / 256, 256>>>(
        W1, (__nv_bfloat16*)p_w1th, (__nv_bfloat16*)p_w1tl, FDIM, HDIM);
    k_splitB<<<(HDIM * HDIM + 255) / 256, 256>>>(
        W2, (__nv_bfloat16*)p_w2th, (__nv_bfloat16*)p_w2tl, HDIM, HDIM);
    k_bias2<<<(HDIM + 7) / 8, 256>>>(bias, W1, b1, FDIM, HDIM);
    k_scan1<<<scanBlocks, SCAN_T>>>(n);
    k_scan2<<<1, 256>>>(scanBlocks);
    k_scan3<<<scanBlocks, SCAN_T>>>(n, Etot);
    k_slot<<<2048, 256>>>(Etot);

    k_att<<<(n + 7) / 8, 256>>>(att_src, att_dst, n);
    k_gather<<<(n + 7) / 8, 256>>>(n);

    // h1 = relu(gat @ W1 + bias2)  — packed A in, packed C out
    k_mma<true, true, true, true><<<dim3(2, mBlocks), 256, SMEM_BYTES>>>(
        nullptr, (const unsigned*)p_gath, (const unsigned*)p_gatl,
        (const __nv_bfloat16*)p_w1th, (const __nv_bfloat16*)p_w1tl,
        nullptr, (unsigned*)p_h1h, (unsigned*)p_h1l,
        (const float*)p_b2, n, HDIM, FDIM);
    // h2 = relu(h1 @ W2 + b2)  — packed A in, fp32 out
    k_mma<true, false, true, true><<<dim3(2, mBlocks), 256, SMEM_BYTES>>>(
        nullptr, (const unsigned*)p_h1h, (const unsigned*)p_h1l,
        (const __nv_bfloat16*)p_w2th, (const __nv_bfloat16*)p_w2tl,
        (float*)p_h2, nullptr, nullptr, b2, n, HDIM, HDIM);
    k_final<<<(n + 7) / 8, 256>>>(W3, b3, out, n);
}

// round 14
// speedup vs baseline: 1.8562x; 1.0487x over previous
#include <cuda_runtime.h>
#include <cuda_bf16.h>
#include <stdint.h>

#define NN      100000
#define FDIM    128
#define HDIM    256
#define EMAX    1800000
#define NEG_SLOPE 0.2f
#define SCAN_T  512

// smem per stage (4B words): A region 2048, B region 2048. 3 stages.
#define STAGE_F 4096
#define SMEM_BYTES (3 * STAGE_F * 4)

// -------- scratch (static device arrays; no runtime malloc) ----------
__device__ float    g_h   [(size_t)NN * FDIM];
__device__ float    g_asrc[NN];
__device__ float    g_adst[NN];
__device__ float    g_dot [NN];                // fused final dot accumulator
__device__ float    g_bias2[HDIM];             // b1 + bias @ W1
__device__ unsigned g_gath[(size_t)NN * (FDIM / 2)];   // gat packed bf16x2 hi
__device__ unsigned g_gatl[(size_t)NN * (FDIM / 2)];   //                 lo
__device__ unsigned g_h1h [(size_t)NN * (HDIM / 2)];   // h1 packed hi
__device__ unsigned g_h1l [(size_t)NN * (HDIM / 2)];   //           lo
__device__ int      g_src [EMAX];
__device__ int      g_dst [EMAX];
__device__ int      g_csrc[EMAX];
__device__ int      g_cnt [NN];
__device__ int      g_cnt2[NN];
__device__ int      g_rp  [NN + 1];
__device__ int      g_part[256];
__device__ int      g_is64;
// weight hi/lo bf16 planes, TRANSPOSED to [N][K]
__device__ __nv_bfloat16 g_wth [FDIM * FDIM];
__device__ __nv_bfloat16 g_wtl [FDIM * FDIM];
__device__ __nv_bfloat16 g_w1th[HDIM * FDIM];
__device__ __nv_bfloat16 g_w1tl[HDIM * FDIM];
__device__ __nv_bfloat16 g_w2th[HDIM * HDIM];
__device__ __nv_bfloat16 g_w2tl[HDIM * HDIM];

// --------------------------- helpers ---------------------------
__device__ __forceinline__ void split2(float v0, float v1,
                                       unsigned& hi, unsigned& lo) {
    unsigned h;
    asm("cvt.rn.bf16x2.f32 %0, %1, %2;" : "=r"(h) : "f"(v1), "f"(v0));
    float f0 = __uint_as_float(h << 16);
    float f1 = __uint_as_float(h & 0xFFFF0000u);
    float l0 = v0 - f0, l1 = v1 - f1;
    unsigned l;
    asm("cvt.rn.bf16x2.f32 %0, %1, %2;" : "=r"(l) : "f"(l1), "f"(l0));
    hi = h; lo = l;
}

__device__ __forceinline__ void mma_bf16(float c[4],
                                         unsigned a0, unsigned a1, unsigned a2, unsigned a3,
                                         unsigned b0, unsigned b1) {
    asm volatile(
        "mma.sync.aligned.m16n8k16.row.col.f32.bf16.bf16.f32 "
        "{%0,%1,%2,%3}, {%4,%5,%6,%7}, {%8,%9}, {%0,%1,%2,%3};"
        : "+f"(c[0]), "+f"(c[1]), "+f"(c[2]), "+f"(c[3])
        : "r"(a0), "r"(a1), "r"(a2), "r"(a3), "r"(b0), "r"(b1));
}

__device__ __forceinline__ void cp_async16(uint32_t dst, const void* src, bool pred) {
    int sz = pred ? 16 : 0;
    asm volatile("cp.async.cg.shared.global [%0], [%1], 16, %2;"
                 :: "r"(dst), "l"(src), "r"(sz));
}
__device__ __forceinline__ void cp_commit() {
    asm volatile("cp.async.commit_group;");
}
template<int NW>
__device__ __forceinline__ void cp_wait() {
    asm volatile("cp.async.wait_group %0;" :: "n"(NW));
}

// --------------------------- dtype probe ---------------------------
__global__ void k_detect(const int* __restrict__ ei, int E) {
    __shared__ int nz;
    if (threadIdx.x == 0) nz = 0;
    __syncthreads();
    int samples = 4096;
    if (samples > E) samples = E;
    for (int i = threadIdx.x; i < samples; i += blockDim.x)
        if (ei[2 * i + 1] != 0) atomicOr(&nz, 1);
    __syncthreads();
    if (threadIdx.x == 0) g_is64 = (nz == 0) ? 1 : 0;
}

__global__ void k_zero(int n) {
    int stride = gridDim.x * blockDim.x;
    for (int i = blockIdx.x * blockDim.x + threadIdx.x; i < n; i += stride) {
        g_cnt[i] = 0; g_cnt2[i] = 0;
        g_asrc[i] = 0.f; g_adst[i] = 0.f; g_dot[i] = 0.f;
    }
}

// ----------- edge expansion (+ self loops) + fused histogram --------------
__global__ void k_convert(const int* __restrict__ ei, int E, int n) {
    int tot = E + n;
    int stride = gridDim.x * blockDim.x;
    int is64 = g_is64;
    for (int idx = blockIdx.x * blockDim.x + threadIdx.x; idx < tot; idx += stride) {
        int s, d;
        if (idx < E) {
            if (is64) { s = ei[2 * idx]; d = ei[2 * E + 2 * idx]; }
            else      { s = ei[idx];     d = ei[E + idx]; }
        } else {
            s = d = idx - E;
        }
        g_src[idx] = s;
        g_dst[idx] = d;
        atomicAdd(&g_cnt[d], 1);
    }
}

// ------------------------ hierarchical scan ------------------------
__global__ void k_scan1(int n) {
    __shared__ int sh[SCAN_T];
    int t = threadIdx.x;
    int i = blockIdx.x * SCAN_T + t;
    int v = (i < n) ? g_cnt[i] : 0;
    sh[t] = v;
    __syncthreads();
    for (int o = 1; o < SCAN_T; o <<= 1) {
        int x = (t >= o) ? sh[t - o] : 0;
        __syncthreads();
        sh[t] += x;
        __syncthreads();
    }
    if (i < n) g_rp[i] = sh[t] - v;
    if (t == SCAN_T - 1) g_part[blockIdx.x] = sh[t];
}

__global__ void k_scan2(int nb) {
    __shared__ int sh[256];
    int t = threadIdx.x;
    int v = (t < nb) ? g_part[t] : 0;
    sh[t] = v;
    __syncthreads();
    for (int o = 1; o < 256; o <<= 1) {
        int x = (t >= o) ? sh[t - o] : 0;
        __syncthreads();
        sh[t] += x;
        __syncthreads();
    }
    if (t < nb) g_part[t] = sh[t] - v;
}

__global__ void k_scan3(int n, int etot) {
    int i = blockIdx.x * SCAN_T + threadIdx.x;
    if (i < n) g_rp[i] += g_part[blockIdx.x];
    if (i == 0) g_rp[n] = etot;
}

__global__ void k_slot(int tot) {
    int stride = gridDim.x * blockDim.x;
    for (int i = blockIdx.x * blockDim.x + threadIdx.x; i < tot; i += stride) {
        int d = g_dst[i];
        int slot = g_rp[d] + atomicAdd(&g_cnt2[d], 1);
        g_csrc[slot] = g_src[i];
    }
}

// ---------------- fused layer-1 bias: bias2 = b1 + bias @ W1 --------------
__global__ void k_bias2(const float* __restrict__ bias,
                        const float* __restrict__ W1,
                        const float* __restrict__ b1, int K, int N) {
    int n = blockIdx.x * (blockDim.x >> 5) + (threadIdx.x >> 5);
    int lane = threadIdx.x & 31;
    if (n >= N) return;
    float s = 0.f;
    for (int k = lane; k < K; k += 32) s += bias[k] * W1[(size_t)k * N + n];
#pragma unroll
    for (int o = 16; o; o >>= 1) s += __shfl_xor_sync(0xFFFFFFFFu, s, o);
    if (lane == 0) g_bias2[n] = s + b1[n];
}

// ---------- weight split: src[K][N] fp32 -> transposed bf16 hi/lo [N][K] --
__global__ void k_splitB(const float* __restrict__ src,
                         __nv_bfloat16* __restrict__ dh,
                         __nv_bfloat16* __restrict__ dl, int K, int N) {
    int i = blockIdx.x * blockDim.x + threadIdx.x;
    if (i >= K * N) return;
    int k = i / N, n = i - k * N;
    float v = src[i];
    __nv_bfloat16 h = __float2bfloat16(v);
    float hf = __bfloat162float(h);
    __nv_bfloat16 l = __float2bfloat16(v - hf);
    dh[(size_t)n * K + k] = h;
    dl[(size_t)n * K + k] = l;
}

// --------- tensor-core GEMM: bf16x2 (3-term), 128x128 CTA, BK=16 ----------
// 256 threads, 8 warps (4M x 2N), 32x64 warp tiles, 2 CTAs/SM, 3 stages.
// CMODE: 0 = fp32 C store, 1 = packed hi/lo C store, 2 = fused dot (no C).
// ATT: fuse a_src/a_dst dots into the epilogue (GEMM1).
template<bool A_PACKED, int CMODE, bool RELU, bool CBIAS, bool ATT>
__global__ void __launch_bounds__(256, 2) k_mma(
    const float* __restrict__ A,
    const unsigned* __restrict__ Ahi, const unsigned* __restrict__ Alo,
    const __nv_bfloat16* __restrict__ Bth,
    const __nv_bfloat16* __restrict__ Btl,
    float* __restrict__ C,
    unsigned* __restrict__ Chi, unsigned* __restrict__ Clo,
    const float* __restrict__ cbias,
    const float* __restrict__ att_src, const float* __restrict__ att_dst,
    const float* __restrict__ W3,
    int M, int N, int K)
{
    extern __shared__ float sm[];
    const uint32_t smem_base = (uint32_t)__cvta_generic_to_shared(sm);

    const int tid  = threadIdx.x;
    const int wid  = tid >> 5;
    const int lane = tid & 31;
    const int gid  = lane >> 2;
    const int tig  = lane & 3;
    const int warpM = (wid & 3) * 32;
    const int warpN = (wid >> 2) * 64;
    const int rowBase = blockIdx.y * 128;
    const int colBase = blockIdx.x * 128;

    float acc[2][8][4];
#pragma unroll
    for (int mf = 0; mf < 2; mf++)
#pragma unroll
        for (int nf = 0; nf < 8; nf++)
#pragma unroll
            for (int r = 0; r < 4; r++) acc[mf][nf][r] = 0.f;

    auto cp_slab = [&](int k0, int stage) {
        uint32_t raA = smem_base + (stage * STAGE_F) * 4;
        uint32_t raB = raA + 2048 * 4;
        if (A_PACKED) {
#pragma unroll
            for (int it = 0; it < 2; it++) {
                int idx = it * 256 + tid;
                int plane = idx >> 8;
                int rem = idx & 255;
                int m = rem >> 1, c = rem & 1;
                int gr = rowBase + m;
                bool p = gr < M;
                const unsigned* srcP = plane ? Alo : Ahi;
                uint32_t dst = raA + plane * 1024 * 4 +
                               (m * 8 + (c ^ ((m >> 2) & 1)) * 4) * 4;
                cp_async16(dst, srcP + (size_t)(p ? gr : 0) * (K >> 1) + (k0 >> 1) + c * 4, p);
            }
        } else {
#pragma unroll
            for (int it = 0; it < 2; it++) {
                int idx = it * 256 + tid;
                int row = idx & 127;
                int k4  = idx >> 7;
                int gr = rowBase + row;
                bool p = gr < M;
                cp_async16(raA + (k4 * 512 + row * 4) * 4,
                           A + (size_t)(p ? gr : 0) * K + k0 + k4 * 4, p);
            }
        }
#pragma unroll
        for (int it = 0; it < 2; it++) {
            int idx = it * 256 + tid;
            int plane = idx >> 8;
            int rem = idx & 255;
            int n = rem >> 1, c = rem & 1;
            const __nv_bfloat16* srcP = plane ? Btl : Bth;
            uint32_t dst = raB + plane * 1024 * 4 +
                           (n * 8 + (c ^ ((n >> 2) & 1)) * 4) * 4;
            cp_async16(dst, srcP + (size_t)(colBase + n) * K + k0 + c * 8, true);
        }
    };

    const int S = K >> 4;

    cp_slab(0, 0);  cp_commit();
    cp_slab(16, 1); cp_commit();

    const int s4 = 4 * (gid >> 2);
    const int w0 = tig ^ s4;
    const int w1 = (tig + 4) ^ s4;

    for (int s = 0; s < S; s++) {
        if (s + 1 < S) cp_wait<1>(); else cp_wait<0>();
        __syncthreads();
        if (s + 2 < S) { cp_slab((s + 2) * 16, (s + 2) % 3); cp_commit(); }

        const int stage = s % 3;
        const float* rawA = sm + stage * STAGE_F;

        unsigned ah[2][4], al[2][4];
        if (A_PACKED) {
            const unsigned* AhS = reinterpret_cast<const unsigned*>(rawA);
            const unsigned* AlS = AhS + 1024;
#pragma unroll
            for (int mf = 0; mf < 2; mf++) {
                int b0 = (warpM + mf * 16 + gid) * 8;
                int b1 = b0 + 64;
                ah[mf][0] = AhS[b0 + w0]; ah[mf][1] = AhS[b1 + w0];
                ah[mf][2] = AhS[b0 + w1]; ah[mf][3] = AhS[b1 + w1];
                al[mf][0] = AlS[b0 + w0]; al[mf][1] = AlS[b1 + w0];
                al[mf][2] = AlS[b0 + w1]; al[mf][3] = AlS[b1 + w1];
            }
        } else {
            const float* Ap = rawA + ((tig * 2) >> 2) * 512 + (tig * 2 & 2);
#pragma unroll
            for (int mf = 0; mf < 2; mf++) {
                int m0 = (warpM + mf * 16 + gid) * 4;
                float2 v00 = *(const float2*)(Ap + m0);
                float2 v01 = *(const float2*)(Ap + m0 + 32);
                float2 v10 = *(const float2*)(Ap + 1024 + m0);
                float2 v11 = *(const float2*)(Ap + 1024 + m0 + 32);
                split2(v00.x, v00.y, ah[mf][0], al[mf][0]);
                split2(v01.x, v01.y, ah[mf][1], al[mf][1]);
                split2(v10.x, v10.y, ah[mf][2], al[mf][2]);
                split2(v11.x, v11.y, ah[mf][3], al[mf][3]);
            }
        }

        const unsigned* Bh = reinterpret_cast<const unsigned*>(rawA + 2048);
        const unsigned* Bl = Bh + 1024;
#pragma unroll
        for (int nf = 0; nf < 8; nf++) {
            int base = (warpN + nf * 8 + gid) * 8;
            unsigned bh0 = Bh[base + w0];
            unsigned bh1 = Bh[base + w1];
            unsigned bl0 = Bl[base + w0];
            unsigned bl1 = Bl[base + w1];
#pragma unroll
            for (int mf = 0; mf < 2; mf++) {
                mma_bf16(acc[mf][nf], al[mf][0], al[mf][1], al[mf][2], al[mf][3], bh0, bh1);
                mma_bf16(acc[mf][nf], ah[mf][0], ah[mf][1], ah[mf][2], ah[mf][3], bl0, bl1);
                mma_bf16(acc[mf][nf], ah[mf][0], ah[mf][1], ah[mf][2], ah[mf][3], bh0, bh1);
            }
        }
    }

    // ---- epilogue
    float psa[2][2] = {{0.f, 0.f}, {0.f, 0.f}};    // att_src partials (r0, r1)
    float psd[2][2] = {{0.f, 0.f}, {0.f, 0.f}};    // att_dst partials
    float pdt[2][2] = {{0.f, 0.f}, {0.f, 0.f}};    // W3 dot partials

#pragma unroll
    for (int mf = 0; mf < 2; mf++) {
        int r0 = rowBase + warpM + mf * 16 + gid;
        int r1 = r0 + 8;
#pragma unroll
        for (int nf = 0; nf < 8; nf++) {
            int gc = colBase + warpN + nf * 8 + tig * 2;
            float v0 = acc[mf][nf][0], v1 = acc[mf][nf][1];
            float v2 = acc[mf][nf][2], v3 = acc[mf][nf][3];
            if (CBIAS) {
                float2 bb = *(const float2*)(cbias + gc);
                v0 += bb.x; v1 += bb.y; v2 += bb.x; v3 += bb.y;
            }
            if (RELU) {
                v0 = fmaxf(v0, 0.f); v1 = fmaxf(v1, 0.f);
                v2 = fmaxf(v2, 0.f); v3 = fmaxf(v3, 0.f);
            }
            if (ATT) {
                float2 as = *(const float2*)(att_src + gc);
                float2 ad = *(const float2*)(att_dst + gc);
                psa[mf][0] += v0 * as.x + v1 * as.y;
                psa[mf][1] += v2 * as.x + v3 * as.y;
                psd[mf][0] += v0 * ad.x + v1 * ad.y;
                psd[mf][1] += v2 * ad.x + v3 * ad.y;
            }
            if (CMODE == 0) {
                if (r0 < M) { float2 o = {v0, v1}; *(float2*)(C + (size_t)r0 * N + gc) = o; }
                if (r1 < M) { float2 o = {v2, v3}; *(float2*)(C + (size_t)r1 * N + gc) = o; }
            } else if (CMODE == 1) {
                int wp = (gc >> 1);
                unsigned hi, lo;
                if (r0 < M) {
                    split2(v0, v1, hi, lo);
                    Chi[(size_t)r0 * (N >> 1) + wp] = hi;
                    Clo[(size_t)r0 * (N >> 1) + wp] = lo;
                }
                if (r1 < M) {
                    split2(v2, v3, hi, lo);
                    Chi[(size_t)r1 * (N >> 1) + wp] = hi;
                    Clo[(size_t)r1 * (N >> 1) + wp] = lo;
                }
            } else {  // CMODE == 2: fused final dot
                float2 w3 = *(const float2*)(W3 + gc);
                pdt[mf][0] += v0 * w3.x + v1 * w3.y;
                pdt[mf][1] += v2 * w3.x + v3 * w3.y;
            }
        }

        if (ATT) {
#pragma unroll
            for (int rs = 0; rs < 2; rs++) {
                float sa = psa[mf][rs], sd = psd[mf][rs];
                sa += __shfl_xor_sync(0xFFFFFFFFu, sa, 1);
                sa += __shfl_xor_sync(0xFFFFFFFFu, sa, 2);
                sd += __shfl_xor_sync(0xFFFFFFFFu, sd, 1);
                sd += __shfl_xor_sync(0xFFFFFFFFu, sd, 2);
                int r = rs ? r1 : r0;
                if (tig == 0 && r < M) {
                    atomicAdd(&g_asrc[r], sa);
                    atomicAdd(&g_adst[r], sd);
                }
            }
        }
        if (CMODE == 2) {
#pragma unroll
            for (int rs = 0; rs < 2; rs++) {
                float pv = pdt[mf][rs];
                pv += __shfl_xor_sync(0xFFFFFFFFu, pv, 1);
                pv += __shfl_xor_sync(0xFFFFFFFFu, pv, 2);
                int r = rs ? r1 : r0;
                if (tig == 0 && r < M) atomicAdd(&g_dot[r], pv);
            }
        }
    }
}

// --------- fused per-node softmax + aggregation (warp per dst) ------------
// output written as packed bf16x2 hi/lo planes (GEMM2's A operand)
__global__ void k_gather(int n) {
    int w = (blockIdx.x * blockDim.x + threadIdx.x) >> 5;
    int lane = threadIdx.x & 31;
    if (w >= n) return;

    int base = g_rp[w];
    int deg  = g_rp[w + 1] - base;
    float adst = g_adst[w];

    float m_l = -3.4e38f, z_l = 0.f;
    for (int j = lane; j < deg; j += 32) {
        int s = g_csrc[base + j];
        float e = g_asrc[s] + adst;
        e = (e > 0.f) ? e : NEG_SLOPE * e;
        float mn = fmaxf(m_l, e);
        z_l = z_l * __expf(m_l - mn) + __expf(e - mn);
        m_l = mn;
    }
#pragma unroll
    for (int o = 16; o; o >>= 1) {
        float mo = __shfl_xor_sync(0xFFFFFFFFu, m_l, o);
        float zo = __shfl_xor_sync(0xFFFFFFFFu, z_l, o);
        float mn = fmaxf(m_l, mo);
        z_l = z_l * __expf(m_l - mn) + zo * __expf(mo - mn);
        m_l = mn;
    }
    float m = m_l;
    float inv_z = 1.f / z_l;

    float4 a0 = make_float4(0.f, 0.f, 0.f, 0.f);
    float4 a1 = a0, a2 = a0, a3 = a0;
    for (int j0 = 0; j0 < deg; j0 += 32) {
        int j = j0 + lane;
        int s = 0; float wgt = 0.f;
        if (j < deg) {
            s = g_csrc[base + j];
            float e = g_asrc[s] + adst;
            e = (e > 0.f) ? e : NEG_SLOPE * e;
            wgt = __expf(e - m);
        }
        int cnt = deg - j0; if (cnt > 32) cnt = 32;
        int jj = 0;
        for (; jj + 4 <= cnt; jj += 4) {
            int   s0 = __shfl_sync(0xFFFFFFFFu, s,   jj);
            int   s1 = __shfl_sync(0xFFFFFFFFu, s,   jj + 1);
            int   s2 = __shfl_sync(0xFFFFFFFFu, s,   jj + 2);
            int   s3 = __shfl_sync(0xFFFFFFFFu, s,   jj + 3);
            float w0 = __shfl_sync(0xFFFFFFFFu, wgt, jj);
            float w1 = __shfl_sync(0xFFFFFFFFu, wgt, jj + 1);
            float w2 = __shfl_sync(0xFFFFFFFFu, wgt, jj + 2);
            float w3 = __shfl_sync(0xFFFFFFFFu, wgt, jj + 3);
            float4 v0 = ((const float4*)(g_h + (size_t)s0 * FDIM))[lane];
            float4 v1 = ((const float4*)(g_h + (size_t)s1 * FDIM))[lane];
            float4 v2 = ((const float4*)(g_h + (size_t)s2 * FDIM))[lane];
            float4 v3 = ((const float4*)(g_h + (size_t)s3 * FDIM))[lane];
            a0.x += w0 * v0.x; a0.y += w0 * v0.y; a0.z += w0 * v0.z; a0.w += w0 * v0.w;
            a1.x += w1 * v1.x; a1.y += w1 * v1.y; a1.z += w1 * v1.z; a1.w += w1 * v1.w;
            a2.x += w2 * v2.x; a2.y += w2 * v2.y; a2.z += w2 * v2.z; a2.w += w2 * v2.w;
            a3.x += w3 * v3.x; a3.y += w3 * v3.y; a3.z += w3 * v3.z; a3.w += w3 * v3.w;
        }
        for (; jj < cnt; jj++) {
            int   ss = __shfl_sync(0xFFFFFFFFu, s,   jj);
            float ww = __shfl_sync(0xFFFFFFFFu, wgt, jj);
            float4 v = ((const float4*)(g_h + (size_t)ss * FDIM))[lane];
            a0.x += ww * v.x; a0.y += ww * v.y;
            a0.z += ww * v.z; a0.w += ww * v.w;
        }
    }
    float4 acc;
    acc.x = ((a0.x + a1.x) + (a2.x + a3.x)) * inv_z;
    acc.y = ((a0.y + a1.y) + (a2.y + a3.y)) * inv_z;
    acc.z = ((a0.z + a1.z) + (a2.z + a3.z)) * inv_z;
    acc.w = ((a0.w + a1.w) + (a2.w + a3.w)) * inv_z;

    unsigned hi0, lo0, hi1, lo1;
    split2(acc.x, acc.y, hi0, lo0);
    split2(acc.z, acc.w, hi1, lo1);
    size_t b2 = (size_t)w * (FDIM / 2) + 2 * lane;
    g_gath[b2]     = hi0; g_gath[b2 + 1] = hi1;
    g_gatl[b2]     = lo0; g_gatl[b2 + 1] = lo1;
}

// ----------------------- final sigmoid over fused dot ---------------------
__global__ void k_final2(const float* __restrict__ b3,
                         float* __restrict__ out, int n) {
    int i = blockIdx.x * blockDim.x + threadIdx.x;
    if (i >= n) return;
    out[i] = 1.f / (1.f + expf(-(g_dot[i] + b3[0])));
}

// --------------------------- host launcher --------------------------------
extern "C" void kernel_launch(void* const* d_in, const int* in_sizes, int n_in,
                              void* d_out, int out_size) {
    const float* x       = (const float*)d_in[0];
    const int*   ei      = (const int*)d_in[1];
    const float* W       = (const float*)d_in[2];
    const float* att_src = (const float*)d_in[3];
    const float* att_dst = (const float*)d_in[4];
    const float* bias    = (const float*)d_in[5];
    const float* W1      = (const float*)d_in[6];
    const float* b1      = (const float*)d_in[7];
    const float* W2      = (const float*)d_in[8];
    const float* b2      = (const float*)d_in[9];
    const float* W3      = (const float*)d_in[10];
    const float* b3      = (const float*)d_in[11];
    float* out = (float*)d_out;

    int n = in_sizes[0] / FDIM;
    int E = in_sizes[1] / 2;
    int Etot = E + n;
    int scanBlocks = (n + SCAN_T - 1) / SCAN_T;

    void *p_h, *p_b2;
    void *p_gath, *p_gatl, *p_h1h, *p_h1l;
    void *p_wth, *p_wtl, *p_w1th, *p_w1tl, *p_w2th, *p_w2tl;
    cudaGetSymbolAddress(&p_h,    g_h);
    cudaGetSymbolAddress(&p_b2,   g_bias2);
    cudaGetSymbolAddress(&p_gath, g_gath);
    cudaGetSymbolAddress(&p_gatl, g_gatl);
    cudaGetSymbolAddress(&p_h1h,  g_h1h);
    cudaGetSymbolAddress(&p_h1l,  g_h1l);
    cudaGetSymbolAddress(&p_wth,  g_wth);
    cudaGetSymbolAddress(&p_wtl,  g_wtl);
    cudaGetSymbolAddress(&p_w1th, g_w1th);
    cudaGetSymbolAddress(&p_w1tl, g_w1tl);
    cudaGetSymbolAddress(&p_w2th, g_w2th);
    cudaGetSymbolAddress(&p_w2tl, g_w2tl);

    int mBlocks = (n + 127) / 128;

    cudaFuncSetAttribute(k_mma<false, 0, false, false, true>,
                         cudaFuncAttributeMaxDynamicSharedMemorySize, SMEM_BYTES);
    cudaFuncSetAttribute(k_mma<true, 1, true, true, false>,
                         cudaFuncAttributeMaxDynamicSharedMemorySize, SMEM_BYTES);
    cudaFuncSetAttribute(k_mma<true, 2, true, true, false>,
                         cudaFuncAttributeMaxDynamicSharedMemorySize, SMEM_BYTES);

    // weight splits (tiny) + CSR build (hist fused into convert)
    k_splitB<<<(FDIM * FDIM + 255) / 256, 256>>>(
        W, (__nv_bfloat16*)p_wth, (__nv_bfloat16*)p_wtl, FDIM, FDIM);
    k_detect<<<1, 256>>>(ei, E);
    k_zero<<<512, 256>>>(n);
    k_convert<<<2048, 256>>>(ei, E, n);

    // h = x @ W  (raw-A, fp32 C, fused att dots)
    k_mma<false, 0, false, false, true><<<dim3(1, mBlocks), 256, SMEM_BYTES>>>(
        x, nullptr, nullptr,
        (const __nv_bfloat16*)p_wth, (const __nv_bfloat16*)p_wtl,
        (float*)p_h, nullptr, nullptr, nullptr,
        att_src, att_dst, nullptr, n, FDIM, FDIM);

    k_splitB<<<(FDIM * HDIM + 255) / 256, 256>>>(
        W1, (__nv_bfloat16*)p_w1th, (__nv_bfloat16*)p_w1tl, FDIM, HDIM);
    k_splitB<<<(HDIM * HDIM + 255) / 256, 256>>>(
        W2, (__nv_bfloat16*)p_w2th, (__nv_bfloat16*)p_w2tl, HDIM, HDIM);
    k_bias2<<<(HDIM + 7) / 8, 256>>>(bias, W1, b1, FDIM, HDIM);
    k_scan1<<<scanBlocks, SCAN_T>>>(n);
    k_scan2<<<1, 256>>>(scanBlocks);
    k_scan3<<<scanBlocks, SCAN_T>>>(n, Etot);
    k_slot<<<2048, 256>>>(Etot);

    k_gather<<<(n + 7) / 8, 256>>>(n);

    // h1 = relu(gat @ W1 + bias2)  — packed A in, packed C out
    k_mma<true, 1, true, true, false><<<dim3(2, mBlocks), 256, SMEM_BYTES>>>(
        nullptr, (const unsigned*)p_gath, (const unsigned*)p_gatl,
        (const __nv_bfloat16*)p_w1th, (const __nv_bfloat16*)p_w1tl,
        nullptr, (unsigned*)p_h1h, (unsigned*)p_h1l,
        (const float*)p_b2, nullptr, nullptr, nullptr, n, HDIM, FDIM);
    // h2 @ W3 fused: relu(h1 @ W2 + b2) · W3 accumulated into g_dot
    k_mma<true, 2, true, true, false><<<dim3(2, mBlocks), 256, SMEM_BYTES>>>(
        nullptr, (const unsigned*)p_h1h, (const unsigned*)p_h1l,
        (const __nv_bfloat16*)p_w2th, (const __nv_bfloat16*)p_w2tl,
        nullptr, nullptr, nullptr, b2, nullptr, nullptr, W3, n, HDIM, HDIM);
    k_final2<<<(n + 255) / 256, 256>>>(b3, out, n);
}

// round 16
// speedup vs baseline: 1.9066x; 1.0271x over previous
#include <cuda_runtime.h>
#include <cuda_bf16.h>
#include <stdint.h>

#define NN      100000
#define FDIM    128
#define HDIM    256
#define EMAX    1800000
#define NEG_SLOPE 0.2f
#define SCAN_T  512

// smem per stage (4B words): A region 2048, B region 2048. 3 stages.
#define STAGE_F 4096
#define SMEM_BYTES (3 * STAGE_F * 4)

// -------- scratch (static device arrays; no runtime malloc) ----------
__device__ float    g_h   [(size_t)NN * FDIM];
__device__ float    g_asrc[NN];
__device__ float    g_adst[NN];
__device__ float    g_dot [NN];                // fused final dot accumulator
__device__ float    g_bias2[HDIM];             // b1 + bias @ W1
__device__ unsigned g_gath[(size_t)NN * (FDIM / 2)];   // gat packed bf16x2 hi
__device__ unsigned g_gatl[(size_t)NN * (FDIM / 2)];   //                 lo
__device__ unsigned g_h1h [(size_t)NN * (HDIM / 2)];   // h1 packed hi
__device__ unsigned g_h1l [(size_t)NN * (HDIM / 2)];   //           lo
__device__ int      g_src [EMAX];
__device__ int      g_dst [EMAX];
__device__ int      g_csrc[EMAX];
__device__ int      g_cnt [NN];
__device__ int      g_cnt2[NN];
__device__ int      g_rp  [NN + 1];
__device__ int      g_part[256];
__device__ int      g_is64;
// weight hi/lo bf16 planes, TRANSPOSED to [N][K]
__device__ __nv_bfloat16 g_wth [FDIM * FDIM];
__device__ __nv_bfloat16 g_wtl [FDIM * FDIM];
__device__ __nv_bfloat16 g_w1th[HDIM * FDIM];
__device__ __nv_bfloat16 g_w1tl[HDIM * FDIM];
__device__ __nv_bfloat16 g_w2th[HDIM * HDIM];
__device__ __nv_bfloat16 g_w2tl[HDIM * HDIM];

// --------------------------- helpers ---------------------------
__device__ __forceinline__ void split2(float v0, float v1,
                                       unsigned& hi, unsigned& lo) {
    unsigned h;
    asm("cvt.rn.bf16x2.f32 %0, %1, %2;" : "=r"(h) : "f"(v1), "f"(v0));
    float f0 = __uint_as_float(h << 16);
    float f1 = __uint_as_float(h & 0xFFFF0000u);
    float l0 = v0 - f0, l1 = v1 - f1;
    unsigned l;
    asm("cvt.rn.bf16x2.f32 %0, %1, %2;" : "=r"(l) : "f"(l1), "f"(l0));
    hi = h; lo = l;
}

__device__ __forceinline__ void mma_bf16(float c[4],
                                         unsigned a0, unsigned a1, unsigned a2, unsigned a3,
                                         unsigned b0, unsigned b1) {
    asm volatile(
        "mma.sync.aligned.m16n8k16.row.col.f32.bf16.bf16.f32 "
        "{%0,%1,%2,%3}, {%4,%5,%6,%7}, {%8,%9}, {%0,%1,%2,%3};"
        : "+f"(c[0]), "+f"(c[1]), "+f"(c[2]), "+f"(c[3])
        : "r"(a0), "r"(a1), "r"(a2), "r"(a3), "r"(b0), "r"(b1));
}

__device__ __forceinline__ void ldm_x4(unsigned& r0, unsigned& r1,
                                       unsigned& r2, unsigned& r3, uint32_t addr) {
    asm volatile("ldmatrix.sync.aligned.m8n8.x4.shared.b16 {%0,%1,%2,%3}, [%4];"
                 : "=r"(r0), "=r"(r1), "=r"(r2), "=r"(r3) : "r"(addr));
}

__device__ __forceinline__ void cp_async16(uint32_t dst, const void* src, bool pred) {
    int sz = pred ? 16 : 0;
    asm volatile("cp.async.cg.shared.global [%0], [%1], 16, %2;"
                 :: "r"(dst), "l"(src), "r"(sz));
}
__device__ __forceinline__ void cp_commit() {
    asm volatile("cp.async.commit_group;");
}
template<int NW>
__device__ __forceinline__ void cp_wait() {
    asm volatile("cp.async.wait_group %0;" :: "n"(NW));
}

// --------------------------- dtype probe ---------------------------
__global__ void k_detect(const int* __restrict__ ei, int E) {
    __shared__ int nz;
    if (threadIdx.x == 0) nz = 0;
    __syncthreads();
    int samples = 4096;
    if (samples > E) samples = E;
    for (int i = threadIdx.x; i < samples; i += blockDim.x)
        if (ei[2 * i + 1] != 0) atomicOr(&nz, 1);
    __syncthreads();
    if (threadIdx.x == 0) g_is64 = (nz == 0) ? 1 : 0;
}

__global__ void k_zero(int n) {
    int stride = gridDim.x * blockDim.x;
    for (int i = blockIdx.x * blockDim.x + threadIdx.x; i < n; i += stride) {
        g_cnt[i] = 0; g_cnt2[i] = 0;
        g_asrc[i] = 0.f; g_adst[i] = 0.f; g_dot[i] = 0.f;
    }
}

// ----------- edge expansion (+ self loops) + fused histogram --------------
__global__ void k_convert(const int* __restrict__ ei, int E, int n) {
    int tot = E + n;
    int stride = gridDim.x * blockDim.x;
    int is64 = g_is64;
    for (int idx = blockIdx.x * blockDim.x + threadIdx.x; idx < tot; idx += stride) {
        int s, d;
        if (idx < E) {
            if (is64) { s = ei[2 * idx]; d = ei[2 * E + 2 * idx]; }
            else      { s = ei[idx];     d = ei[E + idx]; }
        } else {
            s = d = idx - E;
        }
        g_src[idx] = s;
        g_dst[idx] = d;
        atomicAdd(&g_cnt[d], 1);
    }
}

// ------------------------ hierarchical scan ------------------------
__global__ void k_scan1(int n) {
    __shared__ int sh[SCAN_T];
    int t = threadIdx.x;
    int i = blockIdx.x * SCAN_T + t;
    int v = (i < n) ? g_cnt[i] : 0;
    sh[t] = v;
    __syncthreads();
    for (int o = 1; o < SCAN_T; o <<= 1) {
        int x = (t >= o) ? sh[t - o] : 0;
        __syncthreads();
        sh[t] += x;
        __syncthreads();
    }
    if (i < n) g_rp[i] = sh[t] - v;
    if (t == SCAN_T - 1) g_part[blockIdx.x] = sh[t];
}

__global__ void k_scan2(int nb) {
    __shared__ int sh[256];
    int t = threadIdx.x;
    int v = (t < nb) ? g_part[t] : 0;
    sh[t] = v;
    __syncthreads();
    for (int o = 1; o < 256; o <<= 1) {
        int x = (t >= o) ? sh[t - o] : 0;
        __syncthreads();
        sh[t] += x;
        __syncthreads();
    }
    if (t < nb) g_part[t] = sh[t] - v;
}

__global__ void k_scan3(int n, int etot) {
    int i = blockIdx.x * SCAN_T + threadIdx.x;
    if (i < n) g_rp[i] += g_part[blockIdx.x];
    if (i == 0) g_rp[n] = etot;
}

__global__ void k_slot(int tot) {
    int stride = gridDim.x * blockDim.x;
    for (int i = blockIdx.x * blockDim.x + threadIdx.x; i < tot; i += stride) {
        int d = g_dst[i];
        int slot = g_rp[d] + atomicAdd(&g_cnt2[d], 1);
        g_csrc[slot] = g_src[i];
    }
}

// ---------------- fused layer-1 bias: bias2 = b1 + bias @ W1 --------------
__global__ void k_bias2(const float* __restrict__ bias,
                        const float* __restrict__ W1,
                        const float* __restrict__ b1, int K, int N) {
    int n = blockIdx.x * (blockDim.x >> 5) + (threadIdx.x >> 5);
    int lane = threadIdx.x & 31;
    if (n >= N) return;
    float s = 0.f;
    for (int k = lane; k < K; k += 32) s += bias[k] * W1[(size_t)k * N + n];
#pragma unroll
    for (int o = 16; o; o >>= 1) s += __shfl_xor_sync(0xFFFFFFFFu, s, o);
    if (lane == 0) g_bias2[n] = s + b1[n];
}

// ---------- weight split: src[K][N] fp32 -> transposed bf16 hi/lo [N][K] --
__global__ void k_splitB(const float* __restrict__ src,
                         __nv_bfloat16* __restrict__ dh,
                         __nv_bfloat16* __restrict__ dl, int K, int N) {
    int i = blockIdx.x * blockDim.x + threadIdx.x;
    if (i >= K * N) return;
    int k = i / N, n = i - k * N;
    float v = src[i];
    __nv_bfloat16 h = __float2bfloat16(v);
    float hf = __bfloat162float(h);
    __nv_bfloat16 l = __float2bfloat16(v - hf);
    dh[(size_t)n * K + k] = h;
    dl[(size_t)n * K + k] = l;
}

// --------- tensor-core GEMM: bf16x2 (3-term), 128x128 CTA, BK=16 ----------
// 256 threads, 8 warps (4M x 2N), 32x64 warp tiles, 2 CTAs/SM, 3 stages.
// Fragment loads via ldmatrix.x4 (bit-identical to the scalar mapping).
// CMODE: 0 = fp32 C store, 1 = packed hi/lo C store, 2 = fused dot (no C).
// ATT: fuse a_src/a_dst dots into the epilogue (GEMM1).
template<bool A_PACKED, int CMODE, bool RELU, bool CBIAS, bool ATT>
__global__ void __launch_bounds__(256, 2) k_mma(
    const float* __restrict__ A,
    const unsigned* __restrict__ Ahi, const unsigned* __restrict__ Alo,
    const __nv_bfloat16* __restrict__ Bth,
    const __nv_bfloat16* __restrict__ Btl,
    float* __restrict__ C,
    unsigned* __restrict__ Chi, unsigned* __restrict__ Clo,
    const float* __restrict__ cbias,
    const float* __restrict__ att_src, const float* __restrict__ att_dst,
    const float* __restrict__ W3,
    int M, int N, int K)
{
    extern __shared__ float sm[];
    const uint32_t smem_base = (uint32_t)__cvta_generic_to_shared(sm);

    const int tid  = threadIdx.x;
    const int wid  = tid >> 5;
    const int lane = tid & 31;
    const int gid  = lane >> 2;
    const int tig  = lane & 3;
    const int warpM = (wid & 3) * 32;
    const int warpN = (wid >> 2) * 64;
    const int rowBase = blockIdx.y * 128;
    const int colBase = blockIdx.x * 128;

    // ldmatrix lane roles
    const int row8 = lane & 7;
    const int matA = lane >> 3;          // 0..3
    const int dmA  = matA & 1;           // row group (+8)
    const int caA  = matA >> 1;          // k-chunk
    const int dnB  = matA >> 1;          // B: n group (+8)
    const int cbB  = matA & 1;           // B: k-chunk

    float acc[2][8][4];
#pragma unroll
    for (int mf = 0; mf < 2; mf++)
#pragma unroll
        for (int nf = 0; nf < 8; nf++)
#pragma unroll
            for (int r = 0; r < 4; r++) acc[mf][nf][r] = 0.f;

    auto cp_slab = [&](int k0, int stage) {
        uint32_t raA = smem_base + (stage * STAGE_F) * 4;
        uint32_t raB = raA + 2048 * 4;
        if (A_PACKED) {
#pragma unroll
            for (int it = 0; it < 2; it++) {
                int idx = it * 256 + tid;
                int plane = idx >> 8;
                int rem = idx & 255;
                int m = rem >> 1, c = rem & 1;
                int gr = rowBase + m;
                bool p = gr < M;
                const unsigned* srcP = plane ? Alo : Ahi;
                uint32_t dst = raA + plane * 1024 * 4 +
                               (m * 8 + (c ^ ((m >> 2) & 1)) * 4) * 4;
                cp_async16(dst, srcP + (size_t)(p ? gr : 0) * (K >> 1) + (k0 >> 1) + c * 4, p);
            }
        } else {
#pragma unroll
            for (int it = 0; it < 2; it++) {
                int idx = it * 256 + tid;
                int row = idx & 127;
                int k4  = idx >> 7;
                int gr = rowBase + row;
                bool p = gr < M;
                cp_async16(raA + (k4 * 512 + row * 4) * 4,
                           A + (size_t)(p ? gr : 0) * K + k0 + k4 * 4, p);
            }
        }
#pragma unroll
        for (int it = 0; it < 2; it++) {
            int idx = it * 256 + tid;
            int plane = idx >> 8;
            int rem = idx & 255;
            int n = rem >> 1, c = rem & 1;
            const __nv_bfloat16* srcP = plane ? Btl : Bth;
            uint32_t dst = raB + plane * 1024 * 4 +
                           (n * 8 + (c ^ ((n >> 2) & 1)) * 4) * 4;
            cp_async16(dst, srcP + (size_t)(colBase + n) * K + k0 + c * 8, true);
        }
    };

    const int S = K >> 4;

    cp_slab(0, 0);  cp_commit();
    cp_slab(16, 1); cp_commit();

    for (int s = 0; s < S; s++) {
        if (s + 1 < S) cp_wait<1>(); else cp_wait<0>();
        __syncthreads();
        if (s + 2 < S) { cp_slab((s + 2) * 16, (s + 2) % 3); cp_commit(); }

        const int stage = s % 3;
        const uint32_t stB = smem_base + stage * STAGE_F * 4;   // bytes

        // ---- A fragments
        unsigned ah[2][4], al[2][4];
        if (A_PACKED) {
            // ldmatrix: mats (dm,c) = (0,0),(1,0),(0,1),(1,1) -> a0..a3
#pragma unroll
            for (int mf = 0; mf < 2; mf++) {
                int m = warpM + mf * 16 + dmA * 8 + row8;
                uint32_t woff = (uint32_t)(m * 8 + ((caA ^ ((m >> 2) & 1)) * 4)) * 4;
                ldm_x4(ah[mf][0], ah[mf][1], ah[mf][2], ah[mf][3], stB + woff);
                ldm_x4(al[mf][0], al[mf][1], al[mf][2], al[mf][3], stB + 4096 + woff);
            }
        } else {
            const float* rawA = sm + stage * STAGE_F;
            const float* Ap = rawA + ((tig * 2) >> 2) * 512 + (tig * 2 & 2);
#pragma unroll
            for (int mf = 0; mf < 2; mf++) {
                int m0 = (warpM + mf * 16 + gid) * 4;
                float2 v00 = *(const float2*)(Ap + m0);
                float2 v01 = *(const float2*)(Ap + m0 + 32);
                float2 v10 = *(const float2*)(Ap + 1024 + m0);
                float2 v11 = *(const float2*)(Ap + 1024 + m0 + 32);
                split2(v00.x, v00.y, ah[mf][0], al[mf][0]);
                split2(v01.x, v01.y, ah[mf][1], al[mf][1]);
                split2(v10.x, v10.y, ah[mf][2], al[mf][2]);
                split2(v11.x, v11.y, ah[mf][3], al[mf][3]);
            }
        }

        // ---- B fragments via ldmatrix (2 nf per x4) + MMAs
        const uint32_t bB = stB + 8192;
#pragma unroll
        for (int q = 0; q < 4; q++) {
            int n = warpN + (2 * q + dnB) * 8 + row8;
            uint32_t woff = (uint32_t)(n * 8 + ((cbB ^ ((n >> 2) & 1)) * 4)) * 4;
            unsigned bh0, bh1, bh2, bh3, bl0, bl1, bl2, bl3;
            ldm_x4(bh0, bh1, bh2, bh3, bB + woff);           // (nf=2q: b0,b1), (nf=2q+1: b0,b1)
            ldm_x4(bl0, bl1, bl2, bl3, bB + 4096 + woff);
#pragma unroll
            for (int mf = 0; mf < 2; mf++) {
                mma_bf16(acc[mf][2 * q], al[mf][0], al[mf][1], al[mf][2], al[mf][3], bh0, bh1);
                mma_bf16(acc[mf][2 * q], ah[mf][0], ah[mf][1], ah[mf][2], ah[mf][3], bl0, bl1);
                mma_bf16(acc[mf][2 * q], ah[mf][0], ah[mf][1], ah[mf][2], ah[mf][3], bh0, bh1);
                mma_bf16(acc[mf][2 * q + 1], al[mf][0], al[mf][1], al[mf][2], al[mf][3], bh2, bh3);
                mma_bf16(acc[mf][2 * q + 1], ah[mf][0], ah[mf][1], ah[mf][2], ah[mf][3], bl2, bl3);
                mma_bf16(acc[mf][2 * q + 1], ah[mf][0], ah[mf][1], ah[mf][2], ah[mf][3], bh2, bh3);
            }
        }
    }

    // ---- epilogue
    float psa[2][2] = {{0.f, 0.f}, {0.f, 0.f}};
    float psd[2][2] = {{0.f, 0.f}, {0.f, 0.f}};
    float pdt[2][2] = {{0.f, 0.f}, {0.f, 0.f}};

#pragma unroll
    for (int mf = 0; mf < 2; mf++) {
        int r0 = rowBase + warpM + mf * 16 + gid;
        int r1 = r0 + 8;
#pragma unroll
        for (int nf = 0; nf < 8; nf++) {
            int gc = colBase + warpN + nf * 8 + tig * 2;
            float v0 = acc[mf][nf][0], v1 = acc[mf][nf][1];
            float v2 = acc[mf][nf][2], v3 = acc[mf][nf][3];
            if (CBIAS) {
                float2 bb = *(const float2*)(cbias + gc);
                v0 += bb.x; v1 += bb.y; v2 += bb.x; v3 += bb.y;
            }
            if (RELU) {
                v0 = fmaxf(v0, 0.f); v1 = fmaxf(v1, 0.f);
                v2 = fmaxf(v2, 0.f); v3 = fmaxf(v3, 0.f);
            }
            if (ATT) {
                float2 as = *(const float2*)(att_src + gc);
                float2 ad = *(const float2*)(att_dst + gc);
                psa[mf][0] += v0 * as.x + v1 * as.y;
                psa[mf][1] += v2 * as.x + v3 * as.y;
                psd[mf][0] += v0 * ad.x + v1 * ad.y;
                psd[mf][1] += v2 * ad.x + v3 * ad.y;
            }
            if (CMODE == 0) {
                if (r0 < M) { float2 o = {v0, v1}; *(float2*)(C + (size_t)r0 * N + gc) = o; }
                if (r1 < M) { float2 o = {v2, v3}; *(float2*)(C + (size_t)r1 * N + gc) = o; }
            } else if (CMODE == 1) {
                int wp = (gc >> 1);
                unsigned hi, lo;
                if (r0 < M) {
                    split2(v0, v1, hi, lo);
                    Chi[(size_t)r0 * (N >> 1) + wp] = hi;
                    Clo[(size_t)r0 * (N >> 1) + wp] = lo;
                }
                if (r1 < M) {
                    split2(v2, v3, hi, lo);
                    Chi[(size_t)r1 * (N >> 1) + wp] = hi;
                    Clo[(size_t)r1 * (N >> 1) + wp] = lo;
                }
            } else {
                float2 w3 = *(const float2*)(W3 + gc);
                pdt[mf][0] += v0 * w3.x + v1 * w3.y;
                pdt[mf][1] += v2 * w3.x + v3 * w3.y;
            }
        }

        if (ATT) {
#pragma unroll
            for (int rs = 0; rs < 2; rs++) {
                float sa = psa[mf][rs], sd = psd[mf][rs];
                sa += __shfl_xor_sync(0xFFFFFFFFu, sa, 1);
                sa += __shfl_xor_sync(0xFFFFFFFFu, sa, 2);
                sd += __shfl_xor_sync(0xFFFFFFFFu, sd, 1);
                sd += __shfl_xor_sync(0xFFFFFFFFu, sd, 2);
                int r = rs ? r1 : r0;
                if (tig == 0 && r < M) {
                    atomicAdd(&g_asrc[r], sa);
                    atomicAdd(&g_adst[r], sd);
                }
            }
        }
        if (CMODE == 2) {
#pragma unroll
            for (int rs = 0; rs < 2; rs++) {
                float pv = pdt[mf][rs];
                pv += __shfl_xor_sync(0xFFFFFFFFu, pv, 1);
                pv += __shfl_xor_sync(0xFFFFFFFFu, pv, 2);
                int r = rs ? r1 : r0;
                if (tig == 0 && r < M) atomicAdd(&g_dot[r], pv);
            }
        }
    }
}

// --------- fused per-node softmax + aggregation (warp per dst) ------------
__global__ void k_gather(int n) {
    int w = (blockIdx.x * blockDim.x + threadIdx.x) >> 5;
    int lane = threadIdx.x & 31;
    if (w >= n) return;

    int base = g_rp[w];
    int deg  = g_rp[w + 1] - base;
    float adst = g_adst[w];

    float m_l = -3.4e38f, z_l = 0.f;
    for (int j = lane; j < deg; j += 32) {
        int s = g_csrc[base + j];
        float e = g_asrc[s] + adst;
        e = (e > 0.f) ? e : NEG_SLOPE * e;
        float mn = fmaxf(m_l, e);
        z_l = z_l * __expf(m_l - mn) + __expf(e - mn);
        m_l = mn;
    }
#pragma unroll
    for (int o = 16; o; o >>= 1) {
        float mo = __shfl_xor_sync(0xFFFFFFFFu, m_l, o);
        float zo = __shfl_xor_sync(0xFFFFFFFFu, z_l, o);
        float mn = fmaxf(m_l, mo);
        z_l = z_l * __expf(m_l - mn) + zo * __expf(mo - mn);
        m_l = mn;
    }
    float m = m_l;
    float inv_z = 1.f / z_l;

    float4 a0 = make_float4(0.f, 0.f, 0.f, 0.f);
    float4 a1 = a0, a2 = a0, a3 = a0;
    for (int j0 = 0; j0 < deg; j0 += 32) {
        int j = j0 + lane;
        int s = 0; float wgt = 0.f;
        if (j < deg) {
            s = g_csrc[base + j];
            float e = g_asrc[s] + adst;
            e = (e > 0.f) ? e : NEG_SLOPE * e;
            wgt = __expf(e - m);
        }
        int cnt = deg - j0; if (cnt > 32) cnt = 32;
        int jj = 0;
        for (; jj + 4 <= cnt; jj += 4) {
            int   s0 = __shfl_sync(0xFFFFFFFFu, s,   jj);
            int   s1 = __shfl_sync(0xFFFFFFFFu, s,   jj + 1);
            int   s2 = __shfl_sync(0xFFFFFFFFu, s,   jj + 2);
            int   s3 = __shfl_sync(0xFFFFFFFFu, s,   jj + 3);
            float w0 = __shfl_sync(0xFFFFFFFFu, wgt, jj);
            float w1 = __shfl_sync(0xFFFFFFFFu, wgt, jj + 1);
            float w2 = __shfl_sync(0xFFFFFFFFu, wgt, jj + 2);
            float w3 = __shfl_sync(0xFFFFFFFFu, wgt, jj + 3);
            float4 v0 = ((const float4*)(g_h + (size_t)s0 * FDIM))[lane];
            float4 v1 = ((const float4*)(g_h + (size_t)s1 * FDIM))[lane];
            float4 v2 = ((const float4*)(g_h + (size_t)s2 * FDIM))[lane];
            float4 v3 = ((const float4*)(g_h + (size_t)s3 * FDIM))[lane];
            a0.x += w0 * v0.x; a0.y += w0 * v0.y; a0.z += w0 * v0.z; a0.w += w0 * v0.w;
            a1.x += w1 * v1.x; a1.y += w1 * v1.y; a1.z += w1 * v1.z; a1.w += w1 * v1.w;
            a2.x += w2 * v2.x; a2.y += w2 * v2.y; a2.z += w2 * v2.z; a2.w += w2 * v2.w;
            a3.x += w3 * v3.x; a3.y += w3 * v3.y; a3.z += w3 * v3.z; a3.w += w3 * v3.w;
        }
        for (; jj < cnt; jj++) {
            int   ss = __shfl_sync(0xFFFFFFFFu, s,   jj);
            float ww = __shfl_sync(0xFFFFFFFFu, wgt, jj);
            float4 v = ((const float4*)(g_h + (size_t)ss * FDIM))[lane];
            a0.x += ww * v.x; a0.y += ww * v.y;
            a0.z += ww * v.z; a0.w += ww * v.w;
        }
    }
    float4 acc;
    acc.x = ((a0.x + a1.x) + (a2.x + a3.x)) * inv_z;
    acc.y = ((a0.y + a1.y) + (a2.y + a3.y)) * inv_z;
    acc.z = ((a0.z + a1.z) + (a2.z + a3.z)) * inv_z;
    acc.w = ((a0.w + a1.w) + (a2.w + a3.w)) * inv_z;

    unsigned hi0, lo0, hi1, lo1;
    split2(acc.x, acc.y, hi0, lo0);
    split2(acc.z, acc.w, hi1, lo1);
    size_t b2 = (size_t)w * (FDIM / 2) + 2 * lane;
    g_gath[b2]     = hi0; g_gath[b2 + 1] = hi1;
    g_gatl[b2]     = lo0; g_gatl[b2 + 1] = lo1;
}

// ----------------------- final sigmoid over fused dot ---------------------
__global__ void k_final2(const float* __restrict__ b3,
                         float* __restrict__ out, int n) {
    int i = blockIdx.x * blockDim.x + threadIdx.x;
    if (i >= n) return;
    out[i] = 1.f / (1.f + expf(-(g_dot[i] + b3[0])));
}

// --------------------------- host launcher --------------------------------
extern "C" void kernel_launch(void* const* d_in, const int* in_sizes, int n_in,
                              void* d_out, int out_size) {
    const float* x       = (const float*)d_in[0];
    const int*   ei      = (const int*)d_in[1];
    const float* W       = (const float*)d_in[2];
    const float* att_src = (const float*)d_in[3];
    const float* att_dst = (const float*)d_in[4];
    const float* bias    = (const float*)d_in[5];
    const float* W1      = (const float*)d_in[6];
    const float* b1      = (const float*)d_in[7];
    const float* W2      = (const float*)d_in[8];
    const float* b2      = (const float*)d_in[9];
    const float* W3      = (const float*)d_in[10];
    const float* b3      = (const float*)d_in[11];
    float* out = (float*)d_out;

    int n = in_sizes[0] / FDIM;
    int E = in_sizes[1] / 2;
    int Etot = E + n;
    int scanBlocks = (n + SCAN_T - 1) / SCAN_T;

    void *p_h, *p_b2;
    void *p_gath, *p_gatl, *p_h1h, *p_h1l;
    void *p_wth, *p_wtl, *p_w1th, *p_w1tl, *p_w2th, *p_w2tl;
    cudaGetSymbolAddress(&p_h,    g_h);
    cudaGetSymbolAddress(&p_b2,   g_bias2);
    cudaGetSymbolAddress(&p_gath, g_gath);
    cudaGetSymbolAddress(&p_gatl, g_gatl);
    cudaGetSymbolAddress(&p_h1h,  g_h1h);
    cudaGetSymbolAddress(&p_h1l,  g_h1l);
    cudaGetSymbolAddress(&p_wth,  g_wth);
    cudaGetSymbolAddress(&p_wtl,  g_wtl);
    cudaGetSymbolAddress(&p_w1th, g_w1th);
    cudaGetSymbolAddress(&p_w1tl, g_w1tl);
    cudaGetSymbolAddress(&p_w2th, g_w2th);
    cudaGetSymbolAddress(&p_w2tl, g_w2tl);

    int mBlocks = (n + 127) / 128;

    cudaFuncSetAttribute(k_mma<false, 0, false, false, true>,
                         cudaFuncAttributeMaxDynamicSharedMemorySize, SMEM_BYTES);
    cudaFuncSetAttribute(k_mma<true, 1, true, true, false>,
                         cudaFuncAttributeMaxDynamicSharedMemorySize, SMEM_BYTES);
    cudaFuncSetAttribute(k_mma<true, 2, true, true, false>,
                         cudaFuncAttributeMaxDynamicSharedMemorySize, SMEM_BYTES);

    // weight splits (tiny) + CSR build (hist fused into convert)
    k_splitB<<<(FDIM * FDIM + 255) / 256, 256>>>(
        W, (__nv_bfloat16*)p_wth, (__nv_bfloat16*)p_wtl, FDIM, FDIM);
    k_detect<<<1, 256>>>(ei, E);
    k_zero<<<512, 256>>>(n);
    k_convert<<<2048, 256>>>(ei, E, n);

    // h = x @ W  (raw-A, fp32 C, fused att dots)
    k_mma<false, 0, false, false, true><<<dim3(1, mBlocks), 256, SMEM_BYTES>>>(
        x, nullptr, nullptr,
        (const __nv_bfloat16*)p_wth, (const __nv_bfloat16*)p_wtl,
        (float*)p_h, nullptr, nullptr, nullptr,
        att_src, att_dst, nullptr, n, FDIM, FDIM);

    k_splitB<<<(FDIM * HDIM + 255) / 256, 256>>>(
        W1, (__nv_bfloat16*)p_w1th, (__nv_bfloat16*)p_w1tl, FDIM, HDIM);
    k_splitB<<<(HDIM * HDIM + 255) / 256, 256>>>(
        W2, (__nv_bfloat16*)p_w2th, (__nv_bfloat16*)p_w2tl, HDIM, HDIM);
    k_bias2<<<(HDIM + 7) / 8, 256>>>(bias, W1, b1, FDIM, HDIM);
    k_scan1<<<scanBlocks, SCAN_T>>>(n);
    k_scan2<<<1, 256>>>(scanBlocks);
    k_scan3<<<scanBlocks, SCAN_T>>>(n, Etot);
    k_slot<<<2048, 256>>>(Etot);

    k_gather<<<(n + 7) / 8, 256>>>(n);

    // h1 = relu(gat @ W1 + bias2)  — packed A in, packed C out
    k_mma<true, 1, true, true, false><<<dim3(2, mBlocks), 256, SMEM_BYTES>>>(
        nullptr, (const unsigned*)p_gath, (const unsigned*)p_gatl,
        (const __nv_bfloat16*)p_w1th, (const __nv_bfloat16*)p_w1tl,
        nullptr, (unsigned*)p_h1h, (unsigned*)p_h1l,
        (const float*)p_b2, nullptr, nullptr, nullptr, n, HDIM, FDIM);
    // h2 @ W3 fused: relu(h1 @ W2 + b2) · W3 accumulated into g_dot
    k_mma<true, 2, true, true, false><<<dim3(2, mBlocks), 256, SMEM_BYTES>>>(
        nullptr, (const unsigned*)p_h1h, (const unsigned*)p_h1l,
        (const __nv_bfloat16*)p_w2th, (const __nv_bfloat16*)p_w2tl,
        nullptr, nullptr, nullptr, b2, nullptr, nullptr, W3, n, HDIM, HDIM);
    k_final2<<<(n + 255) / 256, 256>>>(b3, out, n);
}

// round 17
// speedup vs baseline: 2.0832x; 1.0926x over previous
#include <cuda_runtime.h>
#include <cuda_bf16.h>
#include <stdint.h>

#define NN      100000
#define FDIM    128
#define HDIM    256
#define EMAX    1800000
#define NEG_SLOPE 0.2f
#define SCAN_T  512

// smem per stage (4B words): A region 4096 (2 planes x 128 rows x 16 words
// OR raw fp32 8 chunks x 128 x 4), B region 4096. 3 stages, BK = 32.
#define STAGE_F 8192
#define SMEM_BYTES (3 * STAGE_F * 4)

// -------- scratch (static device arrays; no runtime malloc) ----------
__device__ float    g_h   [(size_t)NN * FDIM];
__device__ float    g_asrc[NN];
__device__ float    g_adst[NN];
__device__ float    g_dot [NN];                // fused final dot accumulator
__device__ float    g_bias2[HDIM];             // b1 + bias @ W1
__device__ unsigned g_gath[(size_t)NN * (FDIM / 2)];   // gat packed bf16x2 hi
__device__ unsigned g_gatl[(size_t)NN * (FDIM / 2)];   //                 lo
__device__ unsigned g_h1h [(size_t)NN * (HDIM / 2)];   // h1 packed hi
__device__ unsigned g_h1l [(size_t)NN * (HDIM / 2)];   //           lo
__device__ int      g_csrc[EMAX];
__device__ int      g_cnt [NN];
__device__ int      g_cnt2[NN];
__device__ int      g_rp  [NN + 1];
__device__ int      g_part[256];
__device__ int      g_is64;
// weight hi/lo bf16 planes, TRANSPOSED to [N][K]
__device__ __nv_bfloat16 g_wth [FDIM * FDIM];
__device__ __nv_bfloat16 g_wtl [FDIM * FDIM];
__device__ __nv_bfloat16 g_w1th[HDIM * FDIM];
__device__ __nv_bfloat16 g_w1tl[HDIM * FDIM];
__device__ __nv_bfloat16 g_w2th[HDIM * HDIM];
__device__ __nv_bfloat16 g_w2tl[HDIM * HDIM];

// --------------------------- helpers ---------------------------
__device__ __forceinline__ void split2(float v0, float v1,
                                       unsigned& hi, unsigned& lo) {
    unsigned h;
    asm("cvt.rn.bf16x2.f32 %0, %1, %2;" : "=r"(h) : "f"(v1), "f"(v0));
    float f0 = __uint_as_float(h << 16);
    float f1 = __uint_as_float(h & 0xFFFF0000u);
    float l0 = v0 - f0, l1 = v1 - f1;
    unsigned l;
    asm("cvt.rn.bf16x2.f32 %0, %1, %2;" : "=r"(l) : "f"(l1), "f"(l0));
    hi = h; lo = l;
}

__device__ __forceinline__ void mma_bf16(float c[4],
                                         unsigned a0, unsigned a1, unsigned a2, unsigned a3,
                                         unsigned b0, unsigned b1) {
    asm volatile(
        "mma.sync.aligned.m16n8k16.row.col.f32.bf16.bf16.f32 "
        "{%0,%1,%2,%3}, {%4,%5,%6,%7}, {%8,%9}, {%0,%1,%2,%3};"
        : "+f"(c[0]), "+f"(c[1]), "+f"(c[2]), "+f"(c[3])
        : "r"(a0), "r"(a1), "r"(a2), "r"(a3), "r"(b0), "r"(b1));
}

__device__ __forceinline__ void ldm_x4(unsigned& r0, unsigned& r1,
                                       unsigned& r2, unsigned& r3, uint32_t addr) {
    asm volatile("ldmatrix.sync.aligned.m8n8.x4.shared.b16 {%0,%1,%2,%3}, [%4];"
                 : "=r"(r0), "=r"(r1), "=r"(r2), "=r"(r3) : "r"(addr));
}

__device__ __forceinline__ void cp_async16(uint32_t dst, const void* src, bool pred) {
    int sz = pred ? 16 : 0;
    asm volatile("cp.async.cg.shared.global [%0], [%1], 16, %2;"
                 :: "r"(dst), "l"(src), "r"(sz));
}
__device__ __forceinline__ void cp_commit() {
    asm volatile("cp.async.commit_group;");
}
template<int NW>
__device__ __forceinline__ void cp_wait() {
    asm volatile("cp.async.wait_group %0;" :: "n"(NW));
}

// --------------------------- dtype probe ---------------------------
__global__ void k_detect(const int* __restrict__ ei, int E) {
    __shared__ int nz;
    if (threadIdx.x == 0) nz = 0;
    __syncthreads();
    int samples = 4096;
    if (samples > E) samples = E;
    for (int i = threadIdx.x; i < samples; i += blockDim.x)
        if (ei[2 * i + 1] != 0) atomicOr(&nz, 1);
    __syncthreads();
    if (threadIdx.x == 0) g_is64 = (nz == 0) ? 1 : 0;
}

__global__ void k_zero(int n) {
    int stride = gridDim.x * blockDim.x;
    for (int i = blockIdx.x * blockDim.x + threadIdx.x; i < n; i += stride) {
        g_cnt[i] = 0; g_cnt2[i] = 0;
        g_asrc[i] = 0.f; g_adst[i] = 0.f; g_dot[i] = 0.f;
    }
}

// --------- pass 1: histogram of incoming-edge counts (direct decode) ------
__global__ void k_hist(const int* __restrict__ ei, int E, int n) {
    int tot = E + n;
    int stride = gridDim.x * blockDim.x;
    int is64 = g_is64;
    for (int idx = blockIdx.x * blockDim.x + threadIdx.x; idx < tot; idx += stride) {
        int d = (idx < E) ? (is64 ? ei[2 * E + 2 * idx] : ei[E + idx]) : (idx - E);
        atomicAdd(&g_cnt[d], 1);
    }
}

// ------------------------ hierarchical scan ------------------------
__global__ void k_scan1(int n) {
    __shared__ int sh[SCAN_T];
    int t = threadIdx.x;
    int i = blockIdx.x * SCAN_T + t;
    int v = (i < n) ? g_cnt[i] : 0;
    sh[t] = v;
    __syncthreads();
    for (int o = 1; o < SCAN_T; o <<= 1) {
        int x = (t >= o) ? sh[t - o] : 0;
        __syncthreads();
        sh[t] += x;
        __syncthreads();
    }
    if (i < n) g_rp[i] = sh[t] - v;
    if (t == SCAN_T - 1) g_part[blockIdx.x] = sh[t];
}

__global__ void k_scan2(int nb) {
    __shared__ int sh[256];
    int t = threadIdx.x;
    int v = (t < nb) ? g_part[t] : 0;
    sh[t] = v;
    __syncthreads();
    for (int o = 1; o < 256; o <<= 1) {
        int x = (t >= o) ? sh[t - o] : 0;
        __syncthreads();
        sh[t] += x;
        __syncthreads();
    }
    if (t < nb) g_part[t] = sh[t] - v;
}

// --------- pass 2: slot assignment (direct decode; scan3 folded in) -------
__global__ void k_slot(const int* __restrict__ ei, int E, int n) {
    int tot = E + n;
    int stride = gridDim.x * blockDim.x;
    int is64 = g_is64;
    for (int idx = blockIdx.x * blockDim.x + threadIdx.x; idx < tot; idx += stride) {
        int s, d;
        if (idx < E) {
            if (is64) { s = ei[2 * idx]; d = ei[2 * E + 2 * idx]; }
            else      { s = ei[idx];     d = ei[E + idx]; }
        } else {
            s = d = idx - E;
        }
        int slot = g_rp[d] + g_part[d >> 9] + atomicAdd(&g_cnt2[d], 1);
        g_csrc[slot] = s;
    }
}

// ---------------- fused layer-1 bias: bias2 = b1 + bias @ W1 --------------
__global__ void k_bias2(const float* __restrict__ bias,
                        const float* __restrict__ W1,
                        const float* __restrict__ b1, int K, int N) {
    int n = blockIdx.x * (blockDim.x >> 5) + (threadIdx.x >> 5);
    int lane = threadIdx.x & 31;
    if (n >= N) return;
    float s = 0.f;
    for (int k = lane; k < K; k += 32) s += bias[k] * W1[(size_t)k * N + n];
#pragma unroll
    for (int o = 16; o; o >>= 1) s += __shfl_xor_sync(0xFFFFFFFFu, s, o);
    if (lane == 0) g_bias2[n] = s + b1[n];
}

// ---------- weight split: src[K][N] fp32 -> transposed bf16 hi/lo [N][K] --
__global__ void k_splitB(const float* __restrict__ src,
                         __nv_bfloat16* __restrict__ dh,
                         __nv_bfloat16* __restrict__ dl, int K, int N) {
    int i = blockIdx.x * blockDim.x + threadIdx.x;
    if (i >= K * N) return;
    int k = i / N, n = i - k * N;
    float v = src[i];
    __nv_bfloat16 h = __float2bfloat16(v);
    float hf = __bfloat162float(h);
    __nv_bfloat16 l = __float2bfloat16(v - hf);
    dh[(size_t)n * K + k] = h;
    dl[(size_t)n * K + k] = l;
}

// --------- tensor-core GEMM: bf16x2 (3-term), 128x128 CTA, BK=32 ----------
// 256 threads, 8 warps (4M x 2N), 32x64 warp tiles, 2 CTAs/SM, 3 stages.
// Fragment loads via ldmatrix.x4; 4-chunk XOR swizzle c^((row>>1)&3).
// CMODE: 0 = fp32 C store, 1 = packed hi/lo C store, 2 = fused dot (no C).
// ATT: fuse a_src/a_dst dots into the epilogue (GEMM1).
template<bool A_PACKED, int CMODE, bool RELU, bool CBIAS, bool ATT>
__global__ void __launch_bounds__(256, 2) k_mma(
    const float* __restrict__ A,
    const unsigned* __restrict__ Ahi, const unsigned* __restrict__ Alo,
    const __nv_bfloat16* __restrict__ Bth,
    const __nv_bfloat16* __restrict__ Btl,
    float* __restrict__ C,
    unsigned* __restrict__ Chi, unsigned* __restrict__ Clo,
    const float* __restrict__ cbias,
    const float* __restrict__ att_src, const float* __restrict__ att_dst,
    const float* __restrict__ W3,
    int M, int N, int K)
{
    extern __shared__ float sm[];
    const uint32_t smem_base = (uint32_t)__cvta_generic_to_shared(sm);

    const int tid  = threadIdx.x;
    const int wid  = tid >> 5;
    const int lane = tid & 31;
    const int gid  = lane >> 2;
    const int tig  = lane & 3;
    const int warpM = (wid & 3) * 32;
    const int warpN = (wid >> 2) * 64;
    const int rowBase = blockIdx.y * 128;
    const int colBase = blockIdx.x * 128;

    // ldmatrix lane roles
    const int row8 = lane & 7;
    const int matA = lane >> 3;          // 0..3
    const int dmA  = matA & 1;           // A: row group (+8)
    const int caA  = matA >> 1;          // A: k-chunk within k-step
    const int dnB  = matA >> 1;          // B: n group (+8)
    const int cbB  = matA & 1;           // B: k-chunk within k-step

    float acc[2][8][4];
#pragma unroll
    for (int mf = 0; mf < 2; mf++)
#pragma unroll
        for (int nf = 0; nf < 8; nf++)
#pragma unroll
            for (int r = 0; r < 4; r++) acc[mf][nf][r] = 0.f;

    auto cp_slab = [&](int k0, int stage) {
        uint32_t ra = smem_base + stage * STAGE_F * 4;
        if (A_PACKED) {
#pragma unroll
            for (int it = 0; it < 4; it++) {
                int idx = it * 256 + tid;          // 0..1023
                int c = idx & 3;
                int m = (idx >> 2) & 127;
                int plane = idx >> 9;
                int gr = rowBase + m;
                bool p = gr < M;
                const unsigned* srcP = plane ? Alo : Ahi;
                uint32_t dst = ra + (plane * 2048 + m * 16 +
                                     ((c ^ ((m >> 1) & 3)) * 4)) * 4;
                cp_async16(dst, srcP + (size_t)(p ? gr : 0) * (K >> 1) + (k0 >> 1) + c * 4, p);
            }
        } else {
            // raw fp32: 8 k-chunks x 128 rows, layout [k4][m][4]
#pragma unroll
            for (int it = 0; it < 4; it++) {
                int idx = it * 256 + tid;
                int m = idx & 127;
                int k4 = idx >> 7;                 // 0..7
                int gr = rowBase + m;
                bool p = gr < M;
                cp_async16(ra + (k4 * 512 + m * 4) * 4,
                           A + (size_t)(p ? gr : 0) * K + k0 + k4 * 4, p);
            }
        }
#pragma unroll
        for (int it = 0; it < 4; it++) {
            int idx = it * 256 + tid;
            int c = idx & 3;
            int n = (idx >> 2) & 127;
            int plane = idx >> 9;
            const __nv_bfloat16* srcP = plane ? Btl : Bth;
            uint32_t dst = ra + (4096 + plane * 2048 + n * 16 +
                                 ((c ^ ((n >> 1) & 3)) * 4)) * 4;
            cp_async16(dst, srcP + (size_t)(colBase + n) * K + k0 + c * 8, true);
        }
    };

    const int S = K >> 5;

    cp_slab(0, 0);  cp_commit();
    cp_slab(32, 1); cp_commit();

    for (int s = 0; s < S; s++) {
        if (s + 1 < S) cp_wait<1>(); else cp_wait<0>();
        __syncthreads();
        if (s + 2 < S) { cp_slab((s + 2) * 32, (s + 2) % 3); cp_commit(); }

        const int stage = s % 3;
        const uint32_t stB = smem_base + stage * STAGE_F * 4;   // bytes

#pragma unroll
        for (int ks = 0; ks < 2; ks++) {
            // ---- A fragments
            unsigned ah[2][4], al[2][4];
            if (A_PACKED) {
#pragma unroll
                for (int mf = 0; mf < 2; mf++) {
                    int m = warpM + mf * 16 + dmA * 8 + row8;
                    int chunk = ks * 2 + caA;
                    uint32_t woff = (uint32_t)(m * 16 +
                                    ((chunk ^ ((m >> 1) & 3)) * 4)) * 4;
                    ldm_x4(ah[mf][0], ah[mf][1], ah[mf][2], ah[mf][3], stB + woff);
                    ldm_x4(al[mf][0], al[mf][1], al[mf][2], al[mf][3], stB + 8192 + woff);
                }
            } else {
                const float* rawA = sm + stage * STAGE_F;
                const float* Ap = rawA + (ks * 4 + ((tig * 2) >> 2)) * 512 + (tig * 2 & 2);
#pragma unroll
                for (int mf = 0; mf < 2; mf++) {
                    int m0 = (warpM + mf * 16 + gid) * 4;
                    float2 v00 = *(const float2*)(Ap + m0);
                    float2 v01 = *(const float2*)(Ap + m0 + 32);
                    float2 v10 = *(const float2*)(Ap + 1024 + m0);
                    float2 v11 = *(const float2*)(Ap + 1024 + m0 + 32);
                    split2(v00.x, v00.y, ah[mf][0], al[mf][0]);
                    split2(v01.x, v01.y, ah[mf][1], al[mf][1]);
                    split2(v10.x, v10.y, ah[mf][2], al[mf][2]);
                    split2(v11.x, v11.y, ah[mf][3], al[mf][3]);
                }
            }

            // ---- B fragments via ldmatrix (2 nf per x4) + MMAs
            const uint32_t bB = stB + 16384;
#pragma unroll
            for (int q = 0; q < 4; q++) {
                int n = warpN + (2 * q + dnB) * 8 + row8;
                int chunk = ks * 2 + cbB;
                uint32_t woff = (uint32_t)(n * 16 +
                                ((chunk ^ ((n >> 1) & 3)) * 4)) * 4;
                unsigned bh0, bh1, bh2, bh3, bl0, bl1, bl2, bl3;
                ldm_x4(bh0, bh1, bh2, bh3, bB + woff);
                ldm_x4(bl0, bl1, bl2, bl3, bB + 8192 + woff);
#pragma unroll
                for (int mf = 0; mf < 2; mf++) {
                    mma_bf16(acc[mf][2 * q], al[mf][0], al[mf][1], al[mf][2], al[mf][3], bh0, bh1);
                    mma_bf16(acc[mf][2 * q], ah[mf][0], ah[mf][1], ah[mf][2], ah[mf][3], bl0, bl1);
                    mma_bf16(acc[mf][2 * q], ah[mf][0], ah[mf][1], ah[mf][2], ah[mf][3], bh0, bh1);
                    mma_bf16(acc[mf][2 * q + 1], al[mf][0], al[mf][1], al[mf][2], al[mf][3], bh2, bh3);
                    mma_bf16(acc[mf][2 * q + 1], ah[mf][0], ah[mf][1], ah[mf][2], ah[mf][3], bl2, bl3);
                    mma_bf16(acc[mf][2 * q + 1], ah[mf][0], ah[mf][1], ah[mf][2], ah[mf][3], bh2, bh3);
                }
            }
        }
    }

    // ---- epilogue
    float psa[2][2] = {{0.f, 0.f}, {0.f, 0.f}};
    float psd[2][2] = {{0.f, 0.f}, {0.f, 0.f}};
    float pdt[2][2] = {{0.f, 0.f}, {0.f, 0.f}};

#pragma unroll
    for (int mf = 0; mf < 2; mf++) {
        int r0 = rowBase + warpM + mf * 16 + gid;
        int r1 = r0 + 8;
#pragma unroll
        for (int nf = 0; nf < 8; nf++) {
            int gc = colBase + warpN + nf * 8 + tig * 2;
            float v0 = acc[mf][nf][0], v1 = acc[mf][nf][1];
            float v2 = acc[mf][nf][2], v3 = acc[mf][nf][3];
            if (CBIAS) {
                float2 bb = *(const float2*)(cbias + gc);
                v0 += bb.x; v1 += bb.y; v2 += bb.x; v3 += bb.y;
            }
            if (RELU) {
                v0 = fmaxf(v0, 0.f); v1 = fmaxf(v1, 0.f);
                v2 = fmaxf(v2, 0.f); v3 = fmaxf(v3, 0.f);
            }
            if (ATT) {
                float2 as = *(const float2*)(att_src + gc);
                float2 ad = *(const float2*)(att_dst + gc);
                psa[mf][0] += v0 * as.x + v1 * as.y;
                psa[mf][1] += v2 * as.x + v3 * as.y;
                psd[mf][0] += v0 * ad.x + v1 * ad.y;
                psd[mf][1] += v2 * ad.x + v3 * ad.y;
            }
            if (CMODE == 0) {
                if (r0 < M) { float2 o = {v0, v1}; *(float2*)(C + (size_t)r0 * N + gc) = o; }
                if (r1 < M) { float2 o = {v2, v3}; *(float2*)(C + (size_t)r1 * N + gc) = o; }
            } else if (CMODE == 1) {
                int wp = (gc >> 1);
                unsigned hi, lo;
                if (r0 < M) {
                    split2(v0, v1, hi, lo);
                    Chi[(size_t)r0 * (N >> 1) + wp] = hi;
                    Clo[(size_t)r0 * (N >> 1) + wp] = lo;
                }
                if (r1 < M) {
                    split2(v2, v3, hi, lo);
                    Chi[(size_t)r1 * (N >> 1) + wp] = hi;
                    Clo[(size_t)r1 * (N >> 1) + wp] = lo;
                }
            } else {
                float2 w3 = *(const float2*)(W3 + gc);
                pdt[mf][0] += v0 * w3.x + v1 * w3.y;
                pdt[mf][1] += v2 * w3.x + v3 * w3.y;
            }
        }

        if (ATT) {
#pragma unroll
            for (int rs = 0; rs < 2; rs++) {
                float sa = psa[mf][rs], sd = psd[mf][rs];
                sa += __shfl_xor_sync(0xFFFFFFFFu, sa, 1);
                sa += __shfl_xor_sync(0xFFFFFFFFu, sa, 2);
                sd += __shfl_xor_sync(0xFFFFFFFFu, sd, 1);
                sd += __shfl_xor_sync(0xFFFFFFFFu, sd, 2);
                int r = rs ? r1 : r0;
                if (tig == 0 && r < M) {
                    atomicAdd(&g_asrc[r], sa);
                    atomicAdd(&g_adst[r], sd);
                }
            }
        }
        if (CMODE == 2) {
#pragma unroll
            for (int rs = 0; rs < 2; rs++) {
                float pv = pdt[mf][rs];
                pv += __shfl_xor_sync(0xFFFFFFFFu, pv, 1);
                pv += __shfl_xor_sync(0xFFFFFFFFu, pv, 2);
                int r = rs ? r1 : r0;
                if (tig == 0 && r < M) atomicAdd(&g_dot[r], pv);
            }
        }
    }
}

// --------- fused per-node softmax + aggregation (warp per dst) ------------
__global__ void k_gather(int n, int etot) {
    int w = (blockIdx.x * blockDim.x + threadIdx.x) >> 5;
    int lane = threadIdx.x & 31;
    if (w >= n) return;

    int base = g_rp[w] + g_part[w >> 9];
    int nxt  = (w + 1 < n) ? (g_rp[w + 1] + g_part[(w + 1) >> 9]) : etot;
    int deg  = nxt - base;
    float adst = g_adst[w];

    float m_l = -3.4e38f, z_l = 0.f;
    for (int j = lane; j < deg; j += 32) {
        int s = g_csrc[base + j];
        float e = g_asrc[s] + adst;
        e = (e > 0.f) ? e : NEG_SLOPE * e;
        float mn = fmaxf(m_l, e);
        z_l = z_l * __expf(m_l - mn) + __expf(e - mn);
        m_l = mn;
    }
#pragma unroll
    for (int o = 16; o; o >>= 1) {
        float mo = __shfl_xor_sync(0xFFFFFFFFu, m_l, o);
        float zo = __shfl_xor_sync(0xFFFFFFFFu, z_l, o);
        float mn = fmaxf(m_l, mo);
        z_l = z_l * __expf(m_l - mn) + zo * __expf(mo - mn);
        m_l = mn;
    }
    float m = m_l;
    float inv_z = 1.f / z_l;

    float4 a0 = make_float4(0.f, 0.f, 0.f, 0.f);
    float4 a1 = a0, a2 = a0, a3 = a0;
    for (int j0 = 0; j0 < deg; j0 += 32) {
        int j = j0 + lane;
        int s = 0; float wgt = 0.f;
        if (j < deg) {
            s = g_csrc[base + j];
            float e = g_asrc[s] + adst;
            e = (e > 0.f) ? e : NEG_SLOPE * e;
            wgt = __expf(e - m);
        }
        int cnt = deg - j0; if (cnt > 32) cnt = 32;
        int jj = 0;
        for (; jj + 4 <= cnt; jj += 4) {
            int   s0 = __shfl_sync(0xFFFFFFFFu, s,   jj);
            int   s1 = __shfl_sync(0xFFFFFFFFu, s,   jj + 1);
            int   s2 = __shfl_sync(0xFFFFFFFFu, s,   jj + 2);
            int   s3 = __shfl_sync(0xFFFFFFFFu, s,   jj + 3);
            float w0 = __shfl_sync(0xFFFFFFFFu, wgt, jj);
            float w1 = __shfl_sync(0xFFFFFFFFu, wgt, jj + 1);
            float w2 = __shfl_sync(0xFFFFFFFFu, wgt, jj + 2);
            float w3 = __shfl_sync(0xFFFFFFFFu, wgt, jj + 3);
            float4 v0 = ((const float4*)(g_h + (size_t)s0 * FDIM))[lane];
            float4 v1 = ((const float4*)(g_h + (size_t)s1 * FDIM))[lane];
            float4 v2 = ((const float4*)(g_h + (size_t)s2 * FDIM))[lane];
            float4 v3 = ((const float4*)(g_h + (size_t)s3 * FDIM))[lane];
            a0.x += w0 * v0.x; a0.y += w0 * v0.y; a0.z += w0 * v0.z; a0.w += w0 * v0.w;
            a1.x += w1 * v1.x; a1.y += w1 * v1.y; a1.z += w1 * v1.z; a1.w += w1 * v1.w;
            a2.x += w2 * v2.x; a2.y += w2 * v2.y; a2.z += w2 * v2.z; a2.w += w2 * v2.w;
            a3.x += w3 * v3.x; a3.y += w3 * v3.y; a3.z += w3 * v3.z; a3.w += w3 * v3.w;
        }
        for (; jj < cnt; jj++) {
            int   ss = __shfl_sync(0xFFFFFFFFu, s,   jj);
            float ww = __shfl_sync(0xFFFFFFFFu, wgt, jj);
            float4 v = ((const float4*)(g_h + (size_t)ss * FDIM))[lane];
            a0.x += ww * v.x; a0.y += ww * v.y;
            a0.z += ww * v.z; a0.w += ww * v.w;
        }
    }
    float4 acc;
    acc.x = ((a0.x + a1.x) + (a2.x + a3.x)) * inv_z;
    acc.y = ((a0.y + a1.y) + (a2.y + a3.y)) * inv_z;
    acc.z = ((a0.z + a1.z) + (a2.z + a3.z)) * inv_z;
    acc.w = ((a0.w + a1.w) + (a2.w + a3.w)) * inv_z;

    unsigned hi0, lo0, hi1, lo1;
    split2(acc.x, acc.y, hi0, lo0);
    split2(acc.z, acc.w, hi1, lo1);
    size_t b2 = (size_t)w * (FDIM / 2) + 2 * lane;
    g_gath[b2]     = hi0; g_gath[b2 + 1] = hi1;
    g_gatl[b2]     = lo0; g_gatl[b2 + 1] = lo1;
}

// ----------------------- final sigmoid over fused dot ---------------------
__global__ void k_final2(const float* __restrict__ b3,
                         float* __restrict__ out, int n) {
    int i = blockIdx.x * blockDim.x + threadIdx.x;
    if (i >= n) return;
    out[i] = 1.f / (1.f + expf(-(g_dot[i] + b3[0])));
}

// --------------------------- host launcher --------------------------------
extern "C" void kernel_launch(void* const* d_in, const int* in_sizes, int n_in,
                              void* d_out, int out_size) {
    const float* x       = (const float*)d_in[0];
    const int*   ei      = (const int*)d_in[1];
    const float* W       = (const float*)d_in[2];
    const float* att_src = (const float*)d_in[3];
    const float* att_dst = (const float*)d_in[4];
    const float* bias    = (const float*)d_in[5];
    const float* W1      = (const float*)d_in[6];
    const float* b1      = (const float*)d_in[7];
    const float* W2      = (const float*)d_in[8];
    const float* b2      = (const float*)d_in[9];
    const float* W3      = (const float*)d_in[10];
    const float* b3      = (const float*)d_in[11];
    float* out = (float*)d_out;

    int n = in_sizes[0] / FDIM;
    int E = in_sizes[1] / 2;
    int Etot = E + n;
    int scanBlocks = (n + SCAN_T - 1) / SCAN_T;

    void *p_h, *p_b2;
    void *p_gath, *p_gatl, *p_h1h, *p_h1l;
    void *p_wth, *p_wtl, *p_w1th, *p_w1tl, *p_w2th, *p_w2tl;
    cudaGetSymbolAddress(&p_h,    g_h);
    cudaGetSymbolAddress(&p_b2,   g_bias2);
    cudaGetSymbolAddress(&p_gath, g_gath);
    cudaGetSymbolAddress(&p_gatl, g_gatl);
    cudaGetSymbolAddress(&p_h1h,  g_h1h);
    cudaGetSymbolAddress(&p_h1l,  g_h1l);
    cudaGetSymbolAddress(&p_wth,  g_wth);
    cudaGetSymbolAddress(&p_wtl,  g_wtl);
    cudaGetSymbolAddress(&p_w1th, g_w1th);
    cudaGetSymbolAddress(&p_w1tl, g_w1tl);
    cudaGetSymbolAddress(&p_w2th, g_w2th);
    cudaGetSymbolAddress(&p_w2tl, g_w2tl);

    int mBlocks = (n + 127) / 128;

    cudaFuncSetAttribute(k_mma<false, 0, false, false, true>,
                         cudaFuncAttributeMaxDynamicSharedMemorySize, SMEM_BYTES);
    cudaFuncSetAttribute(k_mma<true, 1, true, true, false>,
                         cudaFuncAttributeMaxDynamicSharedMemorySize, SMEM_BYTES);
    cudaFuncSetAttribute(k_mma<true, 2, true, true, false>,
                         cudaFuncAttributeMaxDynamicSharedMemorySize, SMEM_BYTES);

    // weight splits (tiny) + CSR pass 1 (direct decode)
    k_splitB<<<(FDIM * FDIM + 255) / 256, 256>>>(
        W, (__nv_bfloat16*)p_wth, (__nv_bfloat16*)p_wtl, FDIM, FDIM);
    k_detect<<<1, 256>>>(ei, E);
    k_zero<<<512, 256>>>(n);
    k_hist<<<2048, 256>>>(ei, E, n);

    // h = x @ W  (raw-A, fp32 C, fused att dots)
    k_mma<false, 0, false, false, true><<<dim3(1, mBlocks), 256, SMEM_BYTES>>>(
        x, nullptr, nullptr,
        (const __nv_bfloat16*)p_wth, (const __nv_bfloat16*)p_wtl,
        (float*)p_h, nullptr, nullptr, nullptr,
        att_src, att_dst, nullptr, n, FDIM, FDIM);

    k_splitB<<<(FDIM * HDIM + 255) / 256, 256>>>(
        W1, (__nv_bfloat16*)p_w1th, (__nv_bfloat16*)p_w1tl, FDIM, HDIM);
    k_splitB<<<(HDIM * HDIM + 255) / 256, 256>>>(
        W2, (__nv_bfloat16*)p_w2th, (__nv_bfloat16*)p_w2tl, HDIM, HDIM);
    k_bias2<<<(HDIM + 7) / 8, 256>>>(bias, W1, b1, FDIM, HDIM);
    k_scan1<<<scanBlocks, SCAN_T>>>(n);
    k_scan2<<<1, 256>>>(scanBlocks);
    k_slot<<<2048, 256>>>(ei, E, n);

    k_gather<<<(n + 7) / 8, 256>>>(n, Etot);

    // h1 = relu(gat @ W1 + bias2)  — packed A in, packed C out
    k_mma<true, 1, true, true, false><<<dim3(2, mBlocks), 256, SMEM_BYTES>>>(
        nullptr, (const unsigned*)p_gath, (const unsigned*)p_gatl,
        (const __nv_bfloat16*)p_w1th, (const __nv_bfloat16*)p_w1tl,
        nullptr, (unsigned*)p_h1h, (unsigned*)p_h1l,
        (const float*)p_b2, nullptr, nullptr, nullptr, n, HDIM, FDIM);
    // h2 @ W3 fused: relu(h1 @ W2 + b2) · W3 accumulated into g_dot
    k_mma<true, 2, true, true, false><<<dim3(2, mBlocks), 256, SMEM_BYTES>>>(
        nullptr, (const unsigned*)p_h1h, (const unsigned*)p_h1l,
        (const __nv_bfloat16*)p_w2th, (const __nv_bfloat16*)p_w2tl,
        nullptr, nullptr, nullptr, b2, nullptr, nullptr, W3, n, HDIM, HDIM);
    k_final2<<<(n + 255) / 256, 256>>>(b3, out, n);
}